// round 11
// baseline (speedup 1.0000x reference)
#include <cuda_runtime.h>
#include <cuda_bf16.h>
#include <cuda_fp16.h>
#include <cstdint>

#define T_    4096
#define B_    8
#define E_    1024
#define H_    8
#define D_    128
#define KP    64
#define K2    128
#define CH    128
#define NC    32
#define MR    32768
#define BHN   64
#define EPSV  1e-6f

#define K3        3072
#define NSTAGE    2
#define STAGE_B   32768
#define GEMM_SMEM (NSTAGE * STAGE_B)   // 64KB -> 2-3 CTAs/SM with max carveout
#define WSCALE    1024.0f

// ---------------- scratch ---------------------------------------------------
__device__ float g_v[33554432];
__device__ float g_pq[33554432];
__device__ float g_pk[33554432];
__device__ float g_S[33554432];
__device__ float g_z[262144];
__device__ float g_M[1048576];       // fused q/k projection matrix
__device__ float g_pb[1024];
__device__ __half g_a3[100663296];   // [MR][3072] x fp16x3, later attn bf16x3 (reuse)
__device__ __half g_wv3[3145728];    // Wv fp16x3
__device__ __half g_wo3[3145728];    // Wo bf16x3 (bits in half storage)

// ---------------- PTX helpers -----------------------------------------------
__device__ __forceinline__ uint32_t smem_u32(const void* p) {
    uint32_t a;
    asm("{ .reg .u64 t; cvta.to.shared.u64 t, %1; cvt.u32.u64 %0, t; }"
        : "=r"(a) : "l"(p));
    return a;
}
__device__ __forceinline__ void cp16(uint32_t dst, const void* src) {
    asm volatile("cp.async.cg.shared.global [%0], [%1], 16;" :: "r"(dst), "l"(src));
}
__device__ __forceinline__ void ldm_x4(uint32_t& r0, uint32_t& r1,
                                       uint32_t& r2, uint32_t& r3, uint32_t addr) {
    asm volatile("ldmatrix.sync.aligned.m8n8.x4.shared.b16 {%0,%1,%2,%3}, [%4];"
                 : "=r"(r0), "=r"(r1), "=r"(r2), "=r"(r3) : "r"(addr));
}
__device__ __forceinline__ void mma_f16(float* c, const uint32_t* a,
                                        uint32_t b0, uint32_t b1) {
    asm volatile(
        "mma.sync.aligned.m16n8k16.row.col.f32.f16.f16.f32 "
        "{%0,%1,%2,%3}, {%4,%5,%6,%7}, {%8,%9}, {%0,%1,%2,%3};"
        : "+f"(c[0]), "+f"(c[1]), "+f"(c[2]), "+f"(c[3])
        : "r"(a[0]), "r"(a[1]), "r"(a[2]), "r"(a[3]), "r"(b0), "r"(b1));
}
__device__ __forceinline__ void mma_bf16(float* c, const uint32_t* a,
                                         uint32_t b0, uint32_t b1) {
    asm volatile(
        "mma.sync.aligned.m16n8k16.row.col.f32.bf16.bf16.f32 "
        "{%0,%1,%2,%3}, {%4,%5,%6,%7}, {%8,%9}, {%0,%1,%2,%3};"
        : "+f"(c[0]), "+f"(c[1]), "+f"(c[2]), "+f"(c[3])
        : "r"(a[0]), "r"(a[1]), "r"(a[2]), "r"(a[3]), "r"(b0), "r"(b1));
}

// ---------------- prep: fused q/k projection matrix + bias -------------------
__global__ __launch_bounds__(128) void prep_M(
    const float* __restrict__ rm, const float* __restrict__ sig,
    const float* __restrict__ Wq, const float* __restrict__ Wk,
    const float* __restrict__ bq, const float* __restrict__ bk,
    float* __restrict__ M, float* __restrict__ pb)
{
    const int row = blockIdx.x;
    const int isK = row >> 9;
    const int h   = (row >> 6) & 7;
    const int kk  = row & 63;
    const float* W  = isK ? Wk : Wq;
    const float* bb = isK ? bk : bq;
    __shared__ float r[128];
    const int tid = threadIdx.x;
    const float c = 0.29730177875068026f;
    r[tid] = c * sig[h * 128 + tid] * rm[((size_t)(h * 64 + kk)) * 128 + tid];
    __syncthreads();
    for (int e = tid; e < 1024; e += 128) {
        float acc = 0.f;
        #pragma unroll 8
        for (int d = 0; d < 128; d++)
            acc = fmaf(r[d], W[(size_t)(h * 128 + d) * 1024 + e], acc);
        M[(size_t)row * 1024 + e] = acc;
    }
    if (tid == 0) {
        float acc = 0.f;
        for (int d = 0; d < 128; d++) acc = fmaf(r[d], bb[h * 128 + d], acc);
        pb[row] = acc;
    }
}

// ---------------- split fp32 -> fp16 x3 concat (round-6 verified) -------------
__global__ __launch_bounds__(256) void split3h_kernel(
    const float* __restrict__ X, __half* __restrict__ O, int midIsLo, float scale)
{
    size_t idx = (size_t)blockIdx.x * 256 + threadIdx.x;
    size_t m = idx >> 8;
    int kq = (int)(idx & 255) << 2;
    float4 v = *(const float4*)(X + m * 1024 + kq);
    float f[4] = {v.x * scale, v.y * scale, v.z * scale, v.w * scale};
    __half h[4], l[4];
    #pragma unroll
    for (int i = 0; i < 4; i++) {
        h[i] = __float2half(f[i]);
        l[i] = __float2half(f[i] - __half2float(h[i]));
    }
    __half2 hp0 = __halves2half2(h[0], h[1]);
    __half2 hp1 = __halves2half2(h[2], h[3]);
    __half2 lp0 = __halves2half2(l[0], l[1]);
    __half2 lp1 = __halves2half2(l[2], l[3]);
    __half* o = O + m * K3 + kq;
    ((__half2*)o)[0] = hp0;
    ((__half2*)o)[1] = hp1;
    ((__half2*)(o + 1024))[0] = midIsLo ? lp0 : hp0;
    ((__half2*)(o + 1024))[1] = midIsLo ? lp1 : hp1;
    ((__half2*)(o + 2048))[0] = midIsLo ? hp0 : lp0;
    ((__half2*)(o + 2048))[1] = midIsLo ? hp1 : lp1;
}

// ---------------- split fp32 -> bf16 x3 concat (round-6 verified) -------------
__global__ __launch_bounds__(256) void split3b_kernel(
    const float* __restrict__ X, __nv_bfloat16* __restrict__ O, int midIsLo)
{
    size_t idx = (size_t)blockIdx.x * 256 + threadIdx.x;
    size_t m = idx >> 8;
    int kq = (int)(idx & 255) << 2;
    float4 v = *(const float4*)(X + m * 1024 + kq);
    float f[4] = {v.x, v.y, v.z, v.w};
    __nv_bfloat16 h[4], l[4];
    #pragma unroll
    for (int i = 0; i < 4; i++) {
        h[i] = __float2bfloat16(f[i]);
        l[i] = __float2bfloat16(f[i] - __bfloat162float(h[i]));
    }
    __nv_bfloat162 hp0 = __halves2bfloat162(h[0], h[1]);
    __nv_bfloat162 hp1 = __halves2bfloat162(h[2], h[3]);
    __nv_bfloat162 lp0 = __halves2bfloat162(l[0], l[1]);
    __nv_bfloat162 lp1 = __halves2bfloat162(l[2], l[3]);
    __nv_bfloat16* o = O + m * K3 + kq;
    ((__nv_bfloat162*)o)[0] = hp0;
    ((__nv_bfloat162*)o)[1] = hp1;
    ((__nv_bfloat162*)(o + 1024))[0] = midIsLo ? lp0 : hp0;
    ((__nv_bfloat162*)(o + 1024))[1] = midIsLo ? lp1 : hp1;
    ((__nv_bfloat162*)(o + 2048))[0] = midIsLo ? hp0 : lp0;
    ((__nv_bfloat162*)(o + 2048))[1] = midIsLo ? hp1 : lp1;
}

// ---------------- HMMA GEMM: C = (A . W^T) * outScale + bias ------------------
template<bool FP16, int KTOT>
__global__ __launch_bounds__(256) void gemm_hmma(
    const void* __restrict__ A3v, const void* __restrict__ W3v,
    const float* __restrict__ bias, float* __restrict__ C, float outScale)
{
    constexpr int NCHUNK = KTOT / 64;
    constexpr int ROWB   = KTOT * 2;
    extern __shared__ __align__(128) char smem[];
    const uint32_t sb = smem_u32(smem);
    const int tid  = threadIdx.x;
    const int lane = tid & 31;
    const int wid  = tid >> 5;
    const int m0 = blockIdx.y << 7;
    const int n0 = blockIdx.x << 7;
    const int wm = (wid >> 1) << 5;
    const int wn = (wid & 1) << 6;

    const char* Abase = (const char*)A3v + (size_t)m0 * ROWB;
    const char* Bbase = (const char*)W3v + (size_t)n0 * ROWB;

    const int lrow = tid >> 1;
    const int lc0  = (tid & 1) << 2;
    auto load_stage = [&](int chunk, int st) {
        const size_t gcol = (size_t)(chunk << 7);
        const uint32_t sa = sb + st * STAGE_B;
        #pragma unroll
        for (int c = 0; c < 4; c++) {
            int ch = lc0 + c;
            uint32_t soff = (lrow << 7) + (((ch ^ (lrow & 7))) << 4);
            cp16(sa + soff,         Abase + (size_t)lrow * ROWB + gcol + (ch << 4));
            cp16(sa + 16384 + soff, Bbase + (size_t)lrow * ROWB + gcol + (ch << 4));
        }
    };

    #pragma unroll
    for (int s = 0; s < NSTAGE; s++) {
        load_stage(s, s);
        asm volatile("cp.async.commit_group;" ::: "memory");
    }

    const int amln = wm + (lane & 15);
    const int acb  = (lane >> 4) << 4;
    const int asw  = (amln & 7) << 4;
    const int bnln = wn + (lane & 7) + ((lane & 16) >> 1);
    const int bcb  = (lane & 8) << 1;
    const int bsw  = (lane & 7) << 4;

    float acc[2][8][4] = {};

    for (int i = 0; i < NCHUNK; i++) {
        asm volatile("cp.async.wait_group %0;" :: "n"(NSTAGE - 1) : "memory");
        __syncthreads();
        const int st = i % NSTAGE;
        const uint32_t sa = sb + st * STAGE_B;
        const uint32_t sbB = sa + 16384;
        #pragma unroll
        for (int ks = 0; ks < 4; ks++) {
            uint32_t a[2][4];
            #pragma unroll
            for (int mi = 0; mi < 2; mi++) {
                uint32_t addr = sa + ((amln + (mi << 4)) << 7)
                              + (((ks << 5) + acb) ^ asw);
                ldm_x4(a[mi][0], a[mi][1], a[mi][2], a[mi][3], addr);
            }
            #pragma unroll
            for (int njp = 0; njp < 4; njp++) {
                uint32_t q0, q1, q2, q3;
                uint32_t addr = sbB + ((bnln + (njp << 4)) << 7)
                              + (((ks << 5) + bcb) ^ bsw);
                ldm_x4(q0, q1, q2, q3, addr);
                if (FP16) {
                    mma_f16(acc[0][2*njp],     a[0], q0, q1);
                    mma_f16(acc[0][2*njp + 1], a[0], q2, q3);
                    mma_f16(acc[1][2*njp],     a[1], q0, q1);
                    mma_f16(acc[1][2*njp + 1], a[1], q2, q3);
                } else {
                    mma_bf16(acc[0][2*njp],     a[0], q0, q1);
                    mma_bf16(acc[0][2*njp + 1], a[0], q2, q3);
                    mma_bf16(acc[1][2*njp],     a[1], q0, q1);
                    mma_bf16(acc[1][2*njp + 1], a[1], q2, q3);
                }
            }
        }
        __syncthreads();
        if (i + NSTAGE < NCHUNK) load_stage(i + NSTAGE, st);
        asm volatile("cp.async.commit_group;" ::: "memory");
    }

    const int rbase = m0 + wm + (lane >> 2);
    const int cbase = n0 + wn + ((lane & 3) << 1);
    #pragma unroll
    for (int mi = 0; mi < 2; mi++) {
        #pragma unroll
        for (int nj = 0; nj < 8; nj++) {
            int col = cbase + (nj << 3);
            float b0 = bias[col], b1 = bias[col + 1];
            float* p0 = C + (size_t)(rbase + (mi << 4)) * 1024 + col;
            float* p1 = p0 + 8 * 1024;
            float2 v0 = {acc[mi][nj][0] * outScale + b0, acc[mi][nj][1] * outScale + b1};
            float2 v1 = {acc[mi][nj][2] * outScale + b0, acc[mi][nj][3] * outScale + b1};
            *(float2*)p0 = v0;
            *(float2*)p1 = v1;
        }
    }
}

// ---------------- fp32 SGEMM + fused phi: writes sin/cos directly -------------
__global__ __launch_bounds__(256) void sgemm_phi(
    const float* __restrict__ A, const float* __restrict__ Bm,
    const float* __restrict__ bias,
    float* __restrict__ PQ, float* __restrict__ PK, int Kd)
{
    __shared__ float As[16][128];
    __shared__ float Bs[16][128];
    const int bm = blockIdx.y * 128;
    const int bn = blockIdx.x * 128;
    const int tid = threadIdx.x;
    const int t0 = (tid >> 4) << 3;
    const int n0 = (tid & 15) << 3;
    const int lr = tid >> 2;
    const int lc = (tid & 3) << 2;
    const float* Ap = A + (size_t)(bm + lr) * Kd + lc;
    const float* Bp = Bm + (size_t)(bn + lr) * Kd + lc;
    const size_t half = (size_t)64 * Kd;

    float4 a0 = *(const float4*)(Ap);
    float4 a1 = *(const float4*)(Ap + half);
    float4 b0 = *(const float4*)(Bp);
    float4 b1 = *(const float4*)(Bp + half);

    float acc[8][8] = {};
    for (int k0 = 0; k0 < Kd; k0 += 16) {
        As[lc+0][lr]    = a0.x; As[lc+1][lr]    = a0.y; As[lc+2][lr]    = a0.z; As[lc+3][lr]    = a0.w;
        As[lc+0][lr+64] = a1.x; As[lc+1][lr+64] = a1.y; As[lc+2][lr+64] = a1.z; As[lc+3][lr+64] = a1.w;
        Bs[lc+0][lr]    = b0.x; Bs[lc+1][lr]    = b0.y; Bs[lc+2][lr]    = b0.z; Bs[lc+3][lr]    = b0.w;
        Bs[lc+0][lr+64] = b1.x; Bs[lc+1][lr+64] = b1.y; Bs[lc+2][lr+64] = b1.z; Bs[lc+3][lr+64] = b1.w;
        __syncthreads();
        if (k0 + 16 < Kd) {
            a0 = *(const float4*)(Ap + k0 + 16);
            a1 = *(const float4*)(Ap + k0 + 16 + half);
            b0 = *(const float4*)(Bp + k0 + 16);
            b1 = *(const float4*)(Bp + k0 + 16 + half);
        }
        #pragma unroll
        for (int kk = 0; kk < 16; kk++) {
            float4 x0 = *(const float4*)&As[kk][t0];
            float4 x1 = *(const float4*)&As[kk][t0+4];
            float4 y0 = *(const float4*)&Bs[kk][n0];
            float4 y1 = *(const float4*)&Bs[kk][n0+4];
            float ar[8] = {x0.x,x0.y,x0.z,x0.w,x1.x,x1.y,x1.z,x1.w};
            float br[8] = {y0.x,y0.y,y0.z,y0.w,y1.x,y1.y,y1.z,y1.w};
            #pragma unroll
            for (int i = 0; i < 8; i++)
                #pragma unroll
                for (int j = 0; j < 8; j++)
                    acc[i][j] = fmaf(ar[i], br[j], acc[i][j]);
        }
        __syncthreads();
    }

    float bb[8];
    #pragma unroll
    for (int j = 0; j < 8; j++) bb[j] = bias[bn + n0 + j];
    const int colg = bn + n0;
    float* OUTB = (colg < 512) ? PQ : PK;
    const int cc  = colg & 511;
    const int hh  = cc >> 6;
    const int kk0 = cc & 63;
    #pragma unroll
    for (int i = 0; i < 8; i++) {
        size_t base = (size_t)(bm + t0 + i) * 1024 + (hh << 7) + kk0;
        float sv[8], cv[8];
        #pragma unroll
        for (int j = 0; j < 8; j++) {
            float s, c;
            sincosf(acc[i][j] + bb[j], &s, &c);
            sv[j] = s * 0.125f;
            cv[j] = c * 0.125f;
        }
        float4 o;
        o.x=sv[0]; o.y=sv[1]; o.z=sv[2]; o.w=sv[3]; *(float4*)&OUTB[base]      = o;
        o.x=sv[4]; o.y=sv[5]; o.z=sv[6]; o.w=sv[7]; *(float4*)&OUTB[base + 4]  = o;
        o.x=cv[0]; o.y=cv[1]; o.z=cv[2]; o.w=cv[3]; *(float4*)&OUTB[base + 64] = o;
        o.x=cv[4]; o.y=cv[5]; o.z=cv[6]; o.w=cv[7]; *(float4*)&OUTB[base + 68] = o;
    }
}

// ---------------- per-chunk state + fused z -------------------------------------
__global__ __launch_bounds__(256) void chunk_state_kernel(
    const float* __restrict__ PK, const float* __restrict__ V,
    float* __restrict__ S, float* __restrict__ Z)
{
    __shared__ float as[16][128];
    __shared__ float bs[16][128];
    const int c = blockIdx.x, bh = blockIdx.y;
    const int b = bh >> 3, h = bh & 7;
    const int tid = threadIdx.x;
    const int t0 = (tid >> 4) << 3;
    const int n0 = (tid & 15) << 3;
    float acc[8][8] = {};
    float zacc = 0.f;

    for (int s0 = 0; s0 < CH; s0 += 16) {
        #pragma unroll
        for (int it = 0; it < 2; it++) {
            int idx = tid + (it << 8);
            int r  = idx >> 5;
            int c4 = (idx & 31) << 2;
            size_t grow = ((size_t)(c * CH + s0 + r) * B_ + b) * E_ + h * D_;
            *(float4*)&as[r][c4] = *(const float4*)(PK + grow + c4);
            *(float4*)&bs[r][c4] = *(const float4*)(V  + grow + c4);
        }
        __syncthreads();
        if (tid < 128) {
            float za = 0.f;
            #pragma unroll
            for (int ss = 0; ss < 16; ss++) za += as[ss][tid];
            zacc += za;
        }
        #pragma unroll
        for (int ss = 0; ss < 16; ss++) {
            float4 x0 = *(const float4*)&as[ss][t0];
            float4 x1 = *(const float4*)&as[ss][t0+4];
            float4 y0 = *(const float4*)&bs[ss][n0];
            float4 y1 = *(const float4*)&bs[ss][n0+4];
            float ar[8] = {x0.x,x0.y,x0.z,x0.w,x1.x,x1.y,x1.z,x1.w};
            float br[8] = {y0.x,y0.y,y0.z,y0.w,y1.x,y1.y,y1.z,y1.w};
            #pragma unroll
            for (int i = 0; i < 8; i++)
                #pragma unroll
                for (int j = 0; j < 8; j++)
                    acc[i][j] = fmaf(ar[i], br[j], acc[i][j]);
        }
        __syncthreads();
    }
    float* Sp = S + ((size_t)c * BHN + bh) * (K2 * D_);
    #pragma unroll
    for (int i = 0; i < 8; i++) {
        float4 o;
        o.x = acc[i][0]; o.y = acc[i][1]; o.z = acc[i][2]; o.w = acc[i][3];
        *(float4*)(Sp + (size_t)(t0 + i) * D_ + n0) = o;
        o.x = acc[i][4]; o.y = acc[i][5]; o.z = acc[i][6]; o.w = acc[i][7];
        *(float4*)(Sp + (size_t)(t0 + i) * D_ + n0 + 4) = o;
    }
    if (tid < 128)
        Z[((size_t)c * BHN + bh) * K2 + tid] = zacc;
}

__global__ void prefix_S_kernel(float* __restrict__ S)
{
    const int bh = blockIdx.x;
    const int e  = blockIdx.y * 256 + threadIdx.x;
    float acc = 0.f;
    for (int c = 0; c < NC; c++) {
        size_t idx = ((size_t)c * BHN + bh) * (K2 * D_) + e;
        float t = S[idx]; S[idx] = acc; acc += t;
    }
}

__global__ void prefix_z_kernel(float* __restrict__ Z)
{
    const int bh = blockIdx.x;
    const int k  = threadIdx.x;
    float acc = 0.f;
    for (int c = 0; c < NC; c++) {
        size_t idx = ((size_t)c * BHN + bh) * K2 + k;
        float t = Z[idx]; Z[idx] = acc; acc += t;
    }
}

// ---------------- RFA output (2 CTAs/SM with max carveout) ----------------------
#define RFA_SMEM ((128*132 + 2*16*132) * 4)   // 84480 B
__global__ __launch_bounds__(256) void rfa_out_kernel(
    const float* __restrict__ PQ, const float* __restrict__ PK,
    const float* __restrict__ V,  const float* __restrict__ S,
    const float* __restrict__ Z,  __nv_bfloat16* __restrict__ A3)
{
    extern __shared__ float sm[];
    float* SC = sm;
    float* TA = sm + 128 * 132;
    float* TB = TA + 16 * 132;

    const int c = blockIdx.x, bh = blockIdx.y;
    const int b = bh >> 3, h = bh & 7;
    const int tid = threadIdx.x;
    const int t0 = (tid >> 4) << 3;
    const int n0 = (tid & 15) << 3;

    float sc[8][8] = {};
    for (int kt = 0; kt < 8; kt++) {
        #pragma unroll
        for (int it = 0; it < 2; it++) {
            int idx = tid + (it << 8);
            int r  = idx >> 2;
            int c4 = (idx & 3) << 2;
            size_t grow = ((size_t)(c * CH + r) * B_ + b) * E_ + h * K2 + (kt << 4) + c4;
            float4 vq = *(const float4*)(PQ + grow);
            TA[(c4+0)*132 + r] = vq.x; TA[(c4+1)*132 + r] = vq.y;
            TA[(c4+2)*132 + r] = vq.z; TA[(c4+3)*132 + r] = vq.w;
            float4 vk = *(const float4*)(PK + grow);
            TB[(c4+0)*132 + r] = vk.x; TB[(c4+1)*132 + r] = vk.y;
            TB[(c4+2)*132 + r] = vk.z; TB[(c4+3)*132 + r] = vk.w;
        }
        __syncthreads();
        #pragma unroll
        for (int kk = 0; kk < 16; kk++) {
            float4 x0 = *(const float4*)&TA[kk*132 + t0];
            float4 x1 = *(const float4*)&TA[kk*132 + t0 + 4];
            float4 y0 = *(const float4*)&TB[kk*132 + n0];
            float4 y1 = *(const float4*)&TB[kk*132 + n0 + 4];
            float ar[8] = {x0.x,x0.y,x0.z,x0.w,x1.x,x1.y,x1.z,x1.w};
            float br[8] = {y0.x,y0.y,y0.z,y0.w,y1.x,y1.y,y1.z,y1.w};
            #pragma unroll
            for (int i = 0; i < 8; i++)
                #pragma unroll
                for (int j = 0; j < 8; j++)
                    sc[i][j] = fmaf(ar[i], br[j], sc[i][j]);
        }
        __syncthreads();
    }
    #pragma unroll
    for (int j = 0; j < 8; j++)
        #pragma unroll
        for (int i = 0; i < 8; i++)
            SC[(size_t)(n0 + j) * 132 + (t0 + i)] = (n0 + j <= t0 + i) ? sc[i][j] : 0.0f;
    __syncthreads();

    float acc[8][8] = {};
    float dacc[8] = {};
    const float* Sp = S + ((size_t)c * BHN + bh) * (K2 * D_);
    const float* zp = Z + ((size_t)c * BHN + bh) * K2;
    for (int kt = 0; kt < 16; kt++) {
        const int rbase = kt << 4;
        #pragma unroll
        for (int it = 0; it < 2; it++) {
            int idx = tid + (it << 8);
            int r  = idx >> 5;
            int c4 = (idx & 31) << 2;
            int rr = rbase + r;
            float4 vv;
            if (rr < 128)
                vv = *(const float4*)(V + ((size_t)(c * CH + rr) * B_ + b) * E_ + h * D_ + c4);
            else
                vv = *(const float4*)(Sp + (size_t)(rr - 128) * D_ + c4);
            *(float4*)&TB[r * 132 + c4] = vv;
        }
        if (tid < 16) {
            int rr = rbase + tid;
            TB[tid * 132 + 128] = (rr < 128) ? 1.0f : zp[rr - 128];
        }
        if (rbase >= 128) {
            #pragma unroll
            for (int it = 0; it < 2; it++) {
                int idx = tid + (it << 8);
                int r  = idx >> 2;
                int c4 = (idx & 3) << 2;
                size_t grow = ((size_t)(c * CH + r) * B_ + b) * E_ + h * K2
                            + (rbase - 128) + c4;
                float4 vq = *(const float4*)(PQ + grow);
                TA[(c4+0)*132 + r] = vq.x; TA[(c4+1)*132 + r] = vq.y;
                TA[(c4+2)*132 + r] = vq.z; TA[(c4+3)*132 + r] = vq.w;
            }
        }
        __syncthreads();
        const float* Aop = (rbase < 128) ? (SC + (size_t)rbase * 132) : TA;
        #pragma unroll
        for (int ss = 0; ss < 16; ss++) {
            const float* arow = Aop + (size_t)ss * 132;
            float4 x0 = *(const float4*)(arow + t0);
            float4 x1 = *(const float4*)(arow + t0 + 4);
            float ar[8] = {x0.x,x0.y,x0.z,x0.w,x1.x,x1.y,x1.z,x1.w};
            float4 y0 = *(const float4*)&TB[ss * 132 + n0];
            float4 y1 = *(const float4*)&TB[ss * 132 + n0 + 4];
            float br[8] = {y0.x,y0.y,y0.z,y0.w,y1.x,y1.y,y1.z,y1.w};
            float bv = TB[ss * 132 + 128];
            #pragma unroll
            for (int i = 0; i < 8; i++) {
                dacc[i] = fmaf(ar[i], bv, dacc[i]);
                #pragma unroll
                for (int j = 0; j < 8; j++)
                    acc[i][j] = fmaf(ar[i], br[j], acc[i][j]);
            }
        }
        __syncthreads();
    }

    #pragma unroll
    for (int i = 0; i < 8; i++) {
        float inv = 1.0f / fmaxf(dacc[i], EPSV);
        size_t m = (size_t)(c * CH + t0 + i) * B_ + b;
        __nv_bfloat16* o = A3 + m * K3 + h * D_ + n0;
        __nv_bfloat16 hh[8], ll[8];
        #pragma unroll
        for (int j = 0; j < 8; j++) {
            float ov = acc[i][j] * inv;
            hh[j] = __float2bfloat16(ov);
            ll[j] = __float2bfloat16(ov - __bfloat162float(hh[j]));
        }
        #pragma unroll
        for (int j = 0; j < 4; j++) {
            __nv_bfloat162 hp = __halves2bfloat162(hh[2*j], hh[2*j+1]);
            __nv_bfloat162 lp = __halves2bfloat162(ll[2*j], ll[2*j+1]);
            ((__nv_bfloat162*)(o))[j]        = hp;
            ((__nv_bfloat162*)(o + 1024))[j] = lp;
            ((__nv_bfloat162*)(o + 2048))[j] = hp;
        }
    }
}

// ---------------- launcher -----------------------------------------------------
extern "C" void kernel_launch(void* const* d_in, const int* in_sizes, int n_in,
                              void* d_out, int out_size)
{
    const float* x   = (const float*)d_in[0];
    const float* rm  = (const float*)d_in[1];
    const float* Wq  = (const float*)d_in[2];
    const float* bq  = (const float*)d_in[3];
    const float* Wk  = (const float*)d_in[4];
    const float* bk  = (const float*)d_in[5];
    const float* Wv  = (const float*)d_in[6];
    const float* bv  = (const float*)d_in[7];
    const float* Wo  = (const float*)d_in[8];
    const float* bo  = (const float*)d_in[9];
    const float* sig = (const float*)d_in[10];
    float* out = (float*)d_out;

    float *v, *pq, *pk, *S, *z, *M, *pb;
    __half *a3, *wv3, *wo3;
    cudaGetSymbolAddress((void**)&v,    g_v);
    cudaGetSymbolAddress((void**)&pq,   g_pq);
    cudaGetSymbolAddress((void**)&pk,   g_pk);
    cudaGetSymbolAddress((void**)&S,    g_S);
    cudaGetSymbolAddress((void**)&z,    g_z);
    cudaGetSymbolAddress((void**)&M,    g_M);
    cudaGetSymbolAddress((void**)&pb,   g_pb);
    cudaGetSymbolAddress((void**)&a3,   g_a3);
    cudaGetSymbolAddress((void**)&wv3,  g_wv3);
    cudaGetSymbolAddress((void**)&wo3,  g_wo3);

    // occupancy unlock: max smem carveout so 2+ CTAs/SM fit
    cudaFuncSetAttribute(rfa_out_kernel,
                         cudaFuncAttributeMaxDynamicSharedMemorySize, RFA_SMEM);
    cudaFuncSetAttribute(rfa_out_kernel,
                         cudaFuncAttributePreferredSharedMemoryCarveout, 100);
    cudaFuncSetAttribute((const void*)gemm_hmma<true, 3072>,
                         cudaFuncAttributeMaxDynamicSharedMemorySize, GEMM_SMEM);
    cudaFuncSetAttribute((const void*)gemm_hmma<true, 3072>,
                         cudaFuncAttributePreferredSharedMemoryCarveout, 100);
    cudaFuncSetAttribute((const void*)gemm_hmma<false, 3072>,
                         cudaFuncAttributeMaxDynamicSharedMemorySize, GEMM_SMEM);
    cudaFuncSetAttribute((const void*)gemm_hmma<false, 3072>,
                         cudaFuncAttributePreferredSharedMemoryCarveout, 100);

    const float invW = 1.0f / WSCALE;
    dim3 ghmma(E_ / 128, MR / 128);

    cudaStream_t s1;
    cudaStreamCreateWithFlags(&s1, cudaStreamNonBlocking);
    cudaEvent_t e1, e2;
    cudaEventCreateWithFlags(&e1, cudaEventDisableTiming);
    cudaEventCreateWithFlags(&e2, cudaEventDisableTiming);

    // --- main stream: fused q/k matrix then fp32 P GEMM + fused phi ---
    prep_M<<<1024, 128>>>(rm, sig, Wq, Wk, bq, bk, M, pb);
    cudaEventRecord(e1, 0);
    cudaStreamWaitEvent(s1, e1, 0);

    // --- stream 1: v path (splits + fp16x3 HMMA) + Wo split, parallel to P ---
    split3h_kernel<<<MR, 256, 0, s1>>>(x, a3, 1, 1.0f);
    split3h_kernel<<<1024, 256, 0, s1>>>(Wv, wv3, 0, WSCALE);
    gemm_hmma<true, 3072><<<ghmma, 256, GEMM_SMEM, s1>>>(a3, wv3, bv, v, invW);
    split3b_kernel<<<1024, 256, 0, s1>>>(Wo, (__nv_bfloat16*)wo3, 0);
    cudaEventRecord(e2, s1);

    // --- main stream: P GEMM with fused sincos epilogue -> pq/pk directly ---
    sgemm_phi<<<dim3(E_ / 128, MR / 128), 256>>>(x, M, pb, pq, pk, 1024);

    cudaStreamWaitEvent(0, e2, 0);

    dim3 gcs(NC, BHN);
    chunk_state_kernel<<<gcs, 256>>>(pk, v, S, z);
    prefix_S_kernel<<<dim3(BHN, 64), 256>>>(S);
    prefix_z_kernel<<<BHN, 128>>>(z);
    rfa_out_kernel<<<gcs, 256, RFA_SMEM>>>(pq, pk, v, S, z, (__nv_bfloat16*)a3);

    // O projection: bf16x3 HMMA, input already split by rfa_out
    gemm_hmma<false, 3072><<<ghmma, 256, GEMM_SMEM>>>(a3, wo3, bo, out, 1.0f);
}

// round 12
// speedup vs baseline: 1.1846x; 1.1846x over previous
#include <cuda_runtime.h>
#include <cuda_bf16.h>
#include <cuda_fp16.h>
#include <cstdint>

#define T_    4096
#define B_    8
#define E_    1024
#define H_    8
#define D_    128
#define KP    64
#define K2    128
#define CH    128
#define NC    32
#define MR    32768
#define BHN   64
#define EPSV  1e-6f

#define K3        3072
#define NSTAGE    2
#define STAGE_B   32768
#define GEMM_SMEM (NSTAGE * STAGE_B)   // 64KB
#define WSCALE    1024.0f

// ---------------- scratch ---------------------------------------------------
__device__ float g_v[33554432];
__device__ float g_pq[33554432];
__device__ float g_pk[33554432];
__device__ float g_S[33554432];
__device__ float g_z[262144];
__device__ float g_M[1048576];
__device__ float g_pb[1024];
__device__ __half g_a3[100663296];   // [MR][3072] x fp16x3, later attn bf16x3 (reuse)
__device__ __half g_wv3[3145728];    // Wv fp16x3
__device__ __half g_wo3[3145728];    // Wo bf16x3 (bits in half storage)

// ---------------- PTX helpers -----------------------------------------------
__device__ __forceinline__ uint32_t smem_u32(const void* p) {
    uint32_t a;
    asm("{ .reg .u64 t; cvta.to.shared.u64 t, %1; cvt.u32.u64 %0, t; }"
        : "=r"(a) : "l"(p));
    return a;
}
__device__ __forceinline__ void cp16(uint32_t dst, const void* src) {
    asm volatile("cp.async.cg.shared.global [%0], [%1], 16;" :: "r"(dst), "l"(src));
}
__device__ __forceinline__ void ldm_x4(uint32_t& r0, uint32_t& r1,
                                       uint32_t& r2, uint32_t& r3, uint32_t addr) {
    asm volatile("ldmatrix.sync.aligned.m8n8.x4.shared.b16 {%0,%1,%2,%3}, [%4];"
                 : "=r"(r0), "=r"(r1), "=r"(r2), "=r"(r3) : "r"(addr));
}
__device__ __forceinline__ void mma_f16(float* c, const uint32_t* a,
                                        uint32_t b0, uint32_t b1) {
    asm volatile(
        "mma.sync.aligned.m16n8k16.row.col.f32.f16.f16.f32 "
        "{%0,%1,%2,%3}, {%4,%5,%6,%7}, {%8,%9}, {%0,%1,%2,%3};"
        : "+f"(c[0]), "+f"(c[1]), "+f"(c[2]), "+f"(c[3])
        : "r"(a[0]), "r"(a[1]), "r"(a[2]), "r"(a[3]), "r"(b0), "r"(b1));
}
__device__ __forceinline__ void mma_bf16(float* c, const uint32_t* a,
                                         uint32_t b0, uint32_t b1) {
    asm volatile(
        "mma.sync.aligned.m16n8k16.row.col.f32.bf16.bf16.f32 "
        "{%0,%1,%2,%3}, {%4,%5,%6,%7}, {%8,%9}, {%0,%1,%2,%3};"
        : "+f"(c[0]), "+f"(c[1]), "+f"(c[2]), "+f"(c[3])
        : "r"(a[0]), "r"(a[1]), "r"(a[2]), "r"(a[3]), "r"(b0), "r"(b1));
}

// ---------------- prep: fused q/k projection matrix + bias -------------------
__global__ __launch_bounds__(128) void prep_M(
    const float* __restrict__ rm, const float* __restrict__ sig,
    const float* __restrict__ Wq, const float* __restrict__ Wk,
    const float* __restrict__ bq, const float* __restrict__ bk,
    float* __restrict__ M, float* __restrict__ pb)
{
    const int row = blockIdx.x;
    const int isK = row >> 9;
    const int h   = (row >> 6) & 7;
    const int kk  = row & 63;
    const float* W  = isK ? Wk : Wq;
    const float* bb = isK ? bk : bq;
    __shared__ float r[128];
    const int tid = threadIdx.x;
    const float c = 0.29730177875068026f;
    r[tid] = c * sig[h * 128 + tid] * rm[((size_t)(h * 64 + kk)) * 128 + tid];
    __syncthreads();
    for (int e = tid; e < 1024; e += 128) {
        float acc = 0.f;
        #pragma unroll 8
        for (int d = 0; d < 128; d++)
            acc = fmaf(r[d], W[(size_t)(h * 128 + d) * 1024 + e], acc);
        M[(size_t)row * 1024 + e] = acc;
    }
    if (tid == 0) {
        float acc = 0.f;
        for (int d = 0; d < 128; d++) acc = fmaf(r[d], bb[h * 128 + d], acc);
        pb[row] = acc;
    }
}

// ---------------- split fp32 -> fp16 x3 concat --------------------------------
__global__ __launch_bounds__(256) void split3h_kernel(
    const float* __restrict__ X, __half* __restrict__ O, int midIsLo, float scale)
{
    size_t idx = (size_t)blockIdx.x * 256 + threadIdx.x;
    size_t m = idx >> 8;
    int kq = (int)(idx & 255) << 2;
    float4 v = *(const float4*)(X + m * 1024 + kq);
    float f[4] = {v.x * scale, v.y * scale, v.z * scale, v.w * scale};
    __half h[4], l[4];
    #pragma unroll
    for (int i = 0; i < 4; i++) {
        h[i] = __float2half(f[i]);
        l[i] = __float2half(f[i] - __half2float(h[i]));
    }
    __half2 hp0 = __halves2half2(h[0], h[1]);
    __half2 hp1 = __halves2half2(h[2], h[3]);
    __half2 lp0 = __halves2half2(l[0], l[1]);
    __half2 lp1 = __halves2half2(l[2], l[3]);
    __half* o = O + m * K3 + kq;
    ((__half2*)o)[0] = hp0;
    ((__half2*)o)[1] = hp1;
    ((__half2*)(o + 1024))[0] = midIsLo ? lp0 : hp0;
    ((__half2*)(o + 1024))[1] = midIsLo ? lp1 : hp1;
    ((__half2*)(o + 2048))[0] = midIsLo ? hp0 : lp0;
    ((__half2*)(o + 2048))[1] = midIsLo ? hp1 : lp1;
}

// ---------------- split fp32 -> bf16 x3 concat --------------------------------
__global__ __launch_bounds__(256) void split3b_kernel(
    const float* __restrict__ X, __nv_bfloat16* __restrict__ O, int midIsLo)
{
    size_t idx = (size_t)blockIdx.x * 256 + threadIdx.x;
    size_t m = idx >> 8;
    int kq = (int)(idx & 255) << 2;
    float4 v = *(const float4*)(X + m * 1024 + kq);
    float f[4] = {v.x, v.y, v.z, v.w};
    __nv_bfloat16 h[4], l[4];
    #pragma unroll
    for (int i = 0; i < 4; i++) {
        h[i] = __float2bfloat16(f[i]);
        l[i] = __float2bfloat16(f[i] - __bfloat162float(h[i]));
    }
    __nv_bfloat162 hp0 = __halves2bfloat162(h[0], h[1]);
    __nv_bfloat162 hp1 = __halves2bfloat162(h[2], h[3]);
    __nv_bfloat162 lp0 = __halves2bfloat162(l[0], l[1]);
    __nv_bfloat162 lp1 = __halves2bfloat162(l[2], l[3]);
    __nv_bfloat16* o = O + m * K3 + kq;
    ((__nv_bfloat162*)o)[0] = hp0;
    ((__nv_bfloat162*)o)[1] = hp1;
    ((__nv_bfloat162*)(o + 1024))[0] = midIsLo ? lp0 : hp0;
    ((__nv_bfloat162*)(o + 1024))[1] = midIsLo ? lp1 : hp1;
    ((__nv_bfloat162*)(o + 2048))[0] = midIsLo ? hp0 : lp0;
    ((__nv_bfloat162*)(o + 2048))[1] = midIsLo ? hp1 : lp1;
}

// ---------------- HMMA GEMM: C = (A . W^T) * outScale + bias ------------------
// moff: row-block offset (units of 128 rows) for partial-M launches.
template<bool FP16, int KTOT>
__global__ __launch_bounds__(256) void gemm_hmma(
    const void* __restrict__ A3v, const void* __restrict__ W3v,
    const float* __restrict__ bias, float* __restrict__ C, float outScale, int moff)
{
    constexpr int NCHUNK = KTOT / 64;
    constexpr int ROWB   = KTOT * 2;
    extern __shared__ __align__(128) char smem[];
    const uint32_t sb = smem_u32(smem);
    const int tid  = threadIdx.x;
    const int lane = tid & 31;
    const int wid  = tid >> 5;
    const int m0 = (blockIdx.y + moff) << 7;
    const int n0 = blockIdx.x << 7;
    const int wm = (wid >> 1) << 5;
    const int wn = (wid & 1) << 6;

    const char* Abase = (const char*)A3v + (size_t)m0 * ROWB;
    const char* Bbase = (const char*)W3v + (size_t)n0 * ROWB;

    const int lrow = tid >> 1;
    const int lc0  = (tid & 1) << 2;
    auto load_stage = [&](int chunk, int st) {
        const size_t gcol = (size_t)(chunk << 7);
        const uint32_t sa = sb + st * STAGE_B;
        #pragma unroll
        for (int c = 0; c < 4; c++) {
            int ch = lc0 + c;
            uint32_t soff = (lrow << 7) + (((ch ^ (lrow & 7))) << 4);
            cp16(sa + soff,         Abase + (size_t)lrow * ROWB + gcol + (ch << 4));
            cp16(sa + 16384 + soff, Bbase + (size_t)lrow * ROWB + gcol + (ch << 4));
        }
    };

    #pragma unroll
    for (int s = 0; s < NSTAGE; s++) {
        load_stage(s, s);
        asm volatile("cp.async.commit_group;" ::: "memory");
    }

    const int amln = wm + (lane & 15);
    const int acb  = (lane >> 4) << 4;
    const int asw  = (amln & 7) << 4;
    const int bnln = wn + (lane & 7) + ((lane & 16) >> 1);
    const int bcb  = (lane & 8) << 1;
    const int bsw  = (lane & 7) << 4;

    float acc[2][8][4] = {};

    for (int i = 0; i < NCHUNK; i++) {
        asm volatile("cp.async.wait_group %0;" :: "n"(NSTAGE - 1) : "memory");
        __syncthreads();
        const int st = i % NSTAGE;
        const uint32_t sa = sb + st * STAGE_B;
        const uint32_t sbB = sa + 16384;
        #pragma unroll
        for (int ks = 0; ks < 4; ks++) {
            uint32_t a[2][4];
            #pragma unroll
            for (int mi = 0; mi < 2; mi++) {
                uint32_t addr = sa + ((amln + (mi << 4)) << 7)
                              + (((ks << 5) + acb) ^ asw);
                ldm_x4(a[mi][0], a[mi][1], a[mi][2], a[mi][3], addr);
            }
            #pragma unroll
            for (int njp = 0; njp < 4; njp++) {
                uint32_t q0, q1, q2, q3;
                uint32_t addr = sbB + ((bnln + (njp << 4)) << 7)
                              + (((ks << 5) + bcb) ^ bsw);
                ldm_x4(q0, q1, q2, q3, addr);
                if (FP16) {
                    mma_f16(acc[0][2*njp],     a[0], q0, q1);
                    mma_f16(acc[0][2*njp + 1], a[0], q2, q3);
                    mma_f16(acc[1][2*njp],     a[1], q0, q1);
                    mma_f16(acc[1][2*njp + 1], a[1], q2, q3);
                } else {
                    mma_bf16(acc[0][2*njp],     a[0], q0, q1);
                    mma_bf16(acc[0][2*njp + 1], a[0], q2, q3);
                    mma_bf16(acc[1][2*njp],     a[1], q0, q1);
                    mma_bf16(acc[1][2*njp + 1], a[1], q2, q3);
                }
            }
        }
        __syncthreads();
        if (i + NSTAGE < NCHUNK) load_stage(i + NSTAGE, st);
        asm volatile("cp.async.commit_group;" ::: "memory");
    }

    const int rbase = m0 + wm + (lane >> 2);
    const int cbase = n0 + wn + ((lane & 3) << 1);
    #pragma unroll
    for (int mi = 0; mi < 2; mi++) {
        #pragma unroll
        for (int nj = 0; nj < 8; nj++) {
            int col = cbase + (nj << 3);
            float b0 = bias[col], b1 = bias[col + 1];
            float* p0 = C + (size_t)(rbase + (mi << 4)) * 1024 + col;
            float* p1 = p0 + 8 * 1024;
            float2 v0 = {acc[mi][nj][0] * outScale + b0, acc[mi][nj][1] * outScale + b1};
            float2 v1 = {acc[mi][nj][2] * outScale + b0, acc[mi][nj][3] * outScale + b1};
            *(float2*)p0 = v0;
            *(float2*)p1 = v1;
        }
    }
}

// ---------------- fp32 SGEMM + fused phi (bnoff selects column half) ----------
__global__ __launch_bounds__(256) void sgemm_phi(
    const float* __restrict__ A, const float* __restrict__ Bm,
    const float* __restrict__ bias,
    float* __restrict__ PQ, float* __restrict__ PK, int Kd, int bnoff)
{
    __shared__ float As[16][128];
    __shared__ float Bs[16][128];
    const int bm = blockIdx.y * 128;
    const int bn = (blockIdx.x + bnoff) * 128;
    const int tid = threadIdx.x;
    const int t0 = (tid >> 4) << 3;
    const int n0 = (tid & 15) << 3;
    const int lr = tid >> 2;
    const int lc = (tid & 3) << 2;
    const float* Ap = A + (size_t)(bm + lr) * Kd + lc;
    const float* Bp = Bm + (size_t)(bn + lr) * Kd + lc;
    const size_t half = (size_t)64 * Kd;

    float4 a0 = *(const float4*)(Ap);
    float4 a1 = *(const float4*)(Ap + half);
    float4 b0 = *(const float4*)(Bp);
    float4 b1 = *(const float4*)(Bp + half);

    float acc[8][8] = {};
    for (int k0 = 0; k0 < Kd; k0 += 16) {
        As[lc+0][lr]    = a0.x; As[lc+1][lr]    = a0.y; As[lc+2][lr]    = a0.z; As[lc+3][lr]    = a0.w;
        As[lc+0][lr+64] = a1.x; As[lc+1][lr+64] = a1.y; As[lc+2][lr+64] = a1.z; As[lc+3][lr+64] = a1.w;
        Bs[lc+0][lr]    = b0.x; Bs[lc+1][lr]    = b0.y; Bs[lc+2][lr]    = b0.z; Bs[lc+3][lr]    = b0.w;
        Bs[lc+0][lr+64] = b1.x; Bs[lc+1][lr+64] = b1.y; Bs[lc+2][lr+64] = b1.z; Bs[lc+3][lr+64] = b1.w;
        __syncthreads();
        if (k0 + 16 < Kd) {
            a0 = *(const float4*)(Ap + k0 + 16);
            a1 = *(const float4*)(Ap + k0 + 16 + half);
            b0 = *(const float4*)(Bp + k0 + 16);
            b1 = *(const float4*)(Bp + k0 + 16 + half);
        }
        #pragma unroll
        for (int kk = 0; kk < 16; kk++) {
            float4 x0 = *(const float4*)&As[kk][t0];
            float4 x1 = *(const float4*)&As[kk][t0+4];
            float4 y0 = *(const float4*)&Bs[kk][n0];
            float4 y1 = *(const float4*)&Bs[kk][n0+4];
            float ar[8] = {x0.x,x0.y,x0.z,x0.w,x1.x,x1.y,x1.z,x1.w};
            float br[8] = {y0.x,y0.y,y0.z,y0.w,y1.x,y1.y,y1.z,y1.w};
            #pragma unroll
            for (int i = 0; i < 8; i++)
                #pragma unroll
                for (int j = 0; j < 8; j++)
                    acc[i][j] = fmaf(ar[i], br[j], acc[i][j]);
        }
        __syncthreads();
    }

    float bb[8];
    #pragma unroll
    for (int j = 0; j < 8; j++) bb[j] = bias[bn + n0 + j];
    const int colg = bn + n0;
    float* OUTB = (colg < 512) ? PQ : PK;
    const int cc  = colg & 511;
    const int hh  = cc >> 6;
    const int kk0 = cc & 63;
    #pragma unroll
    for (int i = 0; i < 8; i++) {
        size_t base = (size_t)(bm + t0 + i) * 1024 + (hh << 7) + kk0;
        float sv[8], cv[8];
        #pragma unroll
        for (int j = 0; j < 8; j++) {
            float s, c;
            sincosf(acc[i][j] + bb[j], &s, &c);
            sv[j] = s * 0.125f;
            cv[j] = c * 0.125f;
        }
        float4 o;
        o.x=sv[0]; o.y=sv[1]; o.z=sv[2]; o.w=sv[3]; *(float4*)&OUTB[base]      = o;
        o.x=sv[4]; o.y=sv[5]; o.z=sv[6]; o.w=sv[7]; *(float4*)&OUTB[base + 4]  = o;
        o.x=cv[0]; o.y=cv[1]; o.z=cv[2]; o.w=cv[3]; *(float4*)&OUTB[base + 64] = o;
        o.x=cv[4]; o.y=cv[5]; o.z=cv[6]; o.w=cv[7]; *(float4*)&OUTB[base + 68] = o;
    }
}

// ---------------- per-chunk state + fused z -------------------------------------
__global__ __launch_bounds__(256) void chunk_state_kernel(
    const float* __restrict__ PK, const float* __restrict__ V,
    float* __restrict__ S, float* __restrict__ Z)
{
    __shared__ float as[16][128];
    __shared__ float bs[16][128];
    const int c = blockIdx.x, bh = blockIdx.y;
    const int b = bh >> 3, h = bh & 7;
    const int tid = threadIdx.x;
    const int t0 = (tid >> 4) << 3;
    const int n0 = (tid & 15) << 3;
    float acc[8][8] = {};
    float zacc = 0.f;

    for (int s0 = 0; s0 < CH; s0 += 16) {
        #pragma unroll
        for (int it = 0; it < 2; it++) {
            int idx = tid + (it << 8);
            int r  = idx >> 5;
            int c4 = (idx & 31) << 2;
            size_t grow = ((size_t)(c * CH + s0 + r) * B_ + b) * E_ + h * D_;
            *(float4*)&as[r][c4] = *(const float4*)(PK + grow + c4);
            *(float4*)&bs[r][c4] = *(const float4*)(V  + grow + c4);
        }
        __syncthreads();
        if (tid < 128) {
            float za = 0.f;
            #pragma unroll
            for (int ss = 0; ss < 16; ss++) za += as[ss][tid];
            zacc += za;
        }
        #pragma unroll
        for (int ss = 0; ss < 16; ss++) {
            float4 x0 = *(const float4*)&as[ss][t0];
            float4 x1 = *(const float4*)&as[ss][t0+4];
            float4 y0 = *(const float4*)&bs[ss][n0];
            float4 y1 = *(const float4*)&bs[ss][n0+4];
            float ar[8] = {x0.x,x0.y,x0.z,x0.w,x1.x,x1.y,x1.z,x1.w};
            float br[8] = {y0.x,y0.y,y0.z,y0.w,y1.x,y1.y,y1.z,y1.w};
            #pragma unroll
            for (int i = 0; i < 8; i++)
                #pragma unroll
                for (int j = 0; j < 8; j++)
                    acc[i][j] = fmaf(ar[i], br[j], acc[i][j]);
        }
        __syncthreads();
    }
    float* Sp = S + ((size_t)c * BHN + bh) * (K2 * D_);
    #pragma unroll
    for (int i = 0; i < 8; i++) {
        float4 o;
        o.x = acc[i][0]; o.y = acc[i][1]; o.z = acc[i][2]; o.w = acc[i][3];
        *(float4*)(Sp + (size_t)(t0 + i) * D_ + n0) = o;
        o.x = acc[i][4]; o.y = acc[i][5]; o.z = acc[i][6]; o.w = acc[i][7];
        *(float4*)(Sp + (size_t)(t0 + i) * D_ + n0 + 4) = o;
    }
    if (tid < 128)
        Z[((size_t)c * BHN + bh) * K2 + tid] = zacc;
}

__global__ void prefix_S_kernel(float* __restrict__ S)
{
    const int bh = blockIdx.x;
    const int e  = blockIdx.y * 256 + threadIdx.x;
    float acc = 0.f;
    for (int c = 0; c < NC; c++) {
        size_t idx = ((size_t)c * BHN + bh) * (K2 * D_) + e;
        float t = S[idx]; S[idx] = acc; acc += t;
    }
}

__global__ void prefix_z_kernel(float* __restrict__ Z)
{
    const int bh = blockIdx.x;
    const int k  = threadIdx.x;
    float acc = 0.f;
    for (int c = 0; c < NC; c++) {
        size_t idx = ((size_t)c * BHN + bh) * K2 + k;
        float t = Z[idx]; Z[idx] = acc; acc += t;
    }
}

// ---------------- RFA output (c0 = chunk offset for partial launches) -----------
#define RFA_SMEM ((128*132 + 2*16*132) * 4)   // 84480 B
__global__ __launch_bounds__(256) void rfa_out_kernel(
    const float* __restrict__ PQ, const float* __restrict__ PK,
    const float* __restrict__ V,  const float* __restrict__ S,
    const float* __restrict__ Z,  __nv_bfloat16* __restrict__ A3, int c0)
{
    extern __shared__ float sm[];
    float* SC = sm;
    float* TA = sm + 128 * 132;
    float* TB = TA + 16 * 132;

    const int c = blockIdx.x + c0, bh = blockIdx.y;
    const int b = bh >> 3, h = bh & 7;
    const int tid = threadIdx.x;
    const int t0 = (tid >> 4) << 3;
    const int n0 = (tid & 15) << 3;

    float sc[8][8] = {};
    for (int kt = 0; kt < 8; kt++) {
        #pragma unroll
        for (int it = 0; it < 2; it++) {
            int idx = tid + (it << 8);
            int r  = idx >> 2;
            int c4 = (idx & 3) << 2;
            size_t grow = ((size_t)(c * CH + r) * B_ + b) * E_ + h * K2 + (kt << 4) + c4;
            float4 vq = *(const float4*)(PQ + grow);
            TA[(c4+0)*132 + r] = vq.x; TA[(c4+1)*132 + r] = vq.y;
            TA[(c4+2)*132 + r] = vq.z; TA[(c4+3)*132 + r] = vq.w;
            float4 vk = *(const float4*)(PK + grow);
            TB[(c4+0)*132 + r] = vk.x; TB[(c4+1)*132 + r] = vk.y;
            TB[(c4+2)*132 + r] = vk.z; TB[(c4+3)*132 + r] = vk.w;
        }
        __syncthreads();
        #pragma unroll
        for (int kk = 0; kk < 16; kk++) {
            float4 x0 = *(const float4*)&TA[kk*132 + t0];
            float4 x1 = *(const float4*)&TA[kk*132 + t0 + 4];
            float4 y0 = *(const float4*)&TB[kk*132 + n0];
            float4 y1 = *(const float4*)&TB[kk*132 + n0 + 4];
            float ar[8] = {x0.x,x0.y,x0.z,x0.w,x1.x,x1.y,x1.z,x1.w};
            float br[8] = {y0.x,y0.y,y0.z,y0.w,y1.x,y1.y,y1.z,y1.w};
            #pragma unroll
            for (int i = 0; i < 8; i++)
                #pragma unroll
                for (int j = 0; j < 8; j++)
                    sc[i][j] = fmaf(ar[i], br[j], sc[i][j]);
        }
        __syncthreads();
    }
    #pragma unroll
    for (int j = 0; j < 8; j++)
        #pragma unroll
        for (int i = 0; i < 8; i++)
            SC[(size_t)(n0 + j) * 132 + (t0 + i)] = (n0 + j <= t0 + i) ? sc[i][j] : 0.0f;
    __syncthreads();

    float acc[8][8] = {};
    float dacc[8] = {};
    const float* Sp = S + ((size_t)c * BHN + bh) * (K2 * D_);
    const float* zp = Z + ((size_t)c * BHN + bh) * K2;
    for (int kt = 0; kt < 16; kt++) {
        const int rbase = kt << 4;
        #pragma unroll
        for (int it = 0; it < 2; it++) {
            int idx = tid + (it << 8);
            int r  = idx >> 5;
            int c4 = (idx & 31) << 2;
            int rr = rbase + r;
            float4 vv;
            if (rr < 128)
                vv = *(const float4*)(V + ((size_t)(c * CH + rr) * B_ + b) * E_ + h * D_ + c4);
            else
                vv = *(const float4*)(Sp + (size_t)(rr - 128) * D_ + c4);
            *(float4*)&TB[r * 132 + c4] = vv;
        }
        if (tid < 16) {
            int rr = rbase + tid;
            TB[tid * 132 + 128] = (rr < 128) ? 1.0f : zp[rr - 128];
        }
        if (rbase >= 128) {
            #pragma unroll
            for (int it = 0; it < 2; it++) {
                int idx = tid + (it << 8);
                int r  = idx >> 2;
                int c4 = (idx & 3) << 2;
                size_t grow = ((size_t)(c * CH + r) * B_ + b) * E_ + h * K2
                            + (rbase - 128) + c4;
                float4 vq = *(const float4*)(PQ + grow);
                TA[(c4+0)*132 + r] = vq.x; TA[(c4+1)*132 + r] = vq.y;
                TA[(c4+2)*132 + r] = vq.z; TA[(c4+3)*132 + r] = vq.w;
            }
        }
        __syncthreads();
        const float* Aop = (rbase < 128) ? (SC + (size_t)rbase * 132) : TA;
        #pragma unroll
        for (int ss = 0; ss < 16; ss++) {
            const float* arow = Aop + (size_t)ss * 132;
            float4 x0 = *(const float4*)(arow + t0);
            float4 x1 = *(const float4*)(arow + t0 + 4);
            float ar[8] = {x0.x,x0.y,x0.z,x0.w,x1.x,x1.y,x1.z,x1.w};
            float4 y0 = *(const float4*)&TB[ss * 132 + n0];
            float4 y1 = *(const float4*)&TB[ss * 132 + n0 + 4];
            float br[8] = {y0.x,y0.y,y0.z,y0.w,y1.x,y1.y,y1.z,y1.w};
            float bv = TB[ss * 132 + 128];
            #pragma unroll
            for (int i = 0; i < 8; i++) {
                dacc[i] = fmaf(ar[i], bv, dacc[i]);
                #pragma unroll
                for (int j = 0; j < 8; j++)
                    acc[i][j] = fmaf(ar[i], br[j], acc[i][j]);
            }
        }
        __syncthreads();
    }

    #pragma unroll
    for (int i = 0; i < 8; i++) {
        float inv = 1.0f / fmaxf(dacc[i], EPSV);
        size_t m = (size_t)(c * CH + t0 + i) * B_ + b;
        __nv_bfloat16* o = A3 + m * K3 + h * D_ + n0;
        __nv_bfloat16 hh[8], ll[8];
        #pragma unroll
        for (int j = 0; j < 8; j++) {
            float ov = acc[i][j] * inv;
            hh[j] = __float2bfloat16(ov);
            ll[j] = __float2bfloat16(ov - __bfloat162float(hh[j]));
        }
        #pragma unroll
        for (int j = 0; j < 4; j++) {
            __nv_bfloat162 hp = __halves2bfloat162(hh[2*j], hh[2*j+1]);
            __nv_bfloat162 lp = __halves2bfloat162(ll[2*j], ll[2*j+1]);
            ((__nv_bfloat162*)(o))[j]        = hp;
            ((__nv_bfloat162*)(o + 1024))[j] = lp;
            ((__nv_bfloat162*)(o + 2048))[j] = hp;
        }
    }
}

// ---------------- launcher -----------------------------------------------------
extern "C" void kernel_launch(void* const* d_in, const int* in_sizes, int n_in,
                              void* d_out, int out_size)
{
    const float* x   = (const float*)d_in[0];
    const float* rm  = (const float*)d_in[1];
    const float* Wq  = (const float*)d_in[2];
    const float* bq  = (const float*)d_in[3];
    const float* Wk  = (const float*)d_in[4];
    const float* bk  = (const float*)d_in[5];
    const float* Wv  = (const float*)d_in[6];
    const float* bv  = (const float*)d_in[7];
    const float* Wo  = (const float*)d_in[8];
    const float* bo  = (const float*)d_in[9];
    const float* sig = (const float*)d_in[10];
    float* out = (float*)d_out;

    float *v, *pq, *pk, *S, *z, *M, *pb;
    __half *a3, *wv3, *wo3;
    cudaGetSymbolAddress((void**)&v,    g_v);
    cudaGetSymbolAddress((void**)&pq,   g_pq);
    cudaGetSymbolAddress((void**)&pk,   g_pk);
    cudaGetSymbolAddress((void**)&S,    g_S);
    cudaGetSymbolAddress((void**)&z,    g_z);
    cudaGetSymbolAddress((void**)&M,    g_M);
    cudaGetSymbolAddress((void**)&pb,   g_pb);
    cudaGetSymbolAddress((void**)&a3,   g_a3);
    cudaGetSymbolAddress((void**)&wv3,  g_wv3);
    cudaGetSymbolAddress((void**)&wo3,  g_wo3);

    cudaFuncSetAttribute(rfa_out_kernel,
                         cudaFuncAttributeMaxDynamicSharedMemorySize, RFA_SMEM);
    cudaFuncSetAttribute(rfa_out_kernel,
                         cudaFuncAttributePreferredSharedMemoryCarveout, 100);
    cudaFuncSetAttribute((const void*)gemm_hmma<true, 3072>,
                         cudaFuncAttributeMaxDynamicSharedMemorySize, GEMM_SMEM);
    cudaFuncSetAttribute((const void*)gemm_hmma<true, 3072>,
                         cudaFuncAttributePreferredSharedMemoryCarveout, 100);
    cudaFuncSetAttribute((const void*)gemm_hmma<false, 3072>,
                         cudaFuncAttributeMaxDynamicSharedMemorySize, GEMM_SMEM);
    cudaFuncSetAttribute((const void*)gemm_hmma<false, 3072>,
                         cudaFuncAttributePreferredSharedMemoryCarveout, 100);

    const float invW = 1.0f / WSCALE;
    dim3 ghmma(E_ / 128, MR / 128);        // full-M HMMA (v projection)
    dim3 ghalfO(E_ / 128, MR / 256);       // half-M HMMA (O projection halves)
    dim3 gphi_half(4, MR / 128);           // half-N sgemm_phi
    dim3 grfa_half(NC / 2, BHN);           // half-chunk rfa

    cudaStream_t s1;
    cudaStreamCreateWithFlags(&s1, cudaStreamNonBlocking);
    cudaEvent_t eK, ePre, eR1, eO1;
    cudaEventCreateWithFlags(&eK,   cudaEventDisableTiming);
    cudaEventCreateWithFlags(&ePre, cudaEventDisableTiming);
    cudaEventCreateWithFlags(&eR1,  cudaEventDisableTiming);
    cudaEventCreateWithFlags(&eO1,  cudaEventDisableTiming);

    // --- stream 1: v path starts immediately (independent of prep_M) ---
    split3h_kernel<<<MR, 256, 0, s1>>>(x, a3, 1, 1.0f);
    split3h_kernel<<<1024, 256, 0, s1>>>(Wv, wv3, 0, WSCALE);
    gemm_hmma<true, 3072><<<ghmma, 256, GEMM_SMEM, s1>>>(a3, wv3, bv, v, invW, 0);
    split3b_kernel<<<1024, 256, 0, s1>>>(Wo, (__nv_bfloat16*)wo3, 0);

    // --- stream 0: prep then PK-half of the fused projection ---
    prep_M<<<1024, 128>>>(rm, sig, Wq, Wk, bq, bk, M, pb);
    sgemm_phi<<<gphi_half, 256>>>(x, M, pb, pq, pk, 1024, 4);   // cols 512..1023 -> PK
    cudaEventRecord(eK, 0);

    // --- stream 0 continues with PQ half while s1 does the chunk path ---
    sgemm_phi<<<gphi_half, 256>>>(x, M, pb, pq, pk, 1024, 0);   // cols 0..511 -> PQ

    cudaStreamWaitEvent(s1, eK, 0);        // s1 already has v done (in-order)
    dim3 gcs(NC, BHN);
    chunk_state_kernel<<<gcs, 256, 0, s1>>>(pk, v, S, z);
    prefix_S_kernel<<<dim3(BHN, 64), 256, 0, s1>>>(S);
    prefix_z_kernel<<<BHN, 128, 0, s1>>>(z);
    cudaEventRecord(ePre, s1);

    // --- rfa/O pipeline: rfa1 -> [O1 on s1 || rfa2 on s0] -> O2 on s0 ---
    cudaStreamWaitEvent(0, ePre, 0);
    rfa_out_kernel<<<grfa_half, 256, RFA_SMEM>>>(pq, pk, v, S, z,
                                                 (__nv_bfloat16*)a3, 0);
    cudaEventRecord(eR1, 0);
    rfa_out_kernel<<<grfa_half, 256, RFA_SMEM>>>(pq, pk, v, S, z,
                                                 (__nv_bfloat16*)a3, NC / 2);

    cudaStreamWaitEvent(s1, eR1, 0);
    gemm_hmma<false, 3072><<<ghalfO, 256, GEMM_SMEM, s1>>>(a3, wo3, bo, out, 1.0f, 0);
    cudaEventRecord(eO1, s1);

    gemm_hmma<false, 3072><<<ghalfO, 256, GEMM_SMEM>>>(a3, wo3, bo, out, 1.0f, MR / 256);

    // join s1 back into the capture origin stream
    cudaStreamWaitEvent(0, eO1, 0);
}

// round 13
// speedup vs baseline: 1.2322x; 1.0402x over previous
#include <cuda_runtime.h>
#include <cuda_bf16.h>
#include <cuda_fp16.h>
#include <cstdint>

#define T_    4096
#define B_    8
#define E_    1024
#define H_    8
#define D_    128
#define KP    64
#define K2    128
#define CH    128
#define NC    32
#define MR    32768
#define BHN   64
#define EPSV  1e-6f

#define K3        3072
#define NSTAGE    2
#define STAGE_B   32768
#define GEMM_SMEM (NSTAGE * STAGE_B)   // 64KB
#define WSCALE    1024.0f

// ---------------- scratch ---------------------------------------------------
__device__ float g_v[33554432];
__device__ float g_pq[33554432];
__device__ float g_pk[33554432];
__device__ float g_S[33554432];
__device__ float g_z[262144];
__device__ float g_M[1048576];
__device__ float g_pb[1024];
__device__ __half g_a3[100663296];   // [MR][3072] x fp16x3, later attn bf16x3 (reuse)
__device__ __half g_wv3[3145728];    // Wv fp16x3
__device__ __half g_wo3[3145728];    // Wo bf16x3 (bits in half storage)

// ---------------- PTX helpers -----------------------------------------------
__device__ __forceinline__ uint32_t smem_u32(const void* p) {
    uint32_t a;
    asm("{ .reg .u64 t; cvta.to.shared.u64 t, %1; cvt.u32.u64 %0, t; }"
        : "=r"(a) : "l"(p));
    return a;
}
__device__ __forceinline__ void cp16(uint32_t dst, const void* src) {
    asm volatile("cp.async.cg.shared.global [%0], [%1], 16;" :: "r"(dst), "l"(src));
}
__device__ __forceinline__ void ldm_x4(uint32_t& r0, uint32_t& r1,
                                       uint32_t& r2, uint32_t& r3, uint32_t addr) {
    asm volatile("ldmatrix.sync.aligned.m8n8.x4.shared.b16 {%0,%1,%2,%3}, [%4];"
                 : "=r"(r0), "=r"(r1), "=r"(r2), "=r"(r3) : "r"(addr));
}
__device__ __forceinline__ void mma_f16(float* c, const uint32_t* a,
                                        uint32_t b0, uint32_t b1) {
    asm volatile(
        "mma.sync.aligned.m16n8k16.row.col.f32.f16.f16.f32 "
        "{%0,%1,%2,%3}, {%4,%5,%6,%7}, {%8,%9}, {%0,%1,%2,%3};"
        : "+f"(c[0]), "+f"(c[1]), "+f"(c[2]), "+f"(c[3])
        : "r"(a[0]), "r"(a[1]), "r"(a[2]), "r"(a[3]), "r"(b0), "r"(b1));
}
__device__ __forceinline__ void mma_bf16(float* c, const uint32_t* a,
                                         uint32_t b0, uint32_t b1) {
    asm volatile(
        "mma.sync.aligned.m16n8k16.row.col.f32.bf16.bf16.f32 "
        "{%0,%1,%2,%3}, {%4,%5,%6,%7}, {%8,%9}, {%0,%1,%2,%3};"
        : "+f"(c[0]), "+f"(c[1]), "+f"(c[2]), "+f"(c[3])
        : "r"(a[0]), "r"(a[1]), "r"(a[2]), "r"(a[3]), "r"(b0), "r"(b1));
}

// ---------------- prep: fused q/k projection matrix + bias -------------------
__global__ __launch_bounds__(128) void prep_M(
    const float* __restrict__ rm, const float* __restrict__ sig,
    const float* __restrict__ Wq, const float* __restrict__ Wk,
    const float* __restrict__ bq, const float* __restrict__ bk,
    float* __restrict__ M, float* __restrict__ pb)
{
    const int row = blockIdx.x;
    const int isK = row >> 9;
    const int h   = (row >> 6) & 7;
    const int kk  = row & 63;
    const float* W  = isK ? Wk : Wq;
    const float* bb = isK ? bk : bq;
    __shared__ float r[128];
    const int tid = threadIdx.x;
    const float c = 0.29730177875068026f;
    r[tid] = c * sig[h * 128 + tid] * rm[((size_t)(h * 64 + kk)) * 128 + tid];
    __syncthreads();
    for (int e = tid; e < 1024; e += 128) {
        float acc = 0.f;
        #pragma unroll 8
        for (int d = 0; d < 128; d++)
            acc = fmaf(r[d], W[(size_t)(h * 128 + d) * 1024 + e], acc);
        M[(size_t)row * 1024 + e] = acc;
    }
    if (tid == 0) {
        float acc = 0.f;
        for (int d = 0; d < 128; d++) acc = fmaf(r[d], bb[h * 128 + d], acc);
        pb[row] = acc;
    }
}

// ---------------- split fp32 -> fp16 x3 concat --------------------------------
__global__ __launch_bounds__(256) void split3h_kernel(
    const float* __restrict__ X, __half* __restrict__ O, int midIsLo, float scale)
{
    size_t idx = (size_t)blockIdx.x * 256 + threadIdx.x;
    size_t m = idx >> 8;
    int kq = (int)(idx & 255) << 2;
    float4 v = *(const float4*)(X + m * 1024 + kq);
    float f[4] = {v.x * scale, v.y * scale, v.z * scale, v.w * scale};
    __half h[4], l[4];
    #pragma unroll
    for (int i = 0; i < 4; i++) {
        h[i] = __float2half(f[i]);
        l[i] = __float2half(f[i] - __half2float(h[i]));
    }
    __half2 hp0 = __halves2half2(h[0], h[1]);
    __half2 hp1 = __halves2half2(h[2], h[3]);
    __half2 lp0 = __halves2half2(l[0], l[1]);
    __half2 lp1 = __halves2half2(l[2], l[3]);
    __half* o = O + m * K3 + kq;
    ((__half2*)o)[0] = hp0;
    ((__half2*)o)[1] = hp1;
    ((__half2*)(o + 1024))[0] = midIsLo ? lp0 : hp0;
    ((__half2*)(o + 1024))[1] = midIsLo ? lp1 : hp1;
    ((__half2*)(o + 2048))[0] = midIsLo ? hp0 : lp0;
    ((__half2*)(o + 2048))[1] = midIsLo ? hp1 : lp1;
}

// ---------------- split fp32 -> bf16 x3 concat --------------------------------
__global__ __launch_bounds__(256) void split3b_kernel(
    const float* __restrict__ X, __nv_bfloat16* __restrict__ O, int midIsLo)
{
    size_t idx = (size_t)blockIdx.x * 256 + threadIdx.x;
    size_t m = idx >> 8;
    int kq = (int)(idx & 255) << 2;
    float4 v = *(const float4*)(X + m * 1024 + kq);
    float f[4] = {v.x, v.y, v.z, v.w};
    __nv_bfloat16 h[4], l[4];
    #pragma unroll
    for (int i = 0; i < 4; i++) {
        h[i] = __float2bfloat16(f[i]);
        l[i] = __float2bfloat16(f[i] - __bfloat162float(h[i]));
    }
    __nv_bfloat162 hp0 = __halves2bfloat162(h[0], h[1]);
    __nv_bfloat162 hp1 = __halves2bfloat162(h[2], h[3]);
    __nv_bfloat162 lp0 = __halves2bfloat162(l[0], l[1]);
    __nv_bfloat162 lp1 = __halves2bfloat162(l[2], l[3]);
    __nv_bfloat16* o = O + m * K3 + kq;
    ((__nv_bfloat162*)o)[0] = hp0;
    ((__nv_bfloat162*)o)[1] = hp1;
    ((__nv_bfloat162*)(o + 1024))[0] = midIsLo ? lp0 : hp0;
    ((__nv_bfloat162*)(o + 1024))[1] = midIsLo ? lp1 : hp1;
    ((__nv_bfloat162*)(o + 2048))[0] = midIsLo ? hp0 : lp0;
    ((__nv_bfloat162*)(o + 2048))[1] = midIsLo ? hp1 : lp1;
}

// ---------------- HMMA GEMM: C = (A . W^T) * outScale + bias ------------------
template<bool FP16, int KTOT>
__global__ __launch_bounds__(256) void gemm_hmma(
    const void* __restrict__ A3v, const void* __restrict__ W3v,
    const float* __restrict__ bias, float* __restrict__ C, float outScale, int moff)
{
    constexpr int NCHUNK = KTOT / 64;
    constexpr int ROWB   = KTOT * 2;
    extern __shared__ __align__(128) char smem[];
    const uint32_t sb = smem_u32(smem);
    const int tid  = threadIdx.x;
    const int lane = tid & 31;
    const int wid  = tid >> 5;
    const int m0 = (blockIdx.y + moff) << 7;
    const int n0 = blockIdx.x << 7;
    const int wm = (wid >> 1) << 5;
    const int wn = (wid & 1) << 6;

    const char* Abase = (const char*)A3v + (size_t)m0 * ROWB;
    const char* Bbase = (const char*)W3v + (size_t)n0 * ROWB;

    const int lrow = tid >> 1;
    const int lc0  = (tid & 1) << 2;
    auto load_stage = [&](int chunk, int st) {
        const size_t gcol = (size_t)(chunk << 7);
        const uint32_t sa = sb + st * STAGE_B;
        #pragma unroll
        for (int c = 0; c < 4; c++) {
            int ch = lc0 + c;
            uint32_t soff = (lrow << 7) + (((ch ^ (lrow & 7))) << 4);
            cp16(sa + soff,         Abase + (size_t)lrow * ROWB + gcol + (ch << 4));
            cp16(sa + 16384 + soff, Bbase + (size_t)lrow * ROWB + gcol + (ch << 4));
        }
    };

    #pragma unroll
    for (int s = 0; s < NSTAGE; s++) {
        load_stage(s, s);
        asm volatile("cp.async.commit_group;" ::: "memory");
    }

    const int amln = wm + (lane & 15);
    const int acb  = (lane >> 4) << 4;
    const int asw  = (amln & 7) << 4;
    const int bnln = wn + (lane & 7) + ((lane & 16) >> 1);
    const int bcb  = (lane & 8) << 1;
    const int bsw  = (lane & 7) << 4;

    float acc[2][8][4] = {};

    for (int i = 0; i < NCHUNK; i++) {
        asm volatile("cp.async.wait_group %0;" :: "n"(NSTAGE - 1) : "memory");
        __syncthreads();
        const int st = i % NSTAGE;
        const uint32_t sa = sb + st * STAGE_B;
        const uint32_t sbB = sa + 16384;
        #pragma unroll
        for (int ks = 0; ks < 4; ks++) {
            uint32_t a[2][4];
            #pragma unroll
            for (int mi = 0; mi < 2; mi++) {
                uint32_t addr = sa + ((amln + (mi << 4)) << 7)
                              + (((ks << 5) + acb) ^ asw);
                ldm_x4(a[mi][0], a[mi][1], a[mi][2], a[mi][3], addr);
            }
            #pragma unroll
            for (int njp = 0; njp < 4; njp++) {
                uint32_t q0, q1, q2, q3;
                uint32_t addr = sbB + ((bnln + (njp << 4)) << 7)
                              + (((ks << 5) + bcb) ^ bsw);
                ldm_x4(q0, q1, q2, q3, addr);
                if (FP16) {
                    mma_f16(acc[0][2*njp],     a[0], q0, q1);
                    mma_f16(acc[0][2*njp + 1], a[0], q2, q3);
                    mma_f16(acc[1][2*njp],     a[1], q0, q1);
                    mma_f16(acc[1][2*njp + 1], a[1], q2, q3);
                } else {
                    mma_bf16(acc[0][2*njp],     a[0], q0, q1);
                    mma_bf16(acc[0][2*njp + 1], a[0], q2, q3);
                    mma_bf16(acc[1][2*njp],     a[1], q0, q1);
                    mma_bf16(acc[1][2*njp + 1], a[1], q2, q3);
                }
            }
        }
        __syncthreads();
        if (i + NSTAGE < NCHUNK) load_stage(i + NSTAGE, st);
        asm volatile("cp.async.commit_group;" ::: "memory");
    }

    const int rbase = m0 + wm + (lane >> 2);
    const int cbase = n0 + wn + ((lane & 3) << 1);
    #pragma unroll
    for (int mi = 0; mi < 2; mi++) {
        #pragma unroll
        for (int nj = 0; nj < 8; nj++) {
            int col = cbase + (nj << 3);
            float b0 = bias[col], b1 = bias[col + 1];
            float* p0 = C + (size_t)(rbase + (mi << 4)) * 1024 + col;
            float* p1 = p0 + 8 * 1024;
            float2 v0 = {acc[mi][nj][0] * outScale + b0, acc[mi][nj][1] * outScale + b1};
            float2 v1 = {acc[mi][nj][2] * outScale + b0, acc[mi][nj][3] * outScale + b1};
            *(float2*)p0 = v0;
            *(float2*)p1 = v1;
        }
    }
}

// ---------------- fp32 SGEMM + fused phi (bnoff = N offset, moff = M offset) --
__global__ __launch_bounds__(256) void sgemm_phi(
    const float* __restrict__ A, const float* __restrict__ Bm,
    const float* __restrict__ bias,
    float* __restrict__ PQ, float* __restrict__ PK, int Kd, int bnoff, int moff)
{
    __shared__ float As[16][128];
    __shared__ float Bs[16][128];
    const int bm = (blockIdx.y + moff) * 128;
    const int bn = (blockIdx.x + bnoff) * 128;
    const int tid = threadIdx.x;
    const int t0 = (tid >> 4) << 3;
    const int n0 = (tid & 15) << 3;
    const int lr = tid >> 2;
    const int lc = (tid & 3) << 2;
    const float* Ap = A + (size_t)(bm + lr) * Kd + lc;
    const float* Bp = Bm + (size_t)(bn + lr) * Kd + lc;
    const size_t half = (size_t)64 * Kd;

    float4 a0 = *(const float4*)(Ap);
    float4 a1 = *(const float4*)(Ap + half);
    float4 b0 = *(const float4*)(Bp);
    float4 b1 = *(const float4*)(Bp + half);

    float acc[8][8] = {};
    for (int k0 = 0; k0 < Kd; k0 += 16) {
        As[lc+0][lr]    = a0.x; As[lc+1][lr]    = a0.y; As[lc+2][lr]    = a0.z; As[lc+3][lr]    = a0.w;
        As[lc+0][lr+64] = a1.x; As[lc+1][lr+64] = a1.y; As[lc+2][lr+64] = a1.z; As[lc+3][lr+64] = a1.w;
        Bs[lc+0][lr]    = b0.x; Bs[lc+1][lr]    = b0.y; Bs[lc+2][lr]    = b0.z; Bs[lc+3][lr]    = b0.w;
        Bs[lc+0][lr+64] = b1.x; Bs[lc+1][lr+64] = b1.y; Bs[lc+2][lr+64] = b1.z; Bs[lc+3][lr+64] = b1.w;
        __syncthreads();
        if (k0 + 16 < Kd) {
            a0 = *(const float4*)(Ap + k0 + 16);
            a1 = *(const float4*)(Ap + k0 + 16 + half);
            b0 = *(const float4*)(Bp + k0 + 16);
            b1 = *(const float4*)(Bp + k0 + 16 + half);
        }
        #pragma unroll
        for (int kk = 0; kk < 16; kk++) {
            float4 x0 = *(const float4*)&As[kk][t0];
            float4 x1 = *(const float4*)&As[kk][t0+4];
            float4 y0 = *(const float4*)&Bs[kk][n0];
            float4 y1 = *(const float4*)&Bs[kk][n0+4];
            float ar[8] = {x0.x,x0.y,x0.z,x0.w,x1.x,x1.y,x1.z,x1.w};
            float br[8] = {y0.x,y0.y,y0.z,y0.w,y1.x,y1.y,y1.z,y1.w};
            #pragma unroll
            for (int i = 0; i < 8; i++)
                #pragma unroll
                for (int j = 0; j < 8; j++)
                    acc[i][j] = fmaf(ar[i], br[j], acc[i][j]);
        }
        __syncthreads();
    }

    float bb[8];
    #pragma unroll
    for (int j = 0; j < 8; j++) bb[j] = bias[bn + n0 + j];
    const int colg = bn + n0;
    float* OUTB = (colg < 512) ? PQ : PK;
    const int cc  = colg & 511;
    const int hh  = cc >> 6;
    const int kk0 = cc & 63;
    #pragma unroll
    for (int i = 0; i < 8; i++) {
        size_t base = (size_t)(bm + t0 + i) * 1024 + (hh << 7) + kk0;
        float sv[8], cv[8];
        #pragma unroll
        for (int j = 0; j < 8; j++) {
            float s, c;
            sincosf(acc[i][j] + bb[j], &s, &c);
            sv[j] = s * 0.125f;
            cv[j] = c * 0.125f;
        }
        float4 o;
        o.x=sv[0]; o.y=sv[1]; o.z=sv[2]; o.w=sv[3]; *(float4*)&OUTB[base]      = o;
        o.x=sv[4]; o.y=sv[5]; o.z=sv[6]; o.w=sv[7]; *(float4*)&OUTB[base + 4]  = o;
        o.x=cv[0]; o.y=cv[1]; o.z=cv[2]; o.w=cv[3]; *(float4*)&OUTB[base + 64] = o;
        o.x=cv[4]; o.y=cv[5]; o.z=cv[6]; o.w=cv[7]; *(float4*)&OUTB[base + 68] = o;
    }
}

// ---------------- per-chunk state + fused z -------------------------------------
__global__ __launch_bounds__(256) void chunk_state_kernel(
    const float* __restrict__ PK, const float* __restrict__ V,
    float* __restrict__ S, float* __restrict__ Z)
{
    __shared__ float as[16][128];
    __shared__ float bs[16][128];
    const int c = blockIdx.x, bh = blockIdx.y;
    const int b = bh >> 3, h = bh & 7;
    const int tid = threadIdx.x;
    const int t0 = (tid >> 4) << 3;
    const int n0 = (tid & 15) << 3;
    float acc[8][8] = {};
    float zacc = 0.f;

    for (int s0 = 0; s0 < CH; s0 += 16) {
        #pragma unroll
        for (int it = 0; it < 2; it++) {
            int idx = tid + (it << 8);
            int r  = idx >> 5;
            int c4 = (idx & 31) << 2;
            size_t grow = ((size_t)(c * CH + s0 + r) * B_ + b) * E_ + h * D_;
            *(float4*)&as[r][c4] = *(const float4*)(PK + grow + c4);
            *(float4*)&bs[r][c4] = *(const float4*)(V  + grow + c4);
        }
        __syncthreads();
        if (tid < 128) {
            float za = 0.f;
            #pragma unroll
            for (int ss = 0; ss < 16; ss++) za += as[ss][tid];
            zacc += za;
        }
        #pragma unroll
        for (int ss = 0; ss < 16; ss++) {
            float4 x0 = *(const float4*)&as[ss][t0];
            float4 x1 = *(const float4*)&as[ss][t0+4];
            float4 y0 = *(const float4*)&bs[ss][n0];
            float4 y1 = *(const float4*)&bs[ss][n0+4];
            float ar[8] = {x0.x,x0.y,x0.z,x0.w,x1.x,x1.y,x1.z,x1.w};
            float br[8] = {y0.x,y0.y,y0.z,y0.w,y1.x,y1.y,y1.z,y1.w};
            #pragma unroll
            for (int i = 0; i < 8; i++)
                #pragma unroll
                for (int j = 0; j < 8; j++)
                    acc[i][j] = fmaf(ar[i], br[j], acc[i][j]);
        }
        __syncthreads();
    }
    float* Sp = S + ((size_t)c * BHN + bh) * (K2 * D_);
    #pragma unroll
    for (int i = 0; i < 8; i++) {
        float4 o;
        o.x = acc[i][0]; o.y = acc[i][1]; o.z = acc[i][2]; o.w = acc[i][3];
        *(float4*)(Sp + (size_t)(t0 + i) * D_ + n0) = o;
        o.x = acc[i][4]; o.y = acc[i][5]; o.z = acc[i][6]; o.w = acc[i][7];
        *(float4*)(Sp + (size_t)(t0 + i) * D_ + n0 + 4) = o;
    }
    if (tid < 128)
        Z[((size_t)c * BHN + bh) * K2 + tid] = zacc;
}

__global__ void prefix_S_kernel(float* __restrict__ S)
{
    const int bh = blockIdx.x;
    const int e  = blockIdx.y * 256 + threadIdx.x;
    float acc = 0.f;
    for (int c = 0; c < NC; c++) {
        size_t idx = ((size_t)c * BHN + bh) * (K2 * D_) + e;
        float t = S[idx]; S[idx] = acc; acc += t;
    }
}

__global__ void prefix_z_kernel(float* __restrict__ Z)
{
    const int bh = blockIdx.x;
    const int k  = threadIdx.x;
    float acc = 0.f;
    for (int c = 0; c < NC; c++) {
        size_t idx = ((size_t)c * BHN + bh) * K2 + k;
        float t = Z[idx]; Z[idx] = acc; acc += t;
    }
}

// ---------------- RFA output (c0 = chunk offset for partial launches) -----------
#define RFA_SMEM ((128*132 + 2*16*132) * 4)   // 84480 B
__global__ __launch_bounds__(256) void rfa_out_kernel(
    const float* __restrict__ PQ, const float* __restrict__ PK,
    const float* __restrict__ V,  const float* __restrict__ S,
    const float* __restrict__ Z,  __nv_bfloat16* __restrict__ A3, int c0)
{
    extern __shared__ float sm[];
    float* SC = sm;
    float* TA = sm + 128 * 132;
    float* TB = TA + 16 * 132;

    const int c = blockIdx.x + c0, bh = blockIdx.y;
    const int b = bh >> 3, h = bh & 7;
    const int tid = threadIdx.x;
    const int t0 = (tid >> 4) << 3;
    const int n0 = (tid & 15) << 3;

    float sc[8][8] = {};
    for (int kt = 0; kt < 8; kt++) {
        #pragma unroll
        for (int it = 0; it < 2; it++) {
            int idx = tid + (it << 8);
            int r  = idx >> 2;
            int c4 = (idx & 3) << 2;
            size_t grow = ((size_t)(c * CH + r) * B_ + b) * E_ + h * K2 + (kt << 4) + c4;
            float4 vq = *(const float4*)(PQ + grow);
            TA[(c4+0)*132 + r] = vq.x; TA[(c4+1)*132 + r] = vq.y;
            TA[(c4+2)*132 + r] = vq.z; TA[(c4+3)*132 + r] = vq.w;
            float4 vk = *(const float4*)(PK + grow);
            TB[(c4+0)*132 + r] = vk.x; TB[(c4+1)*132 + r] = vk.y;
            TB[(c4+2)*132 + r] = vk.z; TB[(c4+3)*132 + r] = vk.w;
        }
        __syncthreads();
        #pragma unroll
        for (int kk = 0; kk < 16; kk++) {
            float4 x0 = *(const float4*)&TA[kk*132 + t0];
            float4 x1 = *(const float4*)&TA[kk*132 + t0 + 4];
            float4 y0 = *(const float4*)&TB[kk*132 + n0];
            float4 y1 = *(const float4*)&TB[kk*132 + n0 + 4];
            float ar[8] = {x0.x,x0.y,x0.z,x0.w,x1.x,x1.y,x1.z,x1.w};
            float br[8] = {y0.x,y0.y,y0.z,y0.w,y1.x,y1.y,y1.z,y1.w};
            #pragma unroll
            for (int i = 0; i < 8; i++)
                #pragma unroll
                for (int j = 0; j < 8; j++)
                    sc[i][j] = fmaf(ar[i], br[j], sc[i][j]);
        }
        __syncthreads();
    }
    #pragma unroll
    for (int j = 0; j < 8; j++)
        #pragma unroll
        for (int i = 0; i < 8; i++)
            SC[(size_t)(n0 + j) * 132 + (t0 + i)] = (n0 + j <= t0 + i) ? sc[i][j] : 0.0f;
    __syncthreads();

    float acc[8][8] = {};
    float dacc[8] = {};
    const float* Sp = S + ((size_t)c * BHN + bh) * (K2 * D_);
    const float* zp = Z + ((size_t)c * BHN + bh) * K2;
    for (int kt = 0; kt < 16; kt++) {
        const int rbase = kt << 4;
        #pragma unroll
        for (int it = 0; it < 2; it++) {
            int idx = tid + (it << 8);
            int r  = idx >> 5;
            int c4 = (idx & 31) << 2;
            int rr = rbase + r;
            float4 vv;
            if (rr < 128)
                vv = *(const float4*)(V + ((size_t)(c * CH + rr) * B_ + b) * E_ + h * D_ + c4);
            else
                vv = *(const float4*)(Sp + (size_t)(rr - 128) * D_ + c4);
            *(float4*)&TB[r * 132 + c4] = vv;
        }
        if (tid < 16) {
            int rr = rbase + tid;
            TB[tid * 132 + 128] = (rr < 128) ? 1.0f : zp[rr - 128];
        }
        if (rbase >= 128) {
            #pragma unroll
            for (int it = 0; it < 2; it++) {
                int idx = tid + (it << 8);
                int r  = idx >> 2;
                int c4 = (idx & 3) << 2;
                size_t grow = ((size_t)(c * CH + r) * B_ + b) * E_ + h * K2
                            + (rbase - 128) + c4;
                float4 vq = *(const float4*)(PQ + grow);
                TA[(c4+0)*132 + r] = vq.x; TA[(c4+1)*132 + r] = vq.y;
                TA[(c4+2)*132 + r] = vq.z; TA[(c4+3)*132 + r] = vq.w;
            }
        }
        __syncthreads();
        const float* Aop = (rbase < 128) ? (SC + (size_t)rbase * 132) : TA;
        #pragma unroll
        for (int ss = 0; ss < 16; ss++) {
            const float* arow = Aop + (size_t)ss * 132;
            float4 x0 = *(const float4*)(arow + t0);
            float4 x1 = *(const float4*)(arow + t0 + 4);
            float ar[8] = {x0.x,x0.y,x0.z,x0.w,x1.x,x1.y,x1.z,x1.w};
            float4 y0 = *(const float4*)&TB[ss * 132 + n0];
            float4 y1 = *(const float4*)&TB[ss * 132 + n0 + 4];
            float br[8] = {y0.x,y0.y,y0.z,y0.w,y1.x,y1.y,y1.z,y1.w};
            float bv = TB[ss * 132 + 128];
            #pragma unroll
            for (int i = 0; i < 8; i++) {
                dacc[i] = fmaf(ar[i], bv, dacc[i]);
                #pragma unroll
                for (int j = 0; j < 8; j++)
                    acc[i][j] = fmaf(ar[i], br[j], acc[i][j]);
            }
        }
        __syncthreads();
    }

    #pragma unroll
    for (int i = 0; i < 8; i++) {
        float inv = 1.0f / fmaxf(dacc[i], EPSV);
        size_t m = (size_t)(c * CH + t0 + i) * B_ + b;
        __nv_bfloat16* o = A3 + m * K3 + h * D_ + n0;
        __nv_bfloat16 hh[8], ll[8];
        #pragma unroll
        for (int j = 0; j < 8; j++) {
            float ov = acc[i][j] * inv;
            hh[j] = __float2bfloat16(ov);
            ll[j] = __float2bfloat16(ov - __bfloat162float(hh[j]));
        }
        #pragma unroll
        for (int j = 0; j < 4; j++) {
            __nv_bfloat162 hp = __halves2bfloat162(hh[2*j], hh[2*j+1]);
            __nv_bfloat162 lp = __halves2bfloat162(ll[2*j], ll[2*j+1]);
            ((__nv_bfloat162*)(o))[j]        = hp;
            ((__nv_bfloat162*)(o + 1024))[j] = lp;
            ((__nv_bfloat162*)(o + 2048))[j] = hp;
        }
    }
}

// ---------------- launcher -----------------------------------------------------
extern "C" void kernel_launch(void* const* d_in, const int* in_sizes, int n_in,
                              void* d_out, int out_size)
{
    const float* x   = (const float*)d_in[0];
    const float* rm  = (const float*)d_in[1];
    const float* Wq  = (const float*)d_in[2];
    const float* bq  = (const float*)d_in[3];
    const float* Wk  = (const float*)d_in[4];
    const float* bk  = (const float*)d_in[5];
    const float* Wv  = (const float*)d_in[6];
    const float* bv  = (const float*)d_in[7];
    const float* Wo  = (const float*)d_in[8];
    const float* bo  = (const float*)d_in[9];
    const float* sig = (const float*)d_in[10];
    float* out = (float*)d_out;

    float *v, *pq, *pk, *S, *z, *M, *pb;
    __half *a3, *wv3, *wo3;
    cudaGetSymbolAddress((void**)&v,    g_v);
    cudaGetSymbolAddress((void**)&pq,   g_pq);
    cudaGetSymbolAddress((void**)&pk,   g_pk);
    cudaGetSymbolAddress((void**)&S,    g_S);
    cudaGetSymbolAddress((void**)&z,    g_z);
    cudaGetSymbolAddress((void**)&M,    g_M);
    cudaGetSymbolAddress((void**)&pb,   g_pb);
    cudaGetSymbolAddress((void**)&a3,   g_a3);
    cudaGetSymbolAddress((void**)&wv3,  g_wv3);
    cudaGetSymbolAddress((void**)&wo3,  g_wo3);

    cudaFuncSetAttribute(rfa_out_kernel,
                         cudaFuncAttributeMaxDynamicSharedMemorySize, RFA_SMEM);
    cudaFuncSetAttribute(rfa_out_kernel,
                         cudaFuncAttributePreferredSharedMemoryCarveout, 100);
    cudaFuncSetAttribute((const void*)gemm_hmma<true, 3072>,
                         cudaFuncAttributeMaxDynamicSharedMemorySize, GEMM_SMEM);
    cudaFuncSetAttribute((const void*)gemm_hmma<true, 3072>,
                         cudaFuncAttributePreferredSharedMemoryCarveout, 100);
    cudaFuncSetAttribute((const void*)gemm_hmma<false, 3072>,
                         cudaFuncAttributeMaxDynamicSharedMemorySize, GEMM_SMEM);
    cudaFuncSetAttribute((const void*)gemm_hmma<false, 3072>,
                         cudaFuncAttributePreferredSharedMemoryCarveout, 100);

    const float invW = 1.0f / WSCALE;
    dim3 ghmma(E_ / 128, MR / 128);        // full-M HMMA (v projection)
    dim3 gquartO(E_ / 128, MR / 512);      // quarter-M HMMA (O projection)
    dim3 gphi_pk(4, MR / 128);             // PK half (all M)
    dim3 gphi_pqh(4, MR / 256);            // PQ half-M
    dim3 grfa_q(NC / 4, BHN);              // quarter-chunk rfa

    cudaStream_t s1;
    cudaStreamCreateWithFlags(&s1, cudaStreamNonBlocking);
    cudaEvent_t eK, ePre, eQ1, eR[4], eO4;
    cudaEventCreateWithFlags(&eK,   cudaEventDisableTiming);
    cudaEventCreateWithFlags(&ePre, cudaEventDisableTiming);
    cudaEventCreateWithFlags(&eQ1,  cudaEventDisableTiming);
    for (int i = 0; i < 4; i++) cudaEventCreateWithFlags(&eR[i], cudaEventDisableTiming);
    cudaEventCreateWithFlags(&eO4,  cudaEventDisableTiming);

    // --- s1: v path (tensor) hides under the fp32 PK GEMM on s0 ---
    split3h_kernel<<<MR, 256, 0, s1>>>(x, a3, 1, 1.0f);
    split3h_kernel<<<1024, 256, 0, s1>>>(Wv, wv3, 0, WSCALE);
    gemm_hmma<true, 3072><<<ghmma, 256, GEMM_SMEM, s1>>>(a3, wv3, bv, v, invW, 0);
    split3b_kernel<<<1024, 256, 0, s1>>>(Wo, (__nv_bfloat16*)wo3, 0);

    // --- s0 FFMA chain: prep -> PK(all M) -> PQ M-half1 -> PQ M-half2 ---
    prep_M<<<1024, 128>>>(rm, sig, Wq, Wk, bq, bk, M, pb);
    sgemm_phi<<<gphi_pk, 256>>>(x, M, pb, pq, pk, 1024, 4, 0);      // PK cols, all M
    cudaEventRecord(eK, 0);
    sgemm_phi<<<gphi_pqh, 256>>>(x, M, pb, pq, pk, 1024, 0, 0);     // PQ, M rows 0..16383
    cudaEventRecord(eQ1, 0);
    sgemm_phi<<<gphi_pqh, 256>>>(x, M, pb, pq, pk, 1024, 0, 128);   // PQ, M rows 16384..

    // --- s1: chunk path (needs pk + v) ---
    cudaStreamWaitEvent(s1, eK, 0);
    dim3 gcs(NC, BHN);
    chunk_state_kernel<<<gcs, 256, 0, s1>>>(pk, v, S, z);
    prefix_S_kernel<<<dim3(BHN, 64), 256, 0, s1>>>(S);
    prefix_z_kernel<<<BHN, 128, 0, s1>>>(z);
    cudaEventRecord(ePre, s1);

    // --- s0 FFMA chain continues: rfa quarters (each unlocks an O quarter on s1) ---
    cudaStreamWaitEvent(0, ePre, 0);
    for (int q = 0; q < 4; q++) {
        rfa_out_kernel<<<grfa_q, 256, RFA_SMEM>>>(pq, pk, v, S, z,
                                                  (__nv_bfloat16*)a3, q * (NC / 4));
        cudaEventRecord(eR[q], 0);
    }

    // --- s1: O quarters (tensor) pipelined behind rfa quarters ---
    for (int q = 0; q < 4; q++) {
        cudaStreamWaitEvent(s1, eR[q], 0);
        gemm_hmma<false, 3072><<<gquartO, 256, GEMM_SMEM, s1>>>(
            a3, wo3, bo, out, 1.0f, q * (MR / 512));
    }
    cudaEventRecord(eO4, s1);
    cudaStreamWaitEvent(0, eO4, 0);
}

// round 14
// speedup vs baseline: 1.2434x; 1.0091x over previous
#include <cuda_runtime.h>
#include <cuda_bf16.h>
#include <cuda_fp16.h>
#include <cstdint>

#define T_    4096
#define B_    8
#define E_    1024
#define H_    8
#define D_    128
#define KP    64
#define K2    128
#define CH    128
#define NC    32
#define MR    32768
#define BHN   64
#define EPSV  1e-6f

#define K3        3072
#define NSTAGE    2
#define STAGE_B   32768
#define GEMM_SMEM (NSTAGE * STAGE_B)   // 64KB
#define WSCALE    1024.0f

// ---------------- scratch ---------------------------------------------------
__device__ float g_v[33554432];
__device__ float g_pq[33554432];
__device__ float g_pk[33554432];
__device__ float g_S[33554432];
__device__ float g_z[262144];
__device__ float g_M[1048576];
__device__ float g_pb[1024];
__device__ __half g_a3[100663296];   // [MR][3072] x fp16x3, later attn bf16x3 (reuse)
__device__ __half g_wv3[3145728];    // Wv fp16x3
__device__ __half g_wo3[3145728];    // Wo bf16x3 (bits in half storage)

// ---------------- PTX helpers -----------------------------------------------
__device__ __forceinline__ uint32_t smem_u32(const void* p) {
    uint32_t a;
    asm("{ .reg .u64 t; cvta.to.shared.u64 t, %1; cvt.u32.u64 %0, t; }"
        : "=r"(a) : "l"(p));
    return a;
}
__device__ __forceinline__ void cp16(uint32_t dst, const void* src) {
    asm volatile("cp.async.cg.shared.global [%0], [%1], 16;" :: "r"(dst), "l"(src));
}
__device__ __forceinline__ void ldm_x4(uint32_t& r0, uint32_t& r1,
                                       uint32_t& r2, uint32_t& r3, uint32_t addr) {
    asm volatile("ldmatrix.sync.aligned.m8n8.x4.shared.b16 {%0,%1,%2,%3}, [%4];"
                 : "=r"(r0), "=r"(r1), "=r"(r2), "=r"(r3) : "r"(addr));
}
__device__ __forceinline__ void mma_f16(float* c, const uint32_t* a,
                                        uint32_t b0, uint32_t b1) {
    asm volatile(
        "mma.sync.aligned.m16n8k16.row.col.f32.f16.f16.f32 "
        "{%0,%1,%2,%3}, {%4,%5,%6,%7}, {%8,%9}, {%0,%1,%2,%3};"
        : "+f"(c[0]), "+f"(c[1]), "+f"(c[2]), "+f"(c[3])
        : "r"(a[0]), "r"(a[1]), "r"(a[2]), "r"(a[3]), "r"(b0), "r"(b1));
}
__device__ __forceinline__ void mma_bf16(float* c, const uint32_t* a,
                                         uint32_t b0, uint32_t b1) {
    asm volatile(
        "mma.sync.aligned.m16n8k16.row.col.f32.bf16.bf16.f32 "
        "{%0,%1,%2,%3}, {%4,%5,%6,%7}, {%8,%9}, {%0,%1,%2,%3};"
        : "+f"(c[0]), "+f"(c[1]), "+f"(c[2]), "+f"(c[3])
        : "r"(a[0]), "r"(a[1]), "r"(a[2]), "r"(a[3]), "r"(b0), "r"(b1));
}

// ---------------- prep: fused q/k projection matrix + bias -------------------
__global__ __launch_bounds__(128) void prep_M(
    const float* __restrict__ rm, const float* __restrict__ sig,
    const float* __restrict__ Wq, const float* __restrict__ Wk,
    const float* __restrict__ bq, const float* __restrict__ bk,
    float* __restrict__ M, float* __restrict__ pb)
{
    const int row = blockIdx.x;
    const int isK = row >> 9;
    const int h   = (row >> 6) & 7;
    const int kk  = row & 63;
    const float* W  = isK ? Wk : Wq;
    const float* bb = isK ? bk : bq;
    __shared__ float r[128];
    const int tid = threadIdx.x;
    const float c = 0.29730177875068026f;
    r[tid] = c * sig[h * 128 + tid] * rm[((size_t)(h * 64 + kk)) * 128 + tid];
    __syncthreads();
    for (int e = tid; e < 1024; e += 128) {
        float acc = 0.f;
        #pragma unroll 8
        for (int d = 0; d < 128; d++)
            acc = fmaf(r[d], W[(size_t)(h * 128 + d) * 1024 + e], acc);
        M[(size_t)row * 1024 + e] = acc;
    }
    if (tid == 0) {
        float acc = 0.f;
        for (int d = 0; d < 128; d++) acc = fmaf(r[d], bb[h * 128 + d], acc);
        pb[row] = acc;
    }
}

// ---------------- split fp32 -> fp16 x3 concat --------------------------------
__global__ __launch_bounds__(256) void split3h_kernel(
    const float* __restrict__ X, __half* __restrict__ O, int midIsLo, float scale)
{
    size_t idx = (size_t)blockIdx.x * 256 + threadIdx.x;
    size_t m = idx >> 8;
    int kq = (int)(idx & 255) << 2;
    float4 v = *(const float4*)(X + m * 1024 + kq);
    float f[4] = {v.x * scale, v.y * scale, v.z * scale, v.w * scale};
    __half h[4], l[4];
    #pragma unroll
    for (int i = 0; i < 4; i++) {
        h[i] = __float2half(f[i]);
        l[i] = __float2half(f[i] - __half2float(h[i]));
    }
    __half2 hp0 = __halves2half2(h[0], h[1]);
    __half2 hp1 = __halves2half2(h[2], h[3]);
    __half2 lp0 = __halves2half2(l[0], l[1]);
    __half2 lp1 = __halves2half2(l[2], l[3]);
    __half* o = O + m * K3 + kq;
    ((__half2*)o)[0] = hp0;
    ((__half2*)o)[1] = hp1;
    ((__half2*)(o + 1024))[0] = midIsLo ? lp0 : hp0;
    ((__half2*)(o + 1024))[1] = midIsLo ? lp1 : hp1;
    ((__half2*)(o + 2048))[0] = midIsLo ? hp0 : lp0;
    ((__half2*)(o + 2048))[1] = midIsLo ? hp1 : lp1;
}

// ---------------- split fp32 -> bf16 x3 concat --------------------------------
__global__ __launch_bounds__(256) void split3b_kernel(
    const float* __restrict__ X, __nv_bfloat16* __restrict__ O, int midIsLo)
{
    size_t idx = (size_t)blockIdx.x * 256 + threadIdx.x;
    size_t m = idx >> 8;
    int kq = (int)(idx & 255) << 2;
    float4 v = *(const float4*)(X + m * 1024 + kq);
    float f[4] = {v.x, v.y, v.z, v.w};
    __nv_bfloat16 h[4], l[4];
    #pragma unroll
    for (int i = 0; i < 4; i++) {
        h[i] = __float2bfloat16(f[i]);
        l[i] = __float2bfloat16(f[i] - __bfloat162float(h[i]));
    }
    __nv_bfloat162 hp0 = __halves2bfloat162(h[0], h[1]);
    __nv_bfloat162 hp1 = __halves2bfloat162(h[2], h[3]);
    __nv_bfloat162 lp0 = __halves2bfloat162(l[0], l[1]);
    __nv_bfloat162 lp1 = __halves2bfloat162(l[2], l[3]);
    __nv_bfloat16* o = O + m * K3 + kq;
    ((__nv_bfloat162*)o)[0] = hp0;
    ((__nv_bfloat162*)o)[1] = hp1;
    ((__nv_bfloat162*)(o + 1024))[0] = midIsLo ? lp0 : hp0;
    ((__nv_bfloat162*)(o + 1024))[1] = midIsLo ? lp1 : hp1;
    ((__nv_bfloat162*)(o + 2048))[0] = midIsLo ? hp0 : lp0;
    ((__nv_bfloat162*)(o + 2048))[1] = midIsLo ? hp1 : lp1;
}

// ---------------- HMMA GEMM: C = (A . W^T) * outScale + bias ------------------
// moff: row-block offset, nyb: number of row blocks handled via grid.y.
template<bool FP16, int KTOT>
__global__ __launch_bounds__(256) void gemm_hmma(
    const void* __restrict__ A3v, const void* __restrict__ W3v,
    const float* __restrict__ bias, float* __restrict__ C, float outScale, int moff)
{
    constexpr int NCHUNK = KTOT / 64;
    constexpr int ROWB   = KTOT * 2;
    extern __shared__ __align__(128) char smem[];
    const uint32_t sb = smem_u32(smem);
    const int tid  = threadIdx.x;
    const int lane = tid & 31;
    const int wid  = tid >> 5;
    const int m0 = (blockIdx.y + moff) << 7;
    const int n0 = blockIdx.x << 7;
    const int wm = (wid >> 1) << 5;
    const int wn = (wid & 1) << 6;

    const char* Abase = (const char*)A3v + (size_t)m0 * ROWB;
    const char* Bbase = (const char*)W3v + (size_t)n0 * ROWB;

    const int lrow = tid >> 1;
    const int lc0  = (tid & 1) << 2;
    auto load_stage = [&](int chunk, int st) {
        const size_t gcol = (size_t)(chunk << 7);
        const uint32_t sa = sb + st * STAGE_B;
        #pragma unroll
        for (int c = 0; c < 4; c++) {
            int ch = lc0 + c;
            uint32_t soff = (lrow << 7) + (((ch ^ (lrow & 7))) << 4);
            cp16(sa + soff,         Abase + (size_t)lrow * ROWB + gcol + (ch << 4));
            cp16(sa + 16384 + soff, Bbase + (size_t)lrow * ROWB + gcol + (ch << 4));
        }
    };

    #pragma unroll
    for (int s = 0; s < NSTAGE; s++) {
        load_stage(s, s);
        asm volatile("cp.async.commit_group;" ::: "memory");
    }

    const int amln = wm + (lane & 15);
    const int acb  = (lane >> 4) << 4;
    const int asw  = (amln & 7) << 4;
    const int bnln = wn + (lane & 7) + ((lane & 16) >> 1);
    const int bcb  = (lane & 8) << 1;
    const int bsw  = (lane & 7) << 4;

    float acc[2][8][4] = {};

    for (int i = 0; i < NCHUNK; i++) {
        asm volatile("cp.async.wait_group %0;" :: "n"(NSTAGE - 1) : "memory");
        __syncthreads();
        const int st = i % NSTAGE;
        const uint32_t sa = sb + st * STAGE_B;
        const uint32_t sbB = sa + 16384;
        #pragma unroll
        for (int ks = 0; ks < 4; ks++) {
            uint32_t a[2][4];
            #pragma unroll
            for (int mi = 0; mi < 2; mi++) {
                uint32_t addr = sa + ((amln + (mi << 4)) << 7)
                              + (((ks << 5) + acb) ^ asw);
                ldm_x4(a[mi][0], a[mi][1], a[mi][2], a[mi][3], addr);
            }
            #pragma unroll
            for (int njp = 0; njp < 4; njp++) {
                uint32_t q0, q1, q2, q3;
                uint32_t addr = sbB + ((bnln + (njp << 4)) << 7)
                              + (((ks << 5) + bcb) ^ bsw);
                ldm_x4(q0, q1, q2, q3, addr);
                if (FP16) {
                    mma_f16(acc[0][2*njp],     a[0], q0, q1);
                    mma_f16(acc[0][2*njp + 1], a[0], q2, q3);
                    mma_f16(acc[1][2*njp],     a[1], q0, q1);
                    mma_f16(acc[1][2*njp + 1], a[1], q2, q3);
                } else {
                    mma_bf16(acc[0][2*njp],     a[0], q0, q1);
                    mma_bf16(acc[0][2*njp + 1], a[0], q2, q3);
                    mma_bf16(acc[1][2*njp],     a[1], q0, q1);
                    mma_bf16(acc[1][2*njp + 1], a[1], q2, q3);
                }
            }
        }
        __syncthreads();
        if (i + NSTAGE < NCHUNK) load_stage(i + NSTAGE, st);
        asm volatile("cp.async.commit_group;" ::: "memory");
    }

    const int rbase = m0 + wm + (lane >> 2);
    const int cbase = n0 + wn + ((lane & 3) << 1);
    #pragma unroll
    for (int mi = 0; mi < 2; mi++) {
        #pragma unroll
        for (int nj = 0; nj < 8; nj++) {
            int col = cbase + (nj << 3);
            float b0 = bias[col], b1 = bias[col + 1];
            float* p0 = C + (size_t)(rbase + (mi << 4)) * 1024 + col;
            float* p1 = p0 + 8 * 1024;
            float2 v0 = {acc[mi][nj][0] * outScale + b0, acc[mi][nj][1] * outScale + b1};
            float2 v1 = {acc[mi][nj][2] * outScale + b0, acc[mi][nj][3] * outScale + b1};
            *(float2*)p0 = v0;
            *(float2*)p1 = v1;
        }
    }
}

// ---------------- fp32 SGEMM + fused phi (bnoff = N offset, moff = M offset) --
__global__ __launch_bounds__(256) void sgemm_phi(
    const float* __restrict__ A, const float* __restrict__ Bm,
    const float* __restrict__ bias,
    float* __restrict__ PQ, float* __restrict__ PK, int Kd, int bnoff, int moff)
{
    __shared__ float As[16][128];
    __shared__ float Bs[16][128];
    const int bm = (blockIdx.y + moff) * 128;
    const int bn = (blockIdx.x + bnoff) * 128;
    const int tid = threadIdx.x;
    const int t0 = (tid >> 4) << 3;
    const int n0 = (tid & 15) << 3;
    const int lr = tid >> 2;
    const int lc = (tid & 3) << 2;
    const float* Ap = A + (size_t)(bm + lr) * Kd + lc;
    const float* Bp = Bm + (size_t)(bn + lr) * Kd + lc;
    const size_t half = (size_t)64 * Kd;

    float4 a0 = *(const float4*)(Ap);
    float4 a1 = *(const float4*)(Ap + half);
    float4 b0 = *(const float4*)(Bp);
    float4 b1 = *(const float4*)(Bp + half);

    float acc[8][8] = {};
    for (int k0 = 0; k0 < Kd; k0 += 16) {
        As[lc+0][lr]    = a0.x; As[lc+1][lr]    = a0.y; As[lc+2][lr]    = a0.z; As[lc+3][lr]    = a0.w;
        As[lc+0][lr+64] = a1.x; As[lc+1][lr+64] = a1.y; As[lc+2][lr+64] = a1.z; As[lc+3][lr+64] = a1.w;
        Bs[lc+0][lr]    = b0.x; Bs[lc+1][lr]    = b0.y; Bs[lc+2][lr]    = b0.z; Bs[lc+3][lr]    = b0.w;
        Bs[lc+0][lr+64] = b1.x; Bs[lc+1][lr+64] = b1.y; Bs[lc+2][lr+64] = b1.z; Bs[lc+3][lr+64] = b1.w;
        __syncthreads();
        if (k0 + 16 < Kd) {
            a0 = *(const float4*)(Ap + k0 + 16);
            a1 = *(const float4*)(Ap + k0 + 16 + half);
            b0 = *(const float4*)(Bp + k0 + 16);
            b1 = *(const float4*)(Bp + k0 + 16 + half);
        }
        #pragma unroll
        for (int kk = 0; kk < 16; kk++) {
            float4 x0 = *(const float4*)&As[kk][t0];
            float4 x1 = *(const float4*)&As[kk][t0+4];
            float4 y0 = *(const float4*)&Bs[kk][n0];
            float4 y1 = *(const float4*)&Bs[kk][n0+4];
            float ar[8] = {x0.x,x0.y,x0.z,x0.w,x1.x,x1.y,x1.z,x1.w};
            float br[8] = {y0.x,y0.y,y0.z,y0.w,y1.x,y1.y,y1.z,y1.w};
            #pragma unroll
            for (int i = 0; i < 8; i++)
                #pragma unroll
                for (int j = 0; j < 8; j++)
                    acc[i][j] = fmaf(ar[i], br[j], acc[i][j]);
        }
        __syncthreads();
    }

    float bb[8];
    #pragma unroll
    for (int j = 0; j < 8; j++) bb[j] = bias[bn + n0 + j];
    const int colg = bn + n0;
    float* OUTB = (colg < 512) ? PQ : PK;
    const int cc  = colg & 511;
    const int hh  = cc >> 6;
    const int kk0 = cc & 63;
    #pragma unroll
    for (int i = 0; i < 8; i++) {
        size_t base = (size_t)(bm + t0 + i) * 1024 + (hh << 7) + kk0;
        float sv[8], cv[8];
        #pragma unroll
        for (int j = 0; j < 8; j++) {
            float s, c;
            sincosf(acc[i][j] + bb[j], &s, &c);
            sv[j] = s * 0.125f;
            cv[j] = c * 0.125f;
        }
        float4 o;
        o.x=sv[0]; o.y=sv[1]; o.z=sv[2]; o.w=sv[3]; *(float4*)&OUTB[base]      = o;
        o.x=sv[4]; o.y=sv[5]; o.z=sv[6]; o.w=sv[7]; *(float4*)&OUTB[base + 4]  = o;
        o.x=cv[0]; o.y=cv[1]; o.z=cv[2]; o.w=cv[3]; *(float4*)&OUTB[base + 64] = o;
        o.x=cv[4]; o.y=cv[5]; o.z=cv[6]; o.w=cv[7]; *(float4*)&OUTB[base + 68] = o;
    }
}

// ---------------- per-chunk state + fused z -------------------------------------
__global__ __launch_bounds__(256) void chunk_state_kernel(
    const float* __restrict__ PK, const float* __restrict__ V,
    float* __restrict__ S, float* __restrict__ Z)
{
    __shared__ float as[16][128];
    __shared__ float bs[16][128];
    const int c = blockIdx.x, bh = blockIdx.y;
    const int b = bh >> 3, h = bh & 7;
    const int tid = threadIdx.x;
    const int t0 = (tid >> 4) << 3;
    const int n0 = (tid & 15) << 3;
    float acc[8][8] = {};
    float zacc = 0.f;

    for (int s0 = 0; s0 < CH; s0 += 16) {
        #pragma unroll
        for (int it = 0; it < 2; it++) {
            int idx = tid + (it << 8);
            int r  = idx >> 5;
            int c4 = (idx & 31) << 2;
            size_t grow = ((size_t)(c * CH + s0 + r) * B_ + b) * E_ + h * D_;
            *(float4*)&as[r][c4] = *(const float4*)(PK + grow + c4);
            *(float4*)&bs[r][c4] = *(const float4*)(V  + grow + c4);
        }
        __syncthreads();
        if (tid < 128) {
            float za = 0.f;
            #pragma unroll
            for (int ss = 0; ss < 16; ss++) za += as[ss][tid];
            zacc += za;
        }
        #pragma unroll
        for (int ss = 0; ss < 16; ss++) {
            float4 x0 = *(const float4*)&as[ss][t0];
            float4 x1 = *(const float4*)&as[ss][t0+4];
            float4 y0 = *(const float4*)&bs[ss][n0];
            float4 y1 = *(const float4*)&bs[ss][n0+4];
            float ar[8] = {x0.x,x0.y,x0.z,x0.w,x1.x,x1.y,x1.z,x1.w};
            float br[8] = {y0.x,y0.y,y0.z,y0.w,y1.x,y1.y,y1.z,y1.w};
            #pragma unroll
            for (int i = 0; i < 8; i++)
                #pragma unroll
                for (int j = 0; j < 8; j++)
                    acc[i][j] = fmaf(ar[i], br[j], acc[i][j]);
        }
        __syncthreads();
    }
    float* Sp = S + ((size_t)c * BHN + bh) * (K2 * D_);
    #pragma unroll
    for (int i = 0; i < 8; i++) {
        float4 o;
        o.x = acc[i][0]; o.y = acc[i][1]; o.z = acc[i][2]; o.w = acc[i][3];
        *(float4*)(Sp + (size_t)(t0 + i) * D_ + n0) = o;
        o.x = acc[i][4]; o.y = acc[i][5]; o.z = acc[i][6]; o.w = acc[i][7];
        *(float4*)(Sp + (size_t)(t0 + i) * D_ + n0 + 4) = o;
    }
    if (tid < 128)
        Z[((size_t)c * BHN + bh) * K2 + tid] = zacc;
}

__global__ void prefix_S_kernel(float* __restrict__ S)
{
    const int bh = blockIdx.x;
    const int e  = blockIdx.y * 256 + threadIdx.x;
    float acc = 0.f;
    for (int c = 0; c < NC; c++) {
        size_t idx = ((size_t)c * BHN + bh) * (K2 * D_) + e;
        float t = S[idx]; S[idx] = acc; acc += t;
    }
}

__global__ void prefix_z_kernel(float* __restrict__ Z)
{
    const int bh = blockIdx.x;
    const int k  = threadIdx.x;
    float acc = 0.f;
    for (int c = 0; c < NC; c++) {
        size_t idx = ((size_t)c * BHN + bh) * K2 + k;
        float t = Z[idx]; Z[idx] = acc; acc += t;
    }
}

// ---------------- RFA output (c0 = chunk offset for partial launches) -----------
#define RFA_SMEM ((128*132 + 2*16*132) * 4)   // 84480 B
__global__ __launch_bounds__(256) void rfa_out_kernel(
    const float* __restrict__ PQ, const float* __restrict__ PK,
    const float* __restrict__ V,  const float* __restrict__ S,
    const float* __restrict__ Z,  __nv_bfloat16* __restrict__ A3, int c0)
{
    extern __shared__ float sm[];
    float* SC = sm;
    float* TA = sm + 128 * 132;
    float* TB = TA + 16 * 132;

    const int c = blockIdx.x + c0, bh = blockIdx.y;
    const int b = bh >> 3, h = bh & 7;
    const int tid = threadIdx.x;
    const int t0 = (tid >> 4) << 3;
    const int n0 = (tid & 15) << 3;

    float sc[8][8] = {};
    for (int kt = 0; kt < 8; kt++) {
        #pragma unroll
        for (int it = 0; it < 2; it++) {
            int idx = tid + (it << 8);
            int r  = idx >> 2;
            int c4 = (idx & 3) << 2;
            size_t grow = ((size_t)(c * CH + r) * B_ + b) * E_ + h * K2 + (kt << 4) + c4;
            float4 vq = *(const float4*)(PQ + grow);
            TA[(c4+0)*132 + r] = vq.x; TA[(c4+1)*132 + r] = vq.y;
            TA[(c4+2)*132 + r] = vq.z; TA[(c4+3)*132 + r] = vq.w;
            float4 vk = *(const float4*)(PK + grow);
            TB[(c4+0)*132 + r] = vk.x; TB[(c4+1)*132 + r] = vk.y;
            TB[(c4+2)*132 + r] = vk.z; TB[(c4+3)*132 + r] = vk.w;
        }
        __syncthreads();
        #pragma unroll
        for (int kk = 0; kk < 16; kk++) {
            float4 x0 = *(const float4*)&TA[kk*132 + t0];
            float4 x1 = *(const float4*)&TA[kk*132 + t0 + 4];
            float4 y0 = *(const float4*)&TB[kk*132 + n0];
            float4 y1 = *(const float4*)&TB[kk*132 + n0 + 4];
            float ar[8] = {x0.x,x0.y,x0.z,x0.w,x1.x,x1.y,x1.z,x1.w};
            float br[8] = {y0.x,y0.y,y0.z,y0.w,y1.x,y1.y,y1.z,y1.w};
            #pragma unroll
            for (int i = 0; i < 8; i++)
                #pragma unroll
                for (int j = 0; j < 8; j++)
                    sc[i][j] = fmaf(ar[i], br[j], sc[i][j]);
        }
        __syncthreads();
    }
    #pragma unroll
    for (int j = 0; j < 8; j++)
        #pragma unroll
        for (int i = 0; i < 8; i++)
            SC[(size_t)(n0 + j) * 132 + (t0 + i)] = (n0 + j <= t0 + i) ? sc[i][j] : 0.0f;
    __syncthreads();

    float acc[8][8] = {};
    float dacc[8] = {};
    const float* Sp = S + ((size_t)c * BHN + bh) * (K2 * D_);
    const float* zp = Z + ((size_t)c * BHN + bh) * K2;
    for (int kt = 0; kt < 16; kt++) {
        const int rbase = kt << 4;
        #pragma unroll
        for (int it = 0; it < 2; it++) {
            int idx = tid + (it << 8);
            int r  = idx >> 5;
            int c4 = (idx & 31) << 2;
            int rr = rbase + r;
            float4 vv;
            if (rr < 128)
                vv = *(const float4*)(V + ((size_t)(c * CH + rr) * B_ + b) * E_ + h * D_ + c4);
            else
                vv = *(const float4*)(Sp + (size_t)(rr - 128) * D_ + c4);
            *(float4*)&TB[r * 132 + c4] = vv;
        }
        if (tid < 16) {
            int rr = rbase + tid;
            TB[tid * 132 + 128] = (rr < 128) ? 1.0f : zp[rr - 128];
        }
        if (rbase >= 128) {
            #pragma unroll
            for (int it = 0; it < 2; it++) {
                int idx = tid + (it << 8);
                int r  = idx >> 2;
                int c4 = (idx & 3) << 2;
                size_t grow = ((size_t)(c * CH + r) * B_ + b) * E_ + h * K2
                            + (rbase - 128) + c4;
                float4 vq = *(const float4*)(PQ + grow);
                TA[(c4+0)*132 + r] = vq.x; TA[(c4+1)*132 + r] = vq.y;
                TA[(c4+2)*132 + r] = vq.z; TA[(c4+3)*132 + r] = vq.w;
            }
        }
        __syncthreads();
        // causal skip: score rows s>t are exact zeros; fmaf(0,b,acc)==acc, so
        // skipping is bit-exact. Guard is half-warp-uniform (t0 from tid>>4).
        if (rbase >= 128 || rbase <= t0 + 7) {
            const float* Aop = (rbase < 128) ? (SC + (size_t)rbase * 132) : TA;
            #pragma unroll
            for (int ss = 0; ss < 16; ss++) {
                const float* arow = Aop + (size_t)ss * 132;
                float4 x0 = *(const float4*)(arow + t0);
                float4 x1 = *(const float4*)(arow + t0 + 4);
                float ar[8] = {x0.x,x0.y,x0.z,x0.w,x1.x,x1.y,x1.z,x1.w};
                float4 y0 = *(const float4*)&TB[ss * 132 + n0];
                float4 y1 = *(const float4*)&TB[ss * 132 + n0 + 4];
                float br[8] = {y0.x,y0.y,y0.z,y0.w,y1.x,y1.y,y1.z,y1.w};
                float bv = TB[ss * 132 + 128];
                #pragma unroll
                for (int i = 0; i < 8; i++) {
                    dacc[i] = fmaf(ar[i], bv, dacc[i]);
                    #pragma unroll
                    for (int j = 0; j < 8; j++)
                        acc[i][j] = fmaf(ar[i], br[j], acc[i][j]);
                }
            }
        }
        __syncthreads();
    }

    #pragma unroll
    for (int i = 0; i < 8; i++) {
        float inv = 1.0f / fmaxf(dacc[i], EPSV);
        size_t m = (size_t)(c * CH + t0 + i) * B_ + b;
        __nv_bfloat16* o = A3 + m * K3 + h * D_ + n0;
        __nv_bfloat16 hh[8], ll[8];
        #pragma unroll
        for (int j = 0; j < 8; j++) {
            float ov = acc[i][j] * inv;
            hh[j] = __float2bfloat16(ov);
            ll[j] = __float2bfloat16(ov - __bfloat162float(hh[j]));
        }
        #pragma unroll
        for (int j = 0; j < 4; j++) {
            __nv_bfloat162 hp = __halves2bfloat162(hh[2*j], hh[2*j+1]);
            __nv_bfloat162 lp = __halves2bfloat162(ll[2*j], ll[2*j+1]);
            ((__nv_bfloat162*)(o))[j]        = hp;
            ((__nv_bfloat162*)(o + 1024))[j] = lp;
            ((__nv_bfloat162*)(o + 2048))[j] = hp;
        }
    }
}

// ---------------- launcher -----------------------------------------------------
extern "C" void kernel_launch(void* const* d_in, const int* in_sizes, int n_in,
                              void* d_out, int out_size)
{
    const float* x   = (const float*)d_in[0];
    const float* rm  = (const float*)d_in[1];
    const float* Wq  = (const float*)d_in[2];
    const float* bq  = (const float*)d_in[3];
    const float* Wk  = (const float*)d_in[4];
    const float* bk  = (const float*)d_in[5];
    const float* Wv  = (const float*)d_in[6];
    const float* bv  = (const float*)d_in[7];
    const float* Wo  = (const float*)d_in[8];
    const float* bo  = (const float*)d_in[9];
    const float* sig = (const float*)d_in[10];
    float* out = (float*)d_out;

    float *v, *pq, *pk, *S, *z, *M, *pb;
    __half *a3, *wv3, *wo3;
    cudaGetSymbolAddress((void**)&v,    g_v);
    cudaGetSymbolAddress((void**)&pq,   g_pq);
    cudaGetSymbolAddress((void**)&pk,   g_pk);
    cudaGetSymbolAddress((void**)&S,    g_S);
    cudaGetSymbolAddress((void**)&z,    g_z);
    cudaGetSymbolAddress((void**)&M,    g_M);
    cudaGetSymbolAddress((void**)&pb,   g_pb);
    cudaGetSymbolAddress((void**)&a3,   g_a3);
    cudaGetSymbolAddress((void**)&wv3,  g_wv3);
    cudaGetSymbolAddress((void**)&wo3,  g_wo3);

    cudaFuncSetAttribute(rfa_out_kernel,
                         cudaFuncAttributeMaxDynamicSharedMemorySize, RFA_SMEM);
    cudaFuncSetAttribute(rfa_out_kernel,
                         cudaFuncAttributePreferredSharedMemoryCarveout, 100);
    cudaFuncSetAttribute((const void*)gemm_hmma<true, 3072>,
                         cudaFuncAttributeMaxDynamicSharedMemorySize, GEMM_SMEM);
    cudaFuncSetAttribute((const void*)gemm_hmma<true, 3072>,
                         cudaFuncAttributePreferredSharedMemoryCarveout, 100);
    cudaFuncSetAttribute((const void*)gemm_hmma<false, 3072>,
                         cudaFuncAttributeMaxDynamicSharedMemorySize, GEMM_SMEM);
    cudaFuncSetAttribute((const void*)gemm_hmma<false, 3072>,
                         cudaFuncAttributePreferredSharedMemoryCarveout, 100);

    const float invW = 1.0f / WSCALE;
    dim3 ghmma(E_ / 128, MR / 128);        // full-M HMMA (v projection)
    dim3 gphi_pk(4, MR / 128);             // PK half (all M)
    dim3 gphi_pqh(4, MR / 256);            // PQ half-M

    // uneven rfa->O pipeline: chunks {10,10,8,4}; last piece smallest -> min tail
    const int cstart[4] = {0, 10, 20, 28};
    const int ccount[4] = {10, 10, 8, 4};

    cudaStream_t s1;
    cudaStreamCreateWithFlags(&s1, cudaStreamNonBlocking);
    cudaEvent_t eK, ePre, eR[4], eO4;
    cudaEventCreateWithFlags(&eK,   cudaEventDisableTiming);
    cudaEventCreateWithFlags(&ePre, cudaEventDisableTiming);
    for (int i = 0; i < 4; i++) cudaEventCreateWithFlags(&eR[i], cudaEventDisableTiming);
    cudaEventCreateWithFlags(&eO4,  cudaEventDisableTiming);

    // --- s1: v path (tensor) hides under the fp32 PK GEMM on s0 ---
    split3h_kernel<<<MR, 256, 0, s1>>>(x, a3, 1, 1.0f);
    split3h_kernel<<<1024, 256, 0, s1>>>(Wv, wv3, 0, WSCALE);
    gemm_hmma<true, 3072><<<ghmma, 256, GEMM_SMEM, s1>>>(a3, wv3, bv, v, invW, 0);
    split3b_kernel<<<1024, 256, 0, s1>>>(Wo, (__nv_bfloat16*)wo3, 0);

    // --- s0 FFMA chain: prep -> PK(all M) -> PQ M-half1 -> PQ M-half2 ---
    prep_M<<<1024, 128>>>(rm, sig, Wq, Wk, bq, bk, M, pb);
    sgemm_phi<<<gphi_pk, 256>>>(x, M, pb, pq, pk, 1024, 4, 0);
    cudaEventRecord(eK, 0);
    sgemm_phi<<<gphi_pqh, 256>>>(x, M, pb, pq, pk, 1024, 0, 0);
    sgemm_phi<<<gphi_pqh, 256>>>(x, M, pb, pq, pk, 1024, 0, 128);

    // --- s1: chunk path (needs pk + v) ---
    cudaStreamWaitEvent(s1, eK, 0);
    dim3 gcs(NC, BHN);
    chunk_state_kernel<<<gcs, 256, 0, s1>>>(pk, v, S, z);
    prefix_S_kernel<<<dim3(BHN, 64), 256, 0, s1>>>(S);
    prefix_z_kernel<<<BHN, 128, 0, s1>>>(z);
    cudaEventRecord(ePre, s1);

    // --- s0: rfa pieces (FFMA) unlock O pieces (tensor) on s1 ---
    cudaStreamWaitEvent(0, ePre, 0);
    for (int q = 0; q < 4; q++) {
        dim3 grfa(ccount[q], BHN);
        rfa_out_kernel<<<grfa, 256, RFA_SMEM>>>(pq, pk, v, S, z,
                                                (__nv_bfloat16*)a3, cstart[q]);
        cudaEventRecord(eR[q], 0);
    }
    for (int q = 0; q < 4; q++) {
        cudaStreamWaitEvent(s1, eR[q], 0);
        dim3 gO(E_ / 128, ccount[q] * 8);          // 8 row-blocks per chunk
        gemm_hmma<false, 3072><<<gO, 256, GEMM_SMEM, s1>>>(
            a3, wo3, bo, out, 1.0f, cstart[q] * 8);
    }
    cudaEventRecord(eO4, s1);
    cudaStreamWaitEvent(0, eO4, 0);
}

// round 15
// speedup vs baseline: 1.2545x; 1.0089x over previous
#include <cuda_runtime.h>
#include <cuda_bf16.h>
#include <cuda_fp16.h>
#include <cstdint>

#define T_    4096
#define B_    8
#define E_    1024
#define H_    8
#define D_    128
#define KP    64
#define K2    128
#define CH    128
#define NC    32
#define MR    32768
#define BHN   64
#define EPSV  1e-6f

#define K3        3072
#define NSTAGE    2
#define STAGE_B   32768
#define GEMM_SMEM (NSTAGE * STAGE_B)   // 64KB
#define WSCALE    1024.0f

// ---------------- scratch ---------------------------------------------------
__device__ float g_v[33554432];
__device__ float g_pq[33554432];
__device__ float g_pk[33554432];
__device__ float g_S[33554432];
__device__ float g_z[262144];
__device__ float g_M[1048576];
__device__ float g_pb[1024];
__device__ __half g_a3[100663296];   // [MR][3072] x fp16x3, later attn bf16x3 (reuse)
__device__ __half g_wv3[3145728];    // Wv fp16x3
__device__ __half g_wo3[3145728];    // Wo bf16x3 (bits in half storage)

// ---------------- PTX helpers -----------------------------------------------
__device__ __forceinline__ uint32_t smem_u32(const void* p) {
    uint32_t a;
    asm("{ .reg .u64 t; cvta.to.shared.u64 t, %1; cvt.u32.u64 %0, t; }"
        : "=r"(a) : "l"(p));
    return a;
}
__device__ __forceinline__ void cp16(uint32_t dst, const void* src) {
    asm volatile("cp.async.cg.shared.global [%0], [%1], 16;" :: "r"(dst), "l"(src));
}
__device__ __forceinline__ void ldm_x4(uint32_t& r0, uint32_t& r1,
                                       uint32_t& r2, uint32_t& r3, uint32_t addr) {
    asm volatile("ldmatrix.sync.aligned.m8n8.x4.shared.b16 {%0,%1,%2,%3}, [%4];"
                 : "=r"(r0), "=r"(r1), "=r"(r2), "=r"(r3) : "r"(addr));
}
__device__ __forceinline__ void mma_f16(float* c, const uint32_t* a,
                                        uint32_t b0, uint32_t b1) {
    asm volatile(
        "mma.sync.aligned.m16n8k16.row.col.f32.f16.f16.f32 "
        "{%0,%1,%2,%3}, {%4,%5,%6,%7}, {%8,%9}, {%0,%1,%2,%3};"
        : "+f"(c[0]), "+f"(c[1]), "+f"(c[2]), "+f"(c[3])
        : "r"(a[0]), "r"(a[1]), "r"(a[2]), "r"(a[3]), "r"(b0), "r"(b1));
}
__device__ __forceinline__ void mma_bf16(float* c, const uint32_t* a,
                                         uint32_t b0, uint32_t b1) {
    asm volatile(
        "mma.sync.aligned.m16n8k16.row.col.f32.bf16.bf16.f32 "
        "{%0,%1,%2,%3}, {%4,%5,%6,%7}, {%8,%9}, {%0,%1,%2,%3};"
        : "+f"(c[0]), "+f"(c[1]), "+f"(c[2]), "+f"(c[3])
        : "r"(a[0]), "r"(a[1]), "r"(a[2]), "r"(a[3]), "r"(b0), "r"(b1));
}

// ---------------- prep: fused q/k projection matrix + bias -------------------
__global__ __launch_bounds__(128) void prep_M(
    const float* __restrict__ rm, const float* __restrict__ sig,
    const float* __restrict__ Wq, const float* __restrict__ Wk,
    const float* __restrict__ bq, const float* __restrict__ bk,
    float* __restrict__ M, float* __restrict__ pb)
{
    const int row = blockIdx.x;
    const int isK = row >> 9;
    const int h   = (row >> 6) & 7;
    const int kk  = row & 63;
    const float* W  = isK ? Wk : Wq;
    const float* bb = isK ? bk : bq;
    __shared__ float r[128];
    const int tid = threadIdx.x;
    const float c = 0.29730177875068026f;
    r[tid] = c * sig[h * 128 + tid] * rm[((size_t)(h * 64 + kk)) * 128 + tid];
    __syncthreads();
    for (int e = tid; e < 1024; e += 128) {
        float acc = 0.f;
        #pragma unroll 8
        for (int d = 0; d < 128; d++)
            acc = fmaf(r[d], W[(size_t)(h * 128 + d) * 1024 + e], acc);
        M[(size_t)row * 1024 + e] = acc;
    }
    if (tid == 0) {
        float acc = 0.f;
        for (int d = 0; d < 128; d++) acc = fmaf(r[d], bb[h * 128 + d], acc);
        pb[row] = acc;
    }
}

// ---------------- split fp32 -> fp16 x3 concat --------------------------------
__global__ __launch_bounds__(256) void split3h_kernel(
    const float* __restrict__ X, __half* __restrict__ O, int midIsLo, float scale)
{
    size_t idx = (size_t)blockIdx.x * 256 + threadIdx.x;
    size_t m = idx >> 8;
    int kq = (int)(idx & 255) << 2;
    float4 v = *(const float4*)(X + m * 1024 + kq);
    float f[4] = {v.x * scale, v.y * scale, v.z * scale, v.w * scale};
    __half h[4], l[4];
    #pragma unroll
    for (int i = 0; i < 4; i++) {
        h[i] = __float2half(f[i]);
        l[i] = __float2half(f[i] - __half2float(h[i]));
    }
    __half2 hp0 = __halves2half2(h[0], h[1]);
    __half2 hp1 = __halves2half2(h[2], h[3]);
    __half2 lp0 = __halves2half2(l[0], l[1]);
    __half2 lp1 = __halves2half2(l[2], l[3]);
    __half* o = O + m * K3 + kq;
    ((__half2*)o)[0] = hp0;
    ((__half2*)o)[1] = hp1;
    ((__half2*)(o + 1024))[0] = midIsLo ? lp0 : hp0;
    ((__half2*)(o + 1024))[1] = midIsLo ? lp1 : hp1;
    ((__half2*)(o + 2048))[0] = midIsLo ? hp0 : lp0;
    ((__half2*)(o + 2048))[1] = midIsLo ? hp1 : lp1;
}

// ---------------- split fp32 -> bf16 x3 concat --------------------------------
__global__ __launch_bounds__(256) void split3b_kernel(
    const float* __restrict__ X, __nv_bfloat16* __restrict__ O, int midIsLo)
{
    size_t idx = (size_t)blockIdx.x * 256 + threadIdx.x;
    size_t m = idx >> 8;
    int kq = (int)(idx & 255) << 2;
    float4 v = *(const float4*)(X + m * 1024 + kq);
    float f[4] = {v.x, v.y, v.z, v.w};
    __nv_bfloat16 h[4], l[4];
    #pragma unroll
    for (int i = 0; i < 4; i++) {
        h[i] = __float2bfloat16(f[i]);
        l[i] = __float2bfloat16(f[i] - __bfloat162float(h[i]));
    }
    __nv_bfloat162 hp0 = __halves2bfloat162(h[0], h[1]);
    __nv_bfloat162 hp1 = __halves2bfloat162(h[2], h[3]);
    __nv_bfloat162 lp0 = __halves2bfloat162(l[0], l[1]);
    __nv_bfloat162 lp1 = __halves2bfloat162(l[2], l[3]);
    __nv_bfloat16* o = O + m * K3 + kq;
    ((__nv_bfloat162*)o)[0] = hp0;
    ((__nv_bfloat162*)o)[1] = hp1;
    ((__nv_bfloat162*)(o + 1024))[0] = midIsLo ? lp0 : hp0;
    ((__nv_bfloat162*)(o + 1024))[1] = midIsLo ? lp1 : hp1;
    ((__nv_bfloat162*)(o + 2048))[0] = midIsLo ? hp0 : lp0;
    ((__nv_bfloat162*)(o + 2048))[1] = midIsLo ? hp1 : lp1;
}

// ---------------- HMMA GEMM: C = (A . W^T) * outScale + bias ------------------
template<bool FP16, int KTOT>
__global__ __launch_bounds__(256) void gemm_hmma(
    const void* __restrict__ A3v, const void* __restrict__ W3v,
    const float* __restrict__ bias, float* __restrict__ C, float outScale, int moff)
{
    constexpr int NCHUNK = KTOT / 64;
    constexpr int ROWB   = KTOT * 2;
    extern __shared__ __align__(128) char smem[];
    const uint32_t sb = smem_u32(smem);
    const int tid  = threadIdx.x;
    const int lane = tid & 31;
    const int wid  = tid >> 5;
    const int m0 = (blockIdx.y + moff) << 7;
    const int n0 = blockIdx.x << 7;
    const int wm = (wid >> 1) << 5;
    const int wn = (wid & 1) << 6;

    const char* Abase = (const char*)A3v + (size_t)m0 * ROWB;
    const char* Bbase = (const char*)W3v + (size_t)n0 * ROWB;

    const int lrow = tid >> 1;
    const int lc0  = (tid & 1) << 2;
    auto load_stage = [&](int chunk, int st) {
        const size_t gcol = (size_t)(chunk << 7);
        const uint32_t sa = sb + st * STAGE_B;
        #pragma unroll
        for (int c = 0; c < 4; c++) {
            int ch = lc0 + c;
            uint32_t soff = (lrow << 7) + (((ch ^ (lrow & 7))) << 4);
            cp16(sa + soff,         Abase + (size_t)lrow * ROWB + gcol + (ch << 4));
            cp16(sa + 16384 + soff, Bbase + (size_t)lrow * ROWB + gcol + (ch << 4));
        }
    };

    #pragma unroll
    for (int s = 0; s < NSTAGE; s++) {
        load_stage(s, s);
        asm volatile("cp.async.commit_group;" ::: "memory");
    }

    const int amln = wm + (lane & 15);
    const int acb  = (lane >> 4) << 4;
    const int asw  = (amln & 7) << 4;
    const int bnln = wn + (lane & 7) + ((lane & 16) >> 1);
    const int bcb  = (lane & 8) << 1;
    const int bsw  = (lane & 7) << 4;

    float acc[2][8][4] = {};

    for (int i = 0; i < NCHUNK; i++) {
        asm volatile("cp.async.wait_group %0;" :: "n"(NSTAGE - 1) : "memory");
        __syncthreads();
        const int st = i % NSTAGE;
        const uint32_t sa = sb + st * STAGE_B;
        const uint32_t sbB = sa + 16384;
        #pragma unroll
        for (int ks = 0; ks < 4; ks++) {
            uint32_t a[2][4];
            #pragma unroll
            for (int mi = 0; mi < 2; mi++) {
                uint32_t addr = sa + ((amln + (mi << 4)) << 7)
                              + (((ks << 5) + acb) ^ asw);
                ldm_x4(a[mi][0], a[mi][1], a[mi][2], a[mi][3], addr);
            }
            #pragma unroll
            for (int njp = 0; njp < 4; njp++) {
                uint32_t q0, q1, q2, q3;
                uint32_t addr = sbB + ((bnln + (njp << 4)) << 7)
                              + (((ks << 5) + bcb) ^ bsw);
                ldm_x4(q0, q1, q2, q3, addr);
                if (FP16) {
                    mma_f16(acc[0][2*njp],     a[0], q0, q1);
                    mma_f16(acc[0][2*njp + 1], a[0], q2, q3);
                    mma_f16(acc[1][2*njp],     a[1], q0, q1);
                    mma_f16(acc[1][2*njp + 1], a[1], q2, q3);
                } else {
                    mma_bf16(acc[0][2*njp],     a[0], q0, q1);
                    mma_bf16(acc[0][2*njp + 1], a[0], q2, q3);
                    mma_bf16(acc[1][2*njp],     a[1], q0, q1);
                    mma_bf16(acc[1][2*njp + 1], a[1], q2, q3);
                }
            }
        }
        __syncthreads();
        if (i + NSTAGE < NCHUNK) load_stage(i + NSTAGE, st);
        asm volatile("cp.async.commit_group;" ::: "memory");
    }

    const int rbase = m0 + wm + (lane >> 2);
    const int cbase = n0 + wn + ((lane & 3) << 1);
    #pragma unroll
    for (int mi = 0; mi < 2; mi++) {
        #pragma unroll
        for (int nj = 0; nj < 8; nj++) {
            int col = cbase + (nj << 3);
            float b0 = bias[col], b1 = bias[col + 1];
            float* p0 = C + (size_t)(rbase + (mi << 4)) * 1024 + col;
            float* p1 = p0 + 8 * 1024;
            float2 v0 = {acc[mi][nj][0] * outScale + b0, acc[mi][nj][1] * outScale + b1};
            float2 v1 = {acc[mi][nj][2] * outScale + b0, acc[mi][nj][3] * outScale + b1};
            *(float2*)p0 = v0;
            *(float2*)p1 = v1;
        }
    }
}

// ---------------- fp32 SGEMM + fused phi (bnoff = N offset, moff = M offset) --
__global__ __launch_bounds__(256) void sgemm_phi(
    const float* __restrict__ A, const float* __restrict__ Bm,
    const float* __restrict__ bias,
    float* __restrict__ PQ, float* __restrict__ PK, int Kd, int bnoff, int moff)
{
    __shared__ float As[16][128];
    __shared__ float Bs[16][128];
    const int bm = (blockIdx.y + moff) * 128;
    const int bn = (blockIdx.x + bnoff) * 128;
    const int tid = threadIdx.x;
    const int t0 = (tid >> 4) << 3;
    const int n0 = (tid & 15) << 3;
    const int lr = tid >> 2;
    const int lc = (tid & 3) << 2;
    const float* Ap = A + (size_t)(bm + lr) * Kd + lc;
    const float* Bp = Bm + (size_t)(bn + lr) * Kd + lc;
    const size_t half = (size_t)64 * Kd;

    float4 a0 = *(const float4*)(Ap);
    float4 a1 = *(const float4*)(Ap + half);
    float4 b0 = *(const float4*)(Bp);
    float4 b1 = *(const float4*)(Bp + half);

    float acc[8][8] = {};
    for (int k0 = 0; k0 < Kd; k0 += 16) {
        As[lc+0][lr]    = a0.x; As[lc+1][lr]    = a0.y; As[lc+2][lr]    = a0.z; As[lc+3][lr]    = a0.w;
        As[lc+0][lr+64] = a1.x; As[lc+1][lr+64] = a1.y; As[lc+2][lr+64] = a1.z; As[lc+3][lr+64] = a1.w;
        Bs[lc+0][lr]    = b0.x; Bs[lc+1][lr]    = b0.y; Bs[lc+2][lr]    = b0.z; Bs[lc+3][lr]    = b0.w;
        Bs[lc+0][lr+64] = b1.x; Bs[lc+1][lr+64] = b1.y; Bs[lc+2][lr+64] = b1.z; Bs[lc+3][lr+64] = b1.w;
        __syncthreads();
        if (k0 + 16 < Kd) {
            a0 = *(const float4*)(Ap + k0 + 16);
            a1 = *(const float4*)(Ap + k0 + 16 + half);
            b0 = *(const float4*)(Bp + k0 + 16);
            b1 = *(const float4*)(Bp + k0 + 16 + half);
        }
        #pragma unroll
        for (int kk = 0; kk < 16; kk++) {
            float4 x0 = *(const float4*)&As[kk][t0];
            float4 x1 = *(const float4*)&As[kk][t0+4];
            float4 y0 = *(const float4*)&Bs[kk][n0];
            float4 y1 = *(const float4*)&Bs[kk][n0+4];
            float ar[8] = {x0.x,x0.y,x0.z,x0.w,x1.x,x1.y,x1.z,x1.w};
            float br[8] = {y0.x,y0.y,y0.z,y0.w,y1.x,y1.y,y1.z,y1.w};
            #pragma unroll
            for (int i = 0; i < 8; i++)
                #pragma unroll
                for (int j = 0; j < 8; j++)
                    acc[i][j] = fmaf(ar[i], br[j], acc[i][j]);
        }
        __syncthreads();
    }

    float bb[8];
    #pragma unroll
    for (int j = 0; j < 8; j++) bb[j] = bias[bn + n0 + j];
    const int colg = bn + n0;
    float* OUTB = (colg < 512) ? PQ : PK;
    const int cc  = colg & 511;
    const int hh  = cc >> 6;
    const int kk0 = cc & 63;
    #pragma unroll
    for (int i = 0; i < 8; i++) {
        size_t base = (size_t)(bm + t0 + i) * 1024 + (hh << 7) + kk0;
        float sv[8], cv[8];
        #pragma unroll
        for (int j = 0; j < 8; j++) {
            float s, c;
            sincosf(acc[i][j] + bb[j], &s, &c);
            sv[j] = s * 0.125f;
            cv[j] = c * 0.125f;
        }
        float4 o;
        o.x=sv[0]; o.y=sv[1]; o.z=sv[2]; o.w=sv[3]; *(float4*)&OUTB[base]      = o;
        o.x=sv[4]; o.y=sv[5]; o.z=sv[6]; o.w=sv[7]; *(float4*)&OUTB[base + 4]  = o;
        o.x=cv[0]; o.y=cv[1]; o.z=cv[2]; o.w=cv[3]; *(float4*)&OUTB[base + 64] = o;
        o.x=cv[4]; o.y=cv[5]; o.z=cv[6]; o.w=cv[7]; *(float4*)&OUTB[base + 68] = o;
    }
}

// ---------------- per-chunk state + fused z (double-buffered) -------------------
__global__ __launch_bounds__(256) void chunk_state_kernel(
    const float* __restrict__ PK, const float* __restrict__ V,
    float* __restrict__ S, float* __restrict__ Z)
{
    __shared__ float as[2][16][128];
    __shared__ float bs[2][16][128];
    const int c = blockIdx.x, bh = blockIdx.y;
    const int b = bh >> 3, h = bh & 7;
    const int tid = threadIdx.x;
    const int t0 = (tid >> 4) << 3;
    const int n0 = (tid & 15) << 3;
    float acc[8][8] = {};
    float zacc = 0.f;

    auto load_tile = [&](int it8, int bi) {
        #pragma unroll
        for (int it = 0; it < 2; it++) {
            int idx = tid + (it << 8);
            int r  = idx >> 5;
            int c4 = (idx & 31) << 2;
            size_t grow = ((size_t)(c * CH + (it8 << 4) + r) * B_ + b) * E_ + h * D_;
            *(float4*)&as[bi][r][c4] = *(const float4*)(PK + grow + c4);
            *(float4*)&bs[bi][r][c4] = *(const float4*)(V  + grow + c4);
        }
    };

    load_tile(0, 0);
    __syncthreads();
    for (int it8 = 0; it8 < 8; it8++) {
        const int buf = it8 & 1;
        if (it8 < 7) load_tile(it8 + 1, buf ^ 1);
        if (tid < 128) {
            float za = 0.f;
            #pragma unroll
            for (int ss = 0; ss < 16; ss++) za += as[buf][ss][tid];
            zacc += za;
        }
        #pragma unroll
        for (int ss = 0; ss < 16; ss++) {
            float4 x0 = *(const float4*)&as[buf][ss][t0];
            float4 x1 = *(const float4*)&as[buf][ss][t0+4];
            float4 y0 = *(const float4*)&bs[buf][ss][n0];
            float4 y1 = *(const float4*)&bs[buf][ss][n0+4];
            float ar[8] = {x0.x,x0.y,x0.z,x0.w,x1.x,x1.y,x1.z,x1.w};
            float br[8] = {y0.x,y0.y,y0.z,y0.w,y1.x,y1.y,y1.z,y1.w};
            #pragma unroll
            for (int i = 0; i < 8; i++)
                #pragma unroll
                for (int j = 0; j < 8; j++)
                    acc[i][j] = fmaf(ar[i], br[j], acc[i][j]);
        }
        __syncthreads();
    }
    float* Sp = S + ((size_t)c * BHN + bh) * (K2 * D_);
    #pragma unroll
    for (int i = 0; i < 8; i++) {
        float4 o;
        o.x = acc[i][0]; o.y = acc[i][1]; o.z = acc[i][2]; o.w = acc[i][3];
        *(float4*)(Sp + (size_t)(t0 + i) * D_ + n0) = o;
        o.x = acc[i][4]; o.y = acc[i][5]; o.z = acc[i][6]; o.w = acc[i][7];
        *(float4*)(Sp + (size_t)(t0 + i) * D_ + n0 + 4) = o;
    }
    if (tid < 128)
        Z[((size_t)c * BHN + bh) * K2 + tid] = zacc;
}

__global__ void prefix_S_kernel(float* __restrict__ S)
{
    const int bh = blockIdx.x;
    const int e  = blockIdx.y * 256 + threadIdx.x;
    float acc = 0.f;
    for (int c = 0; c < NC; c++) {
        size_t idx = ((size_t)c * BHN + bh) * (K2 * D_) + e;
        float t = S[idx]; S[idx] = acc; acc += t;
    }
}

__global__ void prefix_z_kernel(float* __restrict__ Z)
{
    const int bh = blockIdx.x;
    const int k  = threadIdx.x;
    float acc = 0.f;
    for (int c = 0; c < NC; c++) {
        size_t idx = ((size_t)c * BHN + bh) * K2 + k;
        float t = Z[idx]; Z[idx] = acc; acc += t;
    }
}

// ---------------- RFA output (double-buffered tiles; c0 = chunk offset) ---------
#define RFA_SMEM ((128*132 + 4*16*132) * 4)   // 101376 B -> 2 CTAs/SM (202.8KB)
__global__ __launch_bounds__(256) void rfa_out_kernel(
    const float* __restrict__ PQ, const float* __restrict__ PK,
    const float* __restrict__ V,  const float* __restrict__ S,
    const float* __restrict__ Z,  __nv_bfloat16* __restrict__ A3, int c0)
{
    extern __shared__ float sm[];
    float* SC  = sm;                      // [s][t] masked scores (stride 132)
    float* TAb = sm + 128 * 132;          // 2 x [16][132] Q tiles
    float* TBb = TAb + 2 * 16 * 132;      // 2 x [16][132] K / B tiles

    const int c = blockIdx.x + c0, bh = blockIdx.y;
    const int b = bh >> 3, h = bh & 7;
    const int tid = threadIdx.x;
    const int t0 = (tid >> 4) << 3;
    const int n0 = (tid & 15) << 3;

    // phase-1 tile loader: Q,K columns (kt*16 .. +15), transposed
    auto loadQK = [&](int kt, int bi) {
        float* ta = TAb + bi * 16 * 132;
        float* tb = TBb + bi * 16 * 132;
        #pragma unroll
        for (int it = 0; it < 2; it++) {
            int idx = tid + (it << 8);
            int r  = idx >> 2;
            int c4 = (idx & 3) << 2;
            size_t grow = ((size_t)(c * CH + r) * B_ + b) * E_ + h * K2 + (kt << 4) + c4;
            float4 vq = *(const float4*)(PQ + grow);
            ta[(c4+0)*132 + r] = vq.x; ta[(c4+1)*132 + r] = vq.y;
            ta[(c4+2)*132 + r] = vq.z; ta[(c4+3)*132 + r] = vq.w;
            float4 vk = *(const float4*)(PK + grow);
            tb[(c4+0)*132 + r] = vk.x; tb[(c4+1)*132 + r] = vk.y;
            tb[(c4+2)*132 + r] = vk.z; tb[(c4+3)*132 + r] = vk.w;
        }
    };

    // ---- phase 1: scores, k-tiled by 16, ping-pong ----
    float sc[8][8] = {};
    loadQK(0, 0);
    __syncthreads();
    for (int kt = 0; kt < 8; kt++) {
        const int buf = kt & 1;
        if (kt < 7) loadQK(kt + 1, buf ^ 1);
        const float* ta = TAb + buf * 16 * 132;
        const float* tb = TBb + buf * 16 * 132;
        #pragma unroll
        for (int kk = 0; kk < 16; kk++) {
            float4 x0 = *(const float4*)&ta[kk*132 + t0];
            float4 x1 = *(const float4*)&ta[kk*132 + t0 + 4];
            float4 y0 = *(const float4*)&tb[kk*132 + n0];
            float4 y1 = *(const float4*)&tb[kk*132 + n0 + 4];
            float ar[8] = {x0.x,x0.y,x0.z,x0.w,x1.x,x1.y,x1.z,x1.w};
            float br[8] = {y0.x,y0.y,y0.z,y0.w,y1.x,y1.y,y1.z,y1.w};
            #pragma unroll
            for (int i = 0; i < 8; i++)
                #pragma unroll
                for (int j = 0; j < 8; j++)
                    sc[i][j] = fmaf(ar[i], br[j], sc[i][j]);
        }
        __syncthreads();
    }
    #pragma unroll
    for (int j = 0; j < 8; j++)
        #pragma unroll
        for (int i = 0; i < 8; i++)
            SC[(size_t)(n0 + j) * 132 + (t0 + i)] = (n0 + j <= t0 + i) ? sc[i][j] : 0.0f;
    __syncthreads();

    // phase-2 loaders
    auto loadB = [&](int kt, int bi) {
        float* tb = TBb + bi * 16 * 132;
        const int rbase = kt << 4;
        #pragma unroll
        for (int it = 0; it < 2; it++) {
            int idx = tid + (it << 8);
            int r  = idx >> 5;
            int c4 = (idx & 31) << 2;
            int rr = rbase + r;
            float4 vv;
            if (rr < 128)
                vv = *(const float4*)(V + ((size_t)(c * CH + rr) * B_ + b) * E_ + h * D_ + c4);
            else
                vv = *(const float4*)(S + ((size_t)c * BHN + bh) * (K2 * D_)
                                      + (size_t)(rr - 128) * D_ + c4);
            *(float4*)&tb[r * 132 + c4] = vv;
        }
        if (tid < 16) {
            int rr = rbase + tid;
            tb[tid * 132 + 128] = (rr < 128) ? 1.0f
                : Z[((size_t)c * BHN + bh) * K2 + (rr - 128)];
        }
    };
    auto loadQ2 = [&](int kt, int bi) {
        float* ta = TAb + bi * 16 * 132;
        const int rbase = kt << 4;
        #pragma unroll
        for (int it = 0; it < 2; it++) {
            int idx = tid + (it << 8);
            int r  = idx >> 2;
            int c4 = (idx & 3) << 2;
            size_t grow = ((size_t)(c * CH + r) * B_ + b) * E_ + h * K2
                        + (rbase - 128) + c4;
            float4 vq = *(const float4*)(PQ + grow);
            ta[(c4+0)*132 + r] = vq.x; ta[(c4+1)*132 + r] = vq.y;
            ta[(c4+2)*132 + r] = vq.z; ta[(c4+3)*132 + r] = vq.w;
        }
    };

    // ---- phase 2: num/den over 256 reduction rows, ping-pong ----
    float acc[8][8] = {};
    float dacc[8] = {};
    loadB(0, 0);
    __syncthreads();
    for (int kt = 0; kt < 16; kt++) {
        const int rbase = kt << 4;
        const int buf = kt & 1;
        if (kt < 15) {
            loadB(kt + 1, buf ^ 1);
            if (kt + 1 >= 8) loadQ2(kt + 1, buf ^ 1);
        }
        // causal skip (bit-exact): score rows s>t are exact zeros
        if (rbase >= 128 || rbase <= t0 + 7) {
            const float* Aop = (rbase < 128) ? (SC + (size_t)rbase * 132)
                                             : (TAb + buf * 16 * 132);
            const float* tb = TBb + buf * 16 * 132;
            #pragma unroll
            for (int ss = 0; ss < 16; ss++) {
                const float* arow = Aop + (size_t)ss * 132;
                float4 x0 = *(const float4*)(arow + t0);
                float4 x1 = *(const float4*)(arow + t0 + 4);
                float ar[8] = {x0.x,x0.y,x0.z,x0.w,x1.x,x1.y,x1.z,x1.w};
                float4 y0 = *(const float4*)&tb[ss * 132 + n0];
                float4 y1 = *(const float4*)&tb[ss * 132 + n0 + 4];
                float br[8] = {y0.x,y0.y,y0.z,y0.w,y1.x,y1.y,y1.z,y1.w};
                float bv = tb[ss * 132 + 128];
                #pragma unroll
                for (int i = 0; i < 8; i++) {
                    dacc[i] = fmaf(ar[i], bv, dacc[i]);
                    #pragma unroll
                    for (int j = 0; j < 8; j++)
                        acc[i][j] = fmaf(ar[i], br[j], acc[i][j]);
                }
            }
        }
        __syncthreads();
    }

    #pragma unroll
    for (int i = 0; i < 8; i++) {
        float inv = 1.0f / fmaxf(dacc[i], EPSV);
        size_t m = (size_t)(c * CH + t0 + i) * B_ + b;
        __nv_bfloat16* o = A3 + m * K3 + h * D_ + n0;
        __nv_bfloat16 hh[8], ll[8];
        #pragma unroll
        for (int j = 0; j < 8; j++) {
            float ov = acc[i][j] * inv;
            hh[j] = __float2bfloat16(ov);
            ll[j] = __float2bfloat16(ov - __bfloat162float(hh[j]));
        }
        #pragma unroll
        for (int j = 0; j < 4; j++) {
            __nv_bfloat162 hp = __halves2bfloat162(hh[2*j], hh[2*j+1]);
            __nv_bfloat162 lp = __halves2bfloat162(ll[2*j], ll[2*j+1]);
            ((__nv_bfloat162*)(o))[j]        = hp;
            ((__nv_bfloat162*)(o + 1024))[j] = lp;
            ((__nv_bfloat162*)(o + 2048))[j] = hp;
        }
    }
}

// ---------------- launcher -----------------------------------------------------
extern "C" void kernel_launch(void* const* d_in, const int* in_sizes, int n_in,
                              void* d_out, int out_size)
{
    const float* x   = (const float*)d_in[0];
    const float* rm  = (const float*)d_in[1];
    const float* Wq  = (const float*)d_in[2];
    const float* bq  = (const float*)d_in[3];
    const float* Wk  = (const float*)d_in[4];
    const float* bk  = (const float*)d_in[5];
    const float* Wv  = (const float*)d_in[6];
    const float* bv  = (const float*)d_in[7];
    const float* Wo  = (const float*)d_in[8];
    const float* bo  = (const float*)d_in[9];
    const float* sig = (const float*)d_in[10];
    float* out = (float*)d_out;

    float *v, *pq, *pk, *S, *z, *M, *pb;
    __half *a3, *wv3, *wo3;
    cudaGetSymbolAddress((void**)&v,    g_v);
    cudaGetSymbolAddress((void**)&pq,   g_pq);
    cudaGetSymbolAddress((void**)&pk,   g_pk);
    cudaGetSymbolAddress((void**)&S,    g_S);
    cudaGetSymbolAddress((void**)&z,    g_z);
    cudaGetSymbolAddress((void**)&M,    g_M);
    cudaGetSymbolAddress((void**)&pb,   g_pb);
    cudaGetSymbolAddress((void**)&a3,   g_a3);
    cudaGetSymbolAddress((void**)&wv3,  g_wv3);
    cudaGetSymbolAddress((void**)&wo3,  g_wo3);

    cudaFuncSetAttribute(rfa_out_kernel,
                         cudaFuncAttributeMaxDynamicSharedMemorySize, RFA_SMEM);
    cudaFuncSetAttribute(rfa_out_kernel,
                         cudaFuncAttributePreferredSharedMemoryCarveout, 100);
    cudaFuncSetAttribute((const void*)gemm_hmma<true, 3072>,
                         cudaFuncAttributeMaxDynamicSharedMemorySize, GEMM_SMEM);
    cudaFuncSetAttribute((const void*)gemm_hmma<true, 3072>,
                         cudaFuncAttributePreferredSharedMemoryCarveout, 100);
    cudaFuncSetAttribute((const void*)gemm_hmma<false, 3072>,
                         cudaFuncAttributeMaxDynamicSharedMemorySize, GEMM_SMEM);
    cudaFuncSetAttribute((const void*)gemm_hmma<false, 3072>,
                         cudaFuncAttributePreferredSharedMemoryCarveout, 100);

    const float invW = 1.0f / WSCALE;
    dim3 ghmma(E_ / 128, MR / 128);
    dim3 gphi_pk(4, MR / 128);
    dim3 gphi_pqh(4, MR / 256);

    // uneven rfa->O pipeline: chunks {10,10,8,4}; last piece smallest -> min tail
    const int cstart[4] = {0, 10, 20, 28};
    const int ccount[4] = {10, 10, 8, 4};

    cudaStream_t s1;
    cudaStreamCreateWithFlags(&s1, cudaStreamNonBlocking);
    cudaEvent_t eK, ePre, eR[4], eO4;
    cudaEventCreateWithFlags(&eK,   cudaEventDisableTiming);
    cudaEventCreateWithFlags(&ePre, cudaEventDisableTiming);
    for (int i = 0; i < 4; i++) cudaEventCreateWithFlags(&eR[i], cudaEventDisableTiming);
    cudaEventCreateWithFlags(&eO4,  cudaEventDisableTiming);

    // --- s1: v path (tensor) hides under the fp32 PK GEMM on s0 ---
    split3h_kernel<<<MR, 256, 0, s1>>>(x, a3, 1, 1.0f);
    split3h_kernel<<<1024, 256, 0, s1>>>(Wv, wv3, 0, WSCALE);
    gemm_hmma<true, 3072><<<ghmma, 256, GEMM_SMEM, s1>>>(a3, wv3, bv, v, invW, 0);
    split3b_kernel<<<1024, 256, 0, s1>>>(Wo, (__nv_bfloat16*)wo3, 0);

    // --- s0 FFMA chain: prep -> PK(all M) -> PQ M-half1 -> PQ M-half2 ---
    prep_M<<<1024, 128>>>(rm, sig, Wq, Wk, bq, bk, M, pb);
    sgemm_phi<<<gphi_pk, 256>>>(x, M, pb, pq, pk, 1024, 4, 0);
    cudaEventRecord(eK, 0);
    sgemm_phi<<<gphi_pqh, 256>>>(x, M, pb, pq, pk, 1024, 0, 0);
    sgemm_phi<<<gphi_pqh, 256>>>(x, M, pb, pq, pk, 1024, 0, 128);

    // --- s1: chunk path (needs pk + v) ---
    cudaStreamWaitEvent(s1, eK, 0);
    dim3 gcs(NC, BHN);
    chunk_state_kernel<<<gcs, 256, 0, s1>>>(pk, v, S, z);
    prefix_S_kernel<<<dim3(BHN, 64), 256, 0, s1>>>(S);
    prefix_z_kernel<<<BHN, 128, 0, s1>>>(z);
    cudaEventRecord(ePre, s1);

    // --- s0: rfa pieces (FFMA) unlock O pieces (tensor) on s1 ---
    cudaStreamWaitEvent(0, ePre, 0);
    for (int q = 0; q < 4; q++) {
        dim3 grfa(ccount[q], BHN);
        rfa_out_kernel<<<grfa, 256, RFA_SMEM>>>(pq, pk, v, S, z,
                                                (__nv_bfloat16*)a3, cstart[q]);
        cudaEventRecord(eR[q], 0);
    }
    for (int q = 0; q < 4; q++) {
        cudaStreamWaitEvent(s1, eR[q], 0);
        dim3 gO(E_ / 128, ccount[q] * 8);
        gemm_hmma<false, 3072><<<gO, 256, GEMM_SMEM, s1>>>(
            a3, wo3, bo, out, 1.0f, cstart[q] * 8);
    }
    cudaEventRecord(eO4, s1);
    cudaStreamWaitEvent(0, eO4, 0);
}

// round 16
// speedup vs baseline: 1.2767x; 1.0177x over previous
#include <cuda_runtime.h>
#include <cuda_bf16.h>
#include <cuda_fp16.h>
#include <cstdint>

#define T_    4096
#define B_    8
#define E_    1024
#define H_    8
#define D_    128
#define KP    64
#define K2    128
#define CH    128
#define NC    32
#define MR    32768
#define BHN   64
#define EPSV  1e-6f

#define K3        3072
#define NSTAGE    2
#define STAGE_B   32768
#define GEMM_SMEM (NSTAGE * STAGE_B)   // 64KB
#define WSCALE    1024.0f

// ---------------- scratch ---------------------------------------------------
__device__ float g_v[33554432];
__device__ float g_pq[33554432];
__device__ float g_pk[33554432];
__device__ float g_S[33554432];
__device__ float g_z[262144];
__device__ float g_M[1048576];
__device__ float g_pb[1024];
__device__ __half g_a3[100663296];   // [MR][3072] x fp16x3, later attn bf16x3 (reuse)
__device__ __half g_wv3[3145728];    // Wv fp16x3
__device__ __half g_wo3[3145728];    // Wo bf16x3 (bits in half storage)

// ---------------- PTX helpers -----------------------------------------------
__device__ __forceinline__ uint32_t smem_u32(const void* p) {
    uint32_t a;
    asm("{ .reg .u64 t; cvta.to.shared.u64 t, %1; cvt.u32.u64 %0, t; }"
        : "=r"(a) : "l"(p));
    return a;
}
__device__ __forceinline__ void cp16(uint32_t dst, const void* src) {
    asm volatile("cp.async.cg.shared.global [%0], [%1], 16;" :: "r"(dst), "l"(src));
}
__device__ __forceinline__ void ldm_x4(uint32_t& r0, uint32_t& r1,
                                       uint32_t& r2, uint32_t& r3, uint32_t addr) {
    asm volatile("ldmatrix.sync.aligned.m8n8.x4.shared.b16 {%0,%1,%2,%3}, [%4];"
                 : "=r"(r0), "=r"(r1), "=r"(r2), "=r"(r3) : "r"(addr));
}
__device__ __forceinline__ void mma_f16(float* c, const uint32_t* a,
                                        uint32_t b0, uint32_t b1) {
    asm volatile(
        "mma.sync.aligned.m16n8k16.row.col.f32.f16.f16.f32 "
        "{%0,%1,%2,%3}, {%4,%5,%6,%7}, {%8,%9}, {%0,%1,%2,%3};"
        : "+f"(c[0]), "+f"(c[1]), "+f"(c[2]), "+f"(c[3])
        : "r"(a[0]), "r"(a[1]), "r"(a[2]), "r"(a[3]), "r"(b0), "r"(b1));
}
__device__ __forceinline__ void mma_bf16(float* c, const uint32_t* a,
                                         uint32_t b0, uint32_t b1) {
    asm volatile(
        "mma.sync.aligned.m16n8k16.row.col.f32.bf16.bf16.f32 "
        "{%0,%1,%2,%3}, {%4,%5,%6,%7}, {%8,%9}, {%0,%1,%2,%3};"
        : "+f"(c[0]), "+f"(c[1]), "+f"(c[2]), "+f"(c[3])
        : "r"(a[0]), "r"(a[1]), "r"(a[2]), "r"(a[3]), "r"(b0), "r"(b1));
}
__device__ __forceinline__ uint32_t packh(__half lo, __half hi) {
    __half2 p = __halves2half2(lo, hi);
    return *(uint32_t*)&p;
}

// ---------------- prep: fused q/k projection matrix + bias -------------------
__global__ __launch_bounds__(128) void prep_M(
    const float* __restrict__ rm, const float* __restrict__ sig,
    const float* __restrict__ Wq, const float* __restrict__ Wk,
    const float* __restrict__ bq, const float* __restrict__ bk,
    float* __restrict__ M, float* __restrict__ pb)
{
    const int row = blockIdx.x;
    const int isK = row >> 9;
    const int h   = (row >> 6) & 7;
    const int kk  = row & 63;
    const float* W  = isK ? Wk : Wq;
    const float* bb = isK ? bk : bq;
    __shared__ float r[128];
    const int tid = threadIdx.x;
    const float c = 0.29730177875068026f;
    r[tid] = c * sig[h * 128 + tid] * rm[((size_t)(h * 64 + kk)) * 128 + tid];
    __syncthreads();
    for (int e = tid; e < 1024; e += 128) {
        float acc = 0.f;
        #pragma unroll 8
        for (int d = 0; d < 128; d++)
            acc = fmaf(r[d], W[(size_t)(h * 128 + d) * 1024 + e], acc);
        M[(size_t)row * 1024 + e] = acc;
    }
    if (tid == 0) {
        float acc = 0.f;
        for (int d = 0; d < 128; d++) acc = fmaf(r[d], bb[h * 128 + d], acc);
        pb[row] = acc;
    }
}

// ---------------- split fp32 -> fp16 x3 concat --------------------------------
__global__ __launch_bounds__(256) void split3h_kernel(
    const float* __restrict__ X, __half* __restrict__ O, int midIsLo, float scale)
{
    size_t idx = (size_t)blockIdx.x * 256 + threadIdx.x;
    size_t m = idx >> 8;
    int kq = (int)(idx & 255) << 2;
    float4 v = *(const float4*)(X + m * 1024 + kq);
    float f[4] = {v.x * scale, v.y * scale, v.z * scale, v.w * scale};
    __half h[4], l[4];
    #pragma unroll
    for (int i = 0; i < 4; i++) {
        h[i] = __float2half(f[i]);
        l[i] = __float2half(f[i] - __half2float(h[i]));
    }
    __half2 hp0 = __halves2half2(h[0], h[1]);
    __half2 hp1 = __halves2half2(h[2], h[3]);
    __half2 lp0 = __halves2half2(l[0], l[1]);
    __half2 lp1 = __halves2half2(l[2], l[3]);
    __half* o = O + m * K3 + kq;
    ((__half2*)o)[0] = hp0;
    ((__half2*)o)[1] = hp1;
    ((__half2*)(o + 1024))[0] = midIsLo ? lp0 : hp0;
    ((__half2*)(o + 1024))[1] = midIsLo ? lp1 : hp1;
    ((__half2*)(o + 2048))[0] = midIsLo ? hp0 : lp0;
    ((__half2*)(o + 2048))[1] = midIsLo ? hp1 : lp1;
}

// ---------------- split fp32 -> bf16 x3 concat --------------------------------
__global__ __launch_bounds__(256) void split3b_kernel(
    const float* __restrict__ X, __nv_bfloat16* __restrict__ O, int midIsLo)
{
    size_t idx = (size_t)blockIdx.x * 256 + threadIdx.x;
    size_t m = idx >> 8;
    int kq = (int)(idx & 255) << 2;
    float4 v = *(const float4*)(X + m * 1024 + kq);
    float f[4] = {v.x, v.y, v.z, v.w};
    __nv_bfloat16 h[4], l[4];
    #pragma unroll
    for (int i = 0; i < 4; i++) {
        h[i] = __float2bfloat16(f[i]);
        l[i] = __float2bfloat16(f[i] - __bfloat162float(h[i]));
    }
    __nv_bfloat162 hp0 = __halves2bfloat162(h[0], h[1]);
    __nv_bfloat162 hp1 = __halves2bfloat162(h[2], h[3]);
    __nv_bfloat162 lp0 = __halves2bfloat162(l[0], l[1]);
    __nv_bfloat162 lp1 = __halves2bfloat162(l[2], l[3]);
    __nv_bfloat16* o = O + m * K3 + kq;
    ((__nv_bfloat162*)o)[0] = hp0;
    ((__nv_bfloat162*)o)[1] = hp1;
    ((__nv_bfloat162*)(o + 1024))[0] = midIsLo ? lp0 : hp0;
    ((__nv_bfloat162*)(o + 1024))[1] = midIsLo ? lp1 : hp1;
    ((__nv_bfloat162*)(o + 2048))[0] = midIsLo ? hp0 : lp0;
    ((__nv_bfloat162*)(o + 2048))[1] = midIsLo ? hp1 : lp1;
}

// ---------------- HMMA GEMM: C = (A . W^T) * outScale + bias ------------------
template<bool FP16, int KTOT>
__global__ __launch_bounds__(256) void gemm_hmma(
    const void* __restrict__ A3v, const void* __restrict__ W3v,
    const float* __restrict__ bias, float* __restrict__ C, float outScale, int moff)
{
    constexpr int NCHUNK = KTOT / 64;
    constexpr int ROWB   = KTOT * 2;
    extern __shared__ __align__(128) char smem[];
    const uint32_t sb = smem_u32(smem);
    const int tid  = threadIdx.x;
    const int lane = tid & 31;
    const int wid  = tid >> 5;
    const int m0 = (blockIdx.y + moff) << 7;
    const int n0 = blockIdx.x << 7;
    const int wm = (wid >> 1) << 5;
    const int wn = (wid & 1) << 6;

    const char* Abase = (const char*)A3v + (size_t)m0 * ROWB;
    const char* Bbase = (const char*)W3v + (size_t)n0 * ROWB;

    const int lrow = tid >> 1;
    const int lc0  = (tid & 1) << 2;
    auto load_stage = [&](int chunk, int st) {
        const size_t gcol = (size_t)(chunk << 7);
        const uint32_t sa = sb + st * STAGE_B;
        #pragma unroll
        for (int c = 0; c < 4; c++) {
            int ch = lc0 + c;
            uint32_t soff = (lrow << 7) + (((ch ^ (lrow & 7))) << 4);
            cp16(sa + soff,         Abase + (size_t)lrow * ROWB + gcol + (ch << 4));
            cp16(sa + 16384 + soff, Bbase + (size_t)lrow * ROWB + gcol + (ch << 4));
        }
    };

    #pragma unroll
    for (int s = 0; s < NSTAGE; s++) {
        load_stage(s, s);
        asm volatile("cp.async.commit_group;" ::: "memory");
    }

    const int amln = wm + (lane & 15);
    const int acb  = (lane >> 4) << 4;
    const int asw  = (amln & 7) << 4;
    const int bnln = wn + (lane & 7) + ((lane & 16) >> 1);
    const int bcb  = (lane & 8) << 1;
    const int bsw  = (lane & 7) << 4;

    float acc[2][8][4] = {};

    for (int i = 0; i < NCHUNK; i++) {
        asm volatile("cp.async.wait_group %0;" :: "n"(NSTAGE - 1) : "memory");
        __syncthreads();
        const int st = i % NSTAGE;
        const uint32_t sa = sb + st * STAGE_B;
        const uint32_t sbB = sa + 16384;
        #pragma unroll
        for (int ks = 0; ks < 4; ks++) {
            uint32_t a[2][4];
            #pragma unroll
            for (int mi = 0; mi < 2; mi++) {
                uint32_t addr = sa + ((amln + (mi << 4)) << 7)
                              + (((ks << 5) + acb) ^ asw);
                ldm_x4(a[mi][0], a[mi][1], a[mi][2], a[mi][3], addr);
            }
            #pragma unroll
            for (int njp = 0; njp < 4; njp++) {
                uint32_t q0, q1, q2, q3;
                uint32_t addr = sbB + ((bnln + (njp << 4)) << 7)
                              + (((ks << 5) + bcb) ^ bsw);
                ldm_x4(q0, q1, q2, q3, addr);
                if (FP16) {
                    mma_f16(acc[0][2*njp],     a[0], q0, q1);
                    mma_f16(acc[0][2*njp + 1], a[0], q2, q3);
                    mma_f16(acc[1][2*njp],     a[1], q0, q1);
                    mma_f16(acc[1][2*njp + 1], a[1], q2, q3);
                } else {
                    mma_bf16(acc[0][2*njp],     a[0], q0, q1);
                    mma_bf16(acc[0][2*njp + 1], a[0], q2, q3);
                    mma_bf16(acc[1][2*njp],     a[1], q0, q1);
                    mma_bf16(acc[1][2*njp + 1], a[1], q2, q3);
                }
            }
        }
        __syncthreads();
        if (i + NSTAGE < NCHUNK) load_stage(i + NSTAGE, st);
        asm volatile("cp.async.commit_group;" ::: "memory");
    }

    const int rbase = m0 + wm + (lane >> 2);
    const int cbase = n0 + wn + ((lane & 3) << 1);
    #pragma unroll
    for (int mi = 0; mi < 2; mi++) {
        #pragma unroll
        for (int nj = 0; nj < 8; nj++) {
            int col = cbase + (nj << 3);
            float b0 = bias[col], b1 = bias[col + 1];
            float* p0 = C + (size_t)(rbase + (mi << 4)) * 1024 + col;
            float* p1 = p0 + 8 * 1024;
            float2 v0 = {acc[mi][nj][0] * outScale + b0, acc[mi][nj][1] * outScale + b1};
            float2 v1 = {acc[mi][nj][2] * outScale + b0, acc[mi][nj][3] * outScale + b1};
            *(float2*)p0 = v0;
            *(float2*)p1 = v1;
        }
    }
}

// ---------------- fp32 SGEMM + fused phi (bnoff = N offset, moff = M offset) --
__global__ __launch_bounds__(256) void sgemm_phi(
    const float* __restrict__ A, const float* __restrict__ Bm,
    const float* __restrict__ bias,
    float* __restrict__ PQ, float* __restrict__ PK, int Kd, int bnoff, int moff)
{
    __shared__ float As[16][128];
    __shared__ float Bs[16][128];
    const int bm = (blockIdx.y + moff) * 128;
    const int bn = (blockIdx.x + bnoff) * 128;
    const int tid = threadIdx.x;
    const int t0 = (tid >> 4) << 3;
    const int n0 = (tid & 15) << 3;
    const int lr = tid >> 2;
    const int lc = (tid & 3) << 2;
    const float* Ap = A + (size_t)(bm + lr) * Kd + lc;
    const float* Bp = Bm + (size_t)(bn + lr) * Kd + lc;
    const size_t half = (size_t)64 * Kd;

    float4 a0 = *(const float4*)(Ap);
    float4 a1 = *(const float4*)(Ap + half);
    float4 b0 = *(const float4*)(Bp);
    float4 b1 = *(const float4*)(Bp + half);

    float acc[8][8] = {};
    for (int k0 = 0; k0 < Kd; k0 += 16) {
        As[lc+0][lr]    = a0.x; As[lc+1][lr]    = a0.y; As[lc+2][lr]    = a0.z; As[lc+3][lr]    = a0.w;
        As[lc+0][lr+64] = a1.x; As[lc+1][lr+64] = a1.y; As[lc+2][lr+64] = a1.z; As[lc+3][lr+64] = a1.w;
        Bs[lc+0][lr]    = b0.x; Bs[lc+1][lr]    = b0.y; Bs[lc+2][lr]    = b0.z; Bs[lc+3][lr]    = b0.w;
        Bs[lc+0][lr+64] = b1.x; Bs[lc+1][lr+64] = b1.y; Bs[lc+2][lr+64] = b1.z; Bs[lc+3][lr+64] = b1.w;
        __syncthreads();
        if (k0 + 16 < Kd) {
            a0 = *(const float4*)(Ap + k0 + 16);
            a1 = *(const float4*)(Ap + k0 + 16 + half);
            b0 = *(const float4*)(Bp + k0 + 16);
            b1 = *(const float4*)(Bp + k0 + 16 + half);
        }
        #pragma unroll
        for (int kk = 0; kk < 16; kk++) {
            float4 x0 = *(const float4*)&As[kk][t0];
            float4 x1 = *(const float4*)&As[kk][t0+4];
            float4 y0 = *(const float4*)&Bs[kk][n0];
            float4 y1 = *(const float4*)&Bs[kk][n0+4];
            float ar[8] = {x0.x,x0.y,x0.z,x0.w,x1.x,x1.y,x1.z,x1.w};
            float br[8] = {y0.x,y0.y,y0.z,y0.w,y1.x,y1.y,y1.z,y1.w};
            #pragma unroll
            for (int i = 0; i < 8; i++)
                #pragma unroll
                for (int j = 0; j < 8; j++)
                    acc[i][j] = fmaf(ar[i], br[j], acc[i][j]);
        }
        __syncthreads();
    }

    float bb[8];
    #pragma unroll
    for (int j = 0; j < 8; j++) bb[j] = bias[bn + n0 + j];
    const int colg = bn + n0;
    float* OUTB = (colg < 512) ? PQ : PK;
    const int cc  = colg & 511;
    const int hh  = cc >> 6;
    const int kk0 = cc & 63;
    #pragma unroll
    for (int i = 0; i < 8; i++) {
        size_t base = (size_t)(bm + t0 + i) * 1024 + (hh << 7) + kk0;
        float sv[8], cv[8];
        #pragma unroll
        for (int j = 0; j < 8; j++) {
            float s, c;
            sincosf(acc[i][j] + bb[j], &s, &c);
            sv[j] = s * 0.125f;
            cv[j] = c * 0.125f;
        }
        float4 o;
        o.x=sv[0]; o.y=sv[1]; o.z=sv[2]; o.w=sv[3]; *(float4*)&OUTB[base]      = o;
        o.x=sv[4]; o.y=sv[5]; o.z=sv[6]; o.w=sv[7]; *(float4*)&OUTB[base + 4]  = o;
        o.x=cv[0]; o.y=cv[1]; o.z=cv[2]; o.w=cv[3]; *(float4*)&OUTB[base + 64] = o;
        o.x=cv[4]; o.y=cv[5]; o.z=cv[6]; o.w=cv[7]; *(float4*)&OUTB[base + 68] = o;
    }
}

// ---------------- per-chunk state via HMMA (fp16x3) + bit-exact fp32 z ----------
// S[k2][d] = sum_s pk[s][k2]*v[s][d]. A-frag from ph/pl [s][k2], B-frag from
// vh/vl [s][d]; products hh+lh+hl cover x3; accum fp32; S = acc * 2^-16.
// z summed from the fp32 pk tile in the same order as the old kernel (bit-exact).
#define CSPW 136
__global__ __launch_bounds__(256) void chunk_state_kernel(
    const float* __restrict__ PK, const float* __restrict__ V,
    float* __restrict__ S, float* __restrict__ Z)
{
    __shared__ float  ps32[16][128];
    __shared__ __half ph[16][CSPW];
    __shared__ __half pl[16][CSPW];
    __shared__ __half vh[16][CSPW];
    __shared__ __half vl[16][CSPW];

    const int c = blockIdx.x, bh = blockIdx.y;
    const int b = bh >> 3, h = bh & 7;
    const int tid = threadIdx.x;
    const int lane = tid & 31;
    const int wid  = tid >> 5;
    const int wm = (wid >> 1) << 5;   // k2 base (0,32,64,96)
    const int wn = (wid & 1) << 6;    // d base (0,64)

    float acc[2][8][4] = {};
    float zacc = 0.f;

    for (int st = 0; st < 8; st++) {
        // load + convert tiles (16 s-rows x 128)
        #pragma unroll
        for (int it = 0; it < 2; it++) {
            int idx = tid + (it << 8);
            int r  = idx >> 5;
            int c4 = (idx & 31) << 2;
            size_t grow = ((size_t)(c * CH + (st << 4) + r) * B_ + b) * E_ + h * D_;
            float4 pv = *(const float4*)(PK + grow + c4);
            float4 vv = *(const float4*)(V  + grow + c4);
            *(float4*)&ps32[r][c4] = pv;
            float pf[4] = {pv.x*256.f, pv.y*256.f, pv.z*256.f, pv.w*256.f};
            float vf[4] = {vv.x*256.f, vv.y*256.f, vv.z*256.f, vv.w*256.f};
            #pragma unroll
            for (int j = 0; j < 4; j++) {
                __half hh_ = __float2half(pf[j]);
                ph[r][c4+j] = hh_;
                pl[r][c4+j] = __float2half(pf[j] - __half2float(hh_));
                __half vhh = __float2half(vf[j]);
                vh[r][c4+j] = vhh;
                vl[r][c4+j] = __float2half(vf[j] - __half2float(vhh));
            }
        }
        __syncthreads();

        // bit-exact z (same order as the old fp32 kernel)
        if (tid < 128) {
            float za = 0.f;
            #pragma unroll
            for (int ss = 0; ss < 16; ss++) za += ps32[ss][tid];
            zacc += za;
        }

        // a-frags: A[m=k2][k=s] = ph/pl[s][k2]
        const int s0l = (lane & 3) << 1;
        uint32_t ah[2][4], al[2][4];
        #pragma unroll
        for (int mf = 0; mf < 2; mf++) {
            int k2a = wm + (mf << 4) + (lane >> 2);
            ah[mf][0] = packh(ph[s0l  ][k2a],   ph[s0l+1][k2a]);
            ah[mf][1] = packh(ph[s0l  ][k2a+8], ph[s0l+1][k2a+8]);
            ah[mf][2] = packh(ph[s0l+8][k2a],   ph[s0l+9][k2a]);
            ah[mf][3] = packh(ph[s0l+8][k2a+8], ph[s0l+9][k2a+8]);
            al[mf][0] = packh(pl[s0l  ][k2a],   pl[s0l+1][k2a]);
            al[mf][1] = packh(pl[s0l  ][k2a+8], pl[s0l+1][k2a+8]);
            al[mf][2] = packh(pl[s0l+8][k2a],   pl[s0l+9][k2a]);
            al[mf][3] = packh(pl[s0l+8][k2a+8], pl[s0l+9][k2a+8]);
        }
        // b-frags per nf: B[n=d][k=s] = vh/vl[s][d]
        #pragma unroll
        for (int nf = 0; nf < 8; nf++) {
            int dn = wn + (nf << 3) + (lane >> 2);
            uint32_t bh0 = packh(vh[s0l  ][dn], vh[s0l+1][dn]);
            uint32_t bh1 = packh(vh[s0l+8][dn], vh[s0l+9][dn]);
            uint32_t bl0 = packh(vl[s0l  ][dn], vl[s0l+1][dn]);
            uint32_t bl1 = packh(vl[s0l+8][dn], vl[s0l+9][dn]);
            #pragma unroll
            for (int mf = 0; mf < 2; mf++) {
                mma_f16(acc[mf][nf], ah[mf], bh0, bh1);   // h*h
                mma_f16(acc[mf][nf], al[mf], bh0, bh1);   // l*h
                mma_f16(acc[mf][nf], ah[mf], bl0, bl1);   // h*l
            }
        }
        __syncthreads();
    }

    // epilogue: S[k2][d] = acc * 2^-16
    const float osc = 1.0f / 65536.0f;
    float* Sp = S + ((size_t)c * BHN + bh) * (K2 * D_);
    const int rbase = wm + (lane >> 2);
    const int cbase = wn + ((lane & 3) << 1);
    #pragma unroll
    for (int mf = 0; mf < 2; mf++) {
        #pragma unroll
        for (int nf = 0; nf < 8; nf++) {
            int col = cbase + (nf << 3);
            float2 v0 = {acc[mf][nf][0] * osc, acc[mf][nf][1] * osc};
            float2 v1 = {acc[mf][nf][2] * osc, acc[mf][nf][3] * osc};
            *(float2*)(Sp + (size_t)(rbase + (mf << 4)) * D_ + col) = v0;
            *(float2*)(Sp + (size_t)(rbase + (mf << 4) + 8) * D_ + col) = v1;
        }
    }
    if (tid < 128)
        Z[((size_t)c * BHN + bh) * K2 + tid] = zacc;
}

__global__ void prefix_S_kernel(float* __restrict__ S)
{
    const int bh = blockIdx.x;
    const int e  = blockIdx.y * 256 + threadIdx.x;
    float acc = 0.f;
    for (int c = 0; c < NC; c++) {
        size_t idx = ((size_t)c * BHN + bh) * (K2 * D_) + e;
        float t = S[idx]; S[idx] = acc; acc += t;
    }
}

__global__ void prefix_z_kernel(float* __restrict__ Z)
{
    const int bh = blockIdx.x;
    const int k  = threadIdx.x;
    float acc = 0.f;
    for (int c = 0; c < NC; c++) {
        size_t idx = ((size_t)c * BHN + bh) * K2 + k;
        float t = Z[idx]; Z[idx] = acc; acc += t;
    }
}

// ---------------- RFA output (double-buffered tiles; c0 = chunk offset) ---------
#define RFA_SMEM ((128*132 + 4*16*132) * 4)   // 101376 B -> 2 CTAs/SM
__global__ __launch_bounds__(256) void rfa_out_kernel(
    const float* __restrict__ PQ, const float* __restrict__ PK,
    const float* __restrict__ V,  const float* __restrict__ S,
    const float* __restrict__ Z,  __nv_bfloat16* __restrict__ A3, int c0)
{
    extern __shared__ float sm[];
    float* SC  = sm;
    float* TAb = sm + 128 * 132;
    float* TBb = TAb + 2 * 16 * 132;

    const int c = blockIdx.x + c0, bh = blockIdx.y;
    const int b = bh >> 3, h = bh & 7;
    const int tid = threadIdx.x;
    const int t0 = (tid >> 4) << 3;
    const int n0 = (tid & 15) << 3;

    auto loadQK = [&](int kt, int bi) {
        float* ta = TAb + bi * 16 * 132;
        float* tb = TBb + bi * 16 * 132;
        #pragma unroll
        for (int it = 0; it < 2; it++) {
            int idx = tid + (it << 8);
            int r  = idx >> 2;
            int c4 = (idx & 3) << 2;
            size_t grow = ((size_t)(c * CH + r) * B_ + b) * E_ + h * K2 + (kt << 4) + c4;
            float4 vq = *(const float4*)(PQ + grow);
            ta[(c4+0)*132 + r] = vq.x; ta[(c4+1)*132 + r] = vq.y;
            ta[(c4+2)*132 + r] = vq.z; ta[(c4+3)*132 + r] = vq.w;
            float4 vk = *(const float4*)(PK + grow);
            tb[(c4+0)*132 + r] = vk.x; tb[(c4+1)*132 + r] = vk.y;
            tb[(c4+2)*132 + r] = vk.z; tb[(c4+3)*132 + r] = vk.w;
        }
    };

    float sc[8][8] = {};
    loadQK(0, 0);
    __syncthreads();
    for (int kt = 0; kt < 8; kt++) {
        const int buf = kt & 1;
        if (kt < 7) loadQK(kt + 1, buf ^ 1);
        const float* ta = TAb + buf * 16 * 132;
        const float* tb = TBb + buf * 16 * 132;
        #pragma unroll
        for (int kk = 0; kk < 16; kk++) {
            float4 x0 = *(const float4*)&ta[kk*132 + t0];
            float4 x1 = *(const float4*)&ta[kk*132 + t0 + 4];
            float4 y0 = *(const float4*)&tb[kk*132 + n0];
            float4 y1 = *(const float4*)&tb[kk*132 + n0 + 4];
            float ar[8] = {x0.x,x0.y,x0.z,x0.w,x1.x,x1.y,x1.z,x1.w};
            float br[8] = {y0.x,y0.y,y0.z,y0.w,y1.x,y1.y,y1.z,y1.w};
            #pragma unroll
            for (int i = 0; i < 8; i++)
                #pragma unroll
                for (int j = 0; j < 8; j++)
                    sc[i][j] = fmaf(ar[i], br[j], sc[i][j]);
        }
        __syncthreads();
    }
    #pragma unroll
    for (int j = 0; j < 8; j++)
        #pragma unroll
        for (int i = 0; i < 8; i++)
            SC[(size_t)(n0 + j) * 132 + (t0 + i)] = (n0 + j <= t0 + i) ? sc[i][j] : 0.0f;
    __syncthreads();

    auto loadB = [&](int kt, int bi) {
        float* tb = TBb + bi * 16 * 132;
        const int rbase = kt << 4;
        #pragma unroll
        for (int it = 0; it < 2; it++) {
            int idx = tid + (it << 8);
            int r  = idx >> 5;
            int c4 = (idx & 31) << 2;
            int rr = rbase + r;
            float4 vv;
            if (rr < 128)
                vv = *(const float4*)(V + ((size_t)(c * CH + rr) * B_ + b) * E_ + h * D_ + c4);
            else
                vv = *(const float4*)(S + ((size_t)c * BHN + bh) * (K2 * D_)
                                      + (size_t)(rr - 128) * D_ + c4);
            *(float4*)&tb[r * 132 + c4] = vv;
        }
        if (tid < 16) {
            int rr = rbase + tid;
            tb[tid * 132 + 128] = (rr < 128) ? 1.0f
                : Z[((size_t)c * BHN + bh) * K2 + (rr - 128)];
        }
    };
    auto loadQ2 = [&](int kt, int bi) {
        float* ta = TAb + bi * 16 * 132;
        const int rbase = kt << 4;
        #pragma unroll
        for (int it = 0; it < 2; it++) {
            int idx = tid + (it << 8);
            int r  = idx >> 2;
            int c4 = (idx & 3) << 2;
            size_t grow = ((size_t)(c * CH + r) * B_ + b) * E_ + h * K2
                        + (rbase - 128) + c4;
            float4 vq = *(const float4*)(PQ + grow);
            ta[(c4+0)*132 + r] = vq.x; ta[(c4+1)*132 + r] = vq.y;
            ta[(c4+2)*132 + r] = vq.z; ta[(c4+3)*132 + r] = vq.w;
        }
    };

    float acc[8][8] = {};
    float dacc[8] = {};
    loadB(0, 0);
    __syncthreads();
    for (int kt = 0; kt < 16; kt++) {
        const int rbase = kt << 4;
        const int buf = kt & 1;
        if (kt < 15) {
            loadB(kt + 1, buf ^ 1);
            if (kt + 1 >= 8) loadQ2(kt + 1, buf ^ 1);
        }
        if (rbase >= 128 || rbase <= t0 + 7) {
            const float* Aop = (rbase < 128) ? (SC + (size_t)rbase * 132)
                                             : (TAb + buf * 16 * 132);
            const float* tb = TBb + buf * 16 * 132;
            #pragma unroll
            for (int ss = 0; ss < 16; ss++) {
                const float* arow = Aop + (size_t)ss * 132;
                float4 x0 = *(const float4*)(arow + t0);
                float4 x1 = *(const float4*)(arow + t0 + 4);
                float ar[8] = {x0.x,x0.y,x0.z,x0.w,x1.x,x1.y,x1.z,x1.w};
                float4 y0 = *(const float4*)&tb[ss * 132 + n0];
                float4 y1 = *(const float4*)&tb[ss * 132 + n0 + 4];
                float br[8] = {y0.x,y0.y,y0.z,y0.w,y1.x,y1.y,y1.z,y1.w};
                float bv = tb[ss * 132 + 128];
                #pragma unroll
                for (int i = 0; i < 8; i++) {
                    dacc[i] = fmaf(ar[i], bv, dacc[i]);
                    #pragma unroll
                    for (int j = 0; j < 8; j++)
                        acc[i][j] = fmaf(ar[i], br[j], acc[i][j]);
                }
            }
        }
        __syncthreads();
    }

    #pragma unroll
    for (int i = 0; i < 8; i++) {
        float inv = 1.0f / fmaxf(dacc[i], EPSV);
        size_t m = (size_t)(c * CH + t0 + i) * B_ + b;
        __nv_bfloat16* o = A3 + m * K3 + h * D_ + n0;
        __nv_bfloat16 hh[8], ll[8];
        #pragma unroll
        for (int j = 0; j < 8; j++) {
            float ov = acc[i][j] * inv;
            hh[j] = __float2bfloat16(ov);
            ll[j] = __float2bfloat16(ov - __bfloat162float(hh[j]));
        }
        #pragma unroll
        for (int j = 0; j < 4; j++) {
            __nv_bfloat162 hp = __halves2bfloat162(hh[2*j], hh[2*j+1]);
            __nv_bfloat162 lp = __halves2bfloat162(ll[2*j], ll[2*j+1]);
            ((__nv_bfloat162*)(o))[j]        = hp;
            ((__nv_bfloat162*)(o + 1024))[j] = lp;
            ((__nv_bfloat162*)(o + 2048))[j] = hp;
        }
    }
}

// ---------------- launcher -----------------------------------------------------
extern "C" void kernel_launch(void* const* d_in, const int* in_sizes, int n_in,
                              void* d_out, int out_size)
{
    const float* x   = (const float*)d_in[0];
    const float* rm  = (const float*)d_in[1];
    const float* Wq  = (const float*)d_in[2];
    const float* bq  = (const float*)d_in[3];
    const float* Wk  = (const float*)d_in[4];
    const float* bk  = (const float*)d_in[5];
    const float* Wv  = (const float*)d_in[6];
    const float* bv  = (const float*)d_in[7];
    const float* Wo  = (const float*)d_in[8];
    const float* bo  = (const float*)d_in[9];
    const float* sig = (const float*)d_in[10];
    float* out = (float*)d_out;

    float *v, *pq, *pk, *S, *z, *M, *pb;
    __half *a3, *wv3, *wo3;
    cudaGetSymbolAddress((void**)&v,    g_v);
    cudaGetSymbolAddress((void**)&pq,   g_pq);
    cudaGetSymbolAddress((void**)&pk,   g_pk);
    cudaGetSymbolAddress((void**)&S,    g_S);
    cudaGetSymbolAddress((void**)&z,    g_z);
    cudaGetSymbolAddress((void**)&M,    g_M);
    cudaGetSymbolAddress((void**)&pb,   g_pb);
    cudaGetSymbolAddress((void**)&a3,   g_a3);
    cudaGetSymbolAddress((void**)&wv3,  g_wv3);
    cudaGetSymbolAddress((void**)&wo3,  g_wo3);

    cudaFuncSetAttribute(rfa_out_kernel,
                         cudaFuncAttributeMaxDynamicSharedMemorySize, RFA_SMEM);
    cudaFuncSetAttribute(rfa_out_kernel,
                         cudaFuncAttributePreferredSharedMemoryCarveout, 100);
    cudaFuncSetAttribute((const void*)gemm_hmma<true, 3072>,
                         cudaFuncAttributeMaxDynamicSharedMemorySize, GEMM_SMEM);
    cudaFuncSetAttribute((const void*)gemm_hmma<true, 3072>,
                         cudaFuncAttributePreferredSharedMemoryCarveout, 100);
    cudaFuncSetAttribute((const void*)gemm_hmma<false, 3072>,
                         cudaFuncAttributeMaxDynamicSharedMemorySize, GEMM_SMEM);
    cudaFuncSetAttribute((const void*)gemm_hmma<false, 3072>,
                         cudaFuncAttributePreferredSharedMemoryCarveout, 100);

    const float invW = 1.0f / WSCALE;
    dim3 ghmma(E_ / 128, MR / 128);
    dim3 gphi_pk(4, MR / 128);
    dim3 gphi_pqh(4, MR / 256);

    const int cstart[4] = {0, 10, 20, 28};
    const int ccount[4] = {10, 10, 8, 4};

    cudaStream_t s1;
    cudaStreamCreateWithFlags(&s1, cudaStreamNonBlocking);
    cudaEvent_t eK, ePre, eR[4], eO4;
    cudaEventCreateWithFlags(&eK,   cudaEventDisableTiming);
    cudaEventCreateWithFlags(&ePre, cudaEventDisableTiming);
    for (int i = 0; i < 4; i++) cudaEventCreateWithFlags(&eR[i], cudaEventDisableTiming);
    cudaEventCreateWithFlags(&eO4,  cudaEventDisableTiming);

    // --- s1: v path (tensor) hides under the fp32 PK GEMM on s0 ---
    split3h_kernel<<<MR, 256, 0, s1>>>(x, a3, 1, 1.0f);
    split3h_kernel<<<1024, 256, 0, s1>>>(Wv, wv3, 0, WSCALE);
    gemm_hmma<true, 3072><<<ghmma, 256, GEMM_SMEM, s1>>>(a3, wv3, bv, v, invW, 0);
    split3b_kernel<<<1024, 256, 0, s1>>>(Wo, (__nv_bfloat16*)wo3, 0);

    // --- s0 FFMA chain: prep -> PK(all M) -> PQ M-half1 -> PQ M-half2 ---
    prep_M<<<1024, 128>>>(rm, sig, Wq, Wk, bq, bk, M, pb);
    sgemm_phi<<<gphi_pk, 256>>>(x, M, pb, pq, pk, 1024, 4, 0);
    cudaEventRecord(eK, 0);
    sgemm_phi<<<gphi_pqh, 256>>>(x, M, pb, pq, pk, 1024, 0, 0);
    sgemm_phi<<<gphi_pqh, 256>>>(x, M, pb, pq, pk, 1024, 0, 128);

    // --- s1: chunk path (tensor-pipe chunk_state; needs pk + v) ---
    cudaStreamWaitEvent(s1, eK, 0);
    dim3 gcs(NC, BHN);
    chunk_state_kernel<<<gcs, 256, 0, s1>>>(pk, v, S, z);
    prefix_S_kernel<<<dim3(BHN, 64), 256, 0, s1>>>(S);
    prefix_z_kernel<<<BHN, 128, 0, s1>>>(z);
    cudaEventRecord(ePre, s1);

    // --- s0: rfa pieces (FFMA) unlock O pieces (tensor) on s1 ---
    cudaStreamWaitEvent(0, ePre, 0);
    for (int q = 0; q < 4; q++) {
        dim3 grfa(ccount[q], BHN);
        rfa_out_kernel<<<grfa, 256, RFA_SMEM>>>(pq, pk, v, S, z,
                                                (__nv_bfloat16*)a3, cstart[q]);
        cudaEventRecord(eR[q], 0);
    }
    for (int q = 0; q < 4; q++) {
        cudaStreamWaitEvent(s1, eR[q], 0);
        dim3 gO(E_ / 128, ccount[q] * 8);
        gemm_hmma<false, 3072><<<gO, 256, GEMM_SMEM, s1>>>(
            a3, wo3, bo, out, 1.0f, cstart[q] * 8);
    }
    cudaEventRecord(eO4, s1);
    cudaStreamWaitEvent(0, eO4, 0);
}